// round 2
// baseline (speedup 1.0000x reference)
#include <cuda_runtime.h>
#include <math.h>

#define BB   2
#define CC   48
#define HH   128
#define WW   256
#define HWW  (HH*WW)          // 32768
#define C3   144
#define C2   96
#define NH   3
#define CHD  16

// ---------------- scratch (static device globals; no allocation) ----------------
__device__ float  g_qkv_pre [2][BB][C3][HWW];   // after LN + 1x1 qkv
__device__ float  g_qkv_post[2][BB][C3][HWW];   // after depthwise 3x3
__device__ float  g_qfold   [BB][CC][HWW];      // fused dilated-conv + convQ output
__device__ float2 g_weff2   [C2*27*CC];         // folded weights, duplicated (w,w), [ic][d*9+k][o]
__device__ float  g_beff    [CC];
__device__ float  g_inv     [3][BB][CC];        // 0: Qfold  1: K_l  2: K_r
__device__ float  g_dpart   [2*BB*NH*16*256];   // QK dot partials over 16 p-chunks
__device__ float  g_M       [2*BB*CC*CC];       // folded conv1/2 @ blockdiag(A)

// packed fp32x2 FMA (Blackwell): d = a*b + d, lanewise on two packed floats
__device__ __forceinline__ void ffma2(unsigned long long& d, unsigned long long a, unsigned long long b) {
    asm("fma.rn.f32x2 %0, %1, %2, %0;" : "+l"(d) : "l"(a), "l"(b));
}

// ---------------- weight folding: W_eff = convQ x dil_w (duplicated for f32x2) ----------------
__global__ void k_fold_w(const float* __restrict__ qw, const float* __restrict__ d0,
                         const float* __restrict__ d1, const float* __restrict__ d2) {
    int o = blockIdx.x;        // 0..47
    int d = blockIdx.y;        // 0..2
    const float* dw = (d == 0) ? d0 : (d == 1) ? d1 : d2;
    __shared__ float qr[C2];
    for (int j = threadIdx.x; j < C2; j += blockDim.x)
        qr[j] = qw[o*(3*C2) + d*C2 + j];
    __syncthreads();
    for (int ik = threadIdx.x; ik < C2*9; ik += blockDim.x) {
        float acc = 0.f;
        for (int j = 0; j < C2; ++j)
            acc += qr[j] * dw[j*(C2*9) + ik];
        int i = ik / 9, k = ik - i*9;
        g_weff2[(i*27 + d*9 + k)*CC + o] = make_float2(acc, acc);
    }
}

__global__ void k_fold_b(const float* __restrict__ qw, const float* __restrict__ qb,
                         const float* __restrict__ b0, const float* __restrict__ b1,
                         const float* __restrict__ b2) {
    int o = threadIdx.x;
    if (o < CC) {
        float acc = qb[o];
        for (int j = 0; j < C2; ++j) {
            acc += qw[o*288 +       j] * b0[j];
            acc += qw[o*288 +  96 + j] * b1[j];
            acc += qw[o*288 + 192 + j] * b2[j];
        }
        g_beff[o] = acc;
    }
}

// ---------------- fused LayerNorm2d + 1x1 qkv (48 -> 144) ----------------
__global__ void k_ln_qkv(const float* __restrict__ xl, const float* __restrict__ xr,
                         const float* __restrict__ ln1w, const float* __restrict__ ln1b,
                         const float* __restrict__ ln2w, const float* __restrict__ ln2b,
                         const float* __restrict__ wl, const float* __restrict__ bl,
                         const float* __restrict__ wr, const float* __restrict__ brb) {
    int branch = blockIdx.z, b = blockIdx.y;
    int p = blockIdx.x * blockDim.x + threadIdx.x;
    const float* x    = (branch == 0 ? xl : xr) + b*CC*HWW;
    const float* lw   = branch == 0 ? ln1w : ln2w;
    const float* lb   = branch == 0 ? ln1b : ln2b;
    const float* w    = branch == 0 ? wl : wr;
    const float* bias = branch == 0 ? bl : brb;
    float* out = &g_qkv_pre[branch][b][0][0];

    __shared__ __align__(16) float ws[C3*CC];
    __shared__ float bs[C3];
    __shared__ float lws[CC], lbs[CC];
    for (int i = threadIdx.x; i < C3*CC; i += blockDim.x) ws[i] = w[i];
    for (int i = threadIdx.x; i < C3; i += blockDim.x)    bs[i] = bias[i];
    for (int i = threadIdx.x; i < CC; i += blockDim.x)  { lws[i] = lw[i]; lbs[i] = lb[i]; }
    __syncthreads();

    float y[CC];
    float mu = 0.f;
    #pragma unroll
    for (int c = 0; c < CC; ++c) { y[c] = x[c*HWW + p]; mu += y[c]; }
    mu *= (1.f/CC);
    float var = 0.f;
    #pragma unroll
    for (int c = 0; c < CC; ++c) { float t = y[c] - mu; var += t*t; }
    var *= (1.f/CC);
    float rstd = rsqrtf(var + 1e-6f);
    #pragma unroll
    for (int c = 0; c < CC; ++c) y[c] = (y[c] - mu)*rstd*lws[c] + lbs[c];

    for (int o = 0; o < C3; ++o) {
        float acc = bs[o];
        const float4* w4 = reinterpret_cast<const float4*>(&ws[o*CC]);
        #pragma unroll
        for (int c4 = 0; c4 < CC/4; ++c4) {
            float4 wv = w4[c4];
            acc += wv.x*y[4*c4] + wv.y*y[4*c4+1] + wv.z*y[4*c4+2] + wv.w*y[4*c4+3];
        }
        out[o*HWW + p] = acc;
    }
}

// ---------------- depthwise 3x3, pad 1 (smem row tile, 4 px/thread) ----------------
// block: 256 threads = 4 row-slots x 64 col-quads; covers 4 rows x 256 cols of one channel
__global__ void k_dw(const float* __restrict__ wl, const float* __restrict__ bl,
                     const float* __restrict__ wr, const float* __restrict__ brb) {
    int z = blockIdx.z; int branch = z >> 1, b = z & 1;
    int ch = blockIdx.y;
    int y0 = blockIdx.x * 4;
    __shared__ __align__(16) float rows[6][264];   // data at col+4, halo zeros at 3 and 260
    const float* in = &g_qkv_pre[branch][b][ch][0];
    const float* w  = (branch == 0 ? wl : wr) + ch*9;
    float bias = (branch == 0 ? bl : brb)[ch];
    int tid = threadIdx.x;

    for (int idx = tid; idx < 6*64; idx += 256) {
        int r = idx >> 6, c4 = idx & 63;
        int gy = y0 - 1 + r;
        float4 v = make_float4(0.f, 0.f, 0.f, 0.f);
        if (gy >= 0 && gy < HH) v = *reinterpret_cast<const float4*>(&in[gy*WW + c4*4]);
        *reinterpret_cast<float4*>(&rows[r][4 + 4*c4]) = v;
    }
    if (tid < 6) { rows[tid][3] = 0.f; rows[tid][260] = 0.f; }
    __syncthreads();

    int r  = tid >> 6;           // 0..3
    int x0 = (tid & 63) * 4;
    float acc0 = bias, acc1 = bias, acc2 = bias, acc3 = bias;
    #pragma unroll
    for (int ky = 0; ky < 3; ++ky) {
        const float* rp = &rows[r + ky][3 + x0];
        float v0 = rp[0];
        float4 vm = *reinterpret_cast<const float4*>(rp + 1);
        float v5 = rp[5];
        float w0 = w[ky*3], w1 = w[ky*3+1], w2 = w[ky*3+2];
        acc0 += w0*v0   + w1*vm.x + w2*vm.y;
        acc1 += w0*vm.x + w1*vm.y + w2*vm.z;
        acc2 += w0*vm.y + w1*vm.z + w2*vm.w;
        acc3 += w0*vm.z + w1*vm.w + w2*v5;
    }
    int gy = y0 + r;
    *reinterpret_cast<float4*>(&g_qkv_post[branch][b][ch][gy*WW + x0]) =
        make_float4(acc0, acc1, acc2, acc3);
}

// ---------------- fused dilated convs (2/4/6) + convQ via packed f32x2 FMA ----------------
// grid (2 oc-halves, HH, BB), block 128 = 4 warps; warp handles 6 oc, lane handles 4 px-pairs
__global__ void k_dilated() {
    __shared__ __align__(16) float  ins[2][7][272];     // 2 ic x 7 rows x (256+12 halo, padded)
    __shared__ __align__(16) float2 ws2s[2*27*24];      // duplicated weights for this oc-half
    int ochalf = blockIdx.x;
    int y  = blockIdx.y;
    int b  = blockIdx.z;
    int tid = threadIdx.x;
    int lane = tid & 31, wid = tid >> 5;
    int o0 = ochalf*24 + wid*6;
    const float* pl = &g_qkv_post[0][b][0][0];
    const float* pr = &g_qkv_post[1][b][0][0];

    unsigned long long acc[6][4];
    #pragma unroll
    for (int j = 0; j < 6; ++j)
        #pragma unroll
        for (int q = 0; q < 4; ++q) acc[j][q] = 0ull;

    for (int cb = 0; cb < C2; cb += 2) {
        __syncthreads();
        // weights: 2 ic x 27 taps x 24 oc (float2 duplicated)
        for (int i = tid; i < 2*27*24; i += 128) {
            int tap2 = i / 24;
            int j = i - tap2*24;
            ws2s[i] = g_weff2[(cb*27 + tap2)*CC + ochalf*24 + j];
        }
        // inputs with zero-padded halo
        for (int idx = tid; idx < 2*7*272; idx += 128) {
            int ic  = idx / (7*272);
            int rem = idx - ic*(7*272);
            int r   = rem / 272;
            int col = rem - r*272;
            int gy = y + 2*r - 6;
            int gx = col - 6;
            float v = 0.f;
            if (col < 268 && gx >= 0 && gx < WW && gy >= 0 && gy < HH) {
                int icg = cb + ic;
                v = (icg < CC) ? pl[icg*HWW + gy*WW + gx]
                               : pr[(icg-CC)*HWW + gy*WW + gx];
            }
            ins[ic][r][col] = v;
        }
        __syncthreads();

        #pragma unroll
        for (int icl = 0; icl < 2; ++icl) {
            #pragma unroll
            for (int d = 0; d < 3; ++d) {
                #pragma unroll
                for (int ky = 0; ky < 3; ++ky) {
                    const unsigned long long* rp =
                        reinterpret_cast<const unsigned long long*>(&ins[icl][3 + (ky-1)*(d+1)][0]);
                    #pragma unroll
                    for (int kx = 0; kx < 3; ++kx) {
                        const int off  = (kx-1)*2*(d+1);
                        const int base = (6 + off) >> 1;
                        unsigned long long a0 = rp[base + lane];
                        unsigned long long a1 = rp[base + lane + 32];
                        unsigned long long a2 = rp[base + lane + 64];
                        unsigned long long a3 = rp[base + lane + 96];
                        const unsigned long long* wp = reinterpret_cast<const unsigned long long*>(
                            &ws2s[(icl*27 + d*9 + ky*3 + kx)*24 + wid*6]);
                        #pragma unroll
                        for (int j = 0; j < 6; ++j) {
                            unsigned long long wv = wp[j];
                            ffma2(acc[j][0], a0, wv);
                            ffma2(acc[j][1], a1, wv);
                            ffma2(acc[j][2], a2, wv);
                            ffma2(acc[j][3], a3, wv);
                        }
                    }
                }
            }
        }
    }

    int rowbase = y*WW;
    #pragma unroll
    for (int j = 0; j < 6; ++j) {
        int o = o0 + j;
        float be = g_beff[o];
        #pragma unroll
        for (int q = 0; q < 4; ++q) {
            unsigned long long v = acc[j][q];
            float lo = __uint_as_float((unsigned)v);
            float hi = __uint_as_float((unsigned)(v >> 32));
            *reinterpret_cast<float2*>(&g_qfold[b][o][rowbase + 2*lane + 64*q]) =
                make_float2(lo + be, hi + be);
        }
    }
}

// ---------------- per-channel L2 norms over HW ----------------
__global__ void k_norms() {
    int gid = blockIdx.x;
    int t = gid / (BB*CC);
    int r = gid - t*(BB*CC);
    int b = r / CC, c = r - b*CC;
    const float* src;
    if (t == 0)      src = &g_qfold[b][c][0];
    else if (t == 1) src = &g_qkv_post[0][b][CC + c][0];
    else             src = &g_qkv_post[1][b][CC + c][0];
    float ss = 0.f;
    const float4* s4 = reinterpret_cast<const float4*>(src);
    for (int i = threadIdx.x; i < HWW/4; i += blockDim.x) {
        float4 v = s4[i];
        ss += v.x*v.x + v.y*v.y + v.z*v.z + v.w*v.w;
    }
    #pragma unroll
    for (int off = 16; off > 0; off >>= 1)
        ss += __shfl_down_sync(0xffffffffu, ss, off);
    __shared__ float red[8];
    if ((threadIdx.x & 31) == 0) red[threadIdx.x >> 5] = ss;
    __syncthreads();
    if (threadIdx.x == 0) {
        float tot = 0.f;
        for (int i = 0; i < (int)(blockDim.x >> 5); ++i) tot += red[i];
        float n = sqrtf(tot);
        g_inv[t][b][c] = 1.f / fmaxf(n, 1e-12f);
    }
}

// ---------------- QK^T dot partials (deterministic two-stage) ----------------
__global__ void k_dots() {
    int chunk = blockIdx.x;        // 0..15
    int bh    = blockIdx.y;        // 0..5
    int s     = blockIdx.z;        // 0: Q.K_r  1: Q.K_l
    int b = bh / NH, h = bh - b*NH;
    const float* Q = &g_qfold[b][h*CHD][0];
    const float* K = (s == 0) ? &g_qkv_post[1][b][CC + h*CHD][0]
                              : &g_qkv_post[0][b][CC + h*CHD][0];
    __shared__ float Qs[16][257];
    __shared__ float Ks[16][257];
    int tid = threadIdx.x;
    int cq = tid >> 4, ck = tid & 15;
    float acc = 0.f;
    int p0 = chunk * 2048;
    for (int sub = 0; sub < 8; ++sub) {
        __syncthreads();
        int pb = p0 + sub*256;
        #pragma unroll
        for (int e = 0; e < 16; ++e) {
            Qs[e][tid] = Q[e*HWW + pb + tid];
            Ks[e][tid] = K[e*HWW + pb + tid];
        }
        __syncthreads();
        #pragma unroll 16
        for (int i = 0; i < 256; ++i)
            acc += Qs[cq][i] * Ks[ck][i];
    }
    g_dpart[(((s*BB + b)*NH + h)*16 + chunk)*256 + tid] = acc;
}

// ---------------- softmax + fold conv1/2 into M = w @ blockdiag(A) ----------------
__global__ void k_soft_m(const float* __restrict__ temp,
                         const float* __restrict__ w1, const float* __restrict__ w2) {
    __shared__ float As[192][16];
    int tid = threadIdx.x;
    if (tid < 192) {
        int s = tid / 96, rem = tid - s*96;
        int b = rem / 48, rem2 = rem - b*48;
        int h = rem2 / 16, cq = rem2 - h*16;
        float v[16];
        #pragma unroll
        for (int ck = 0; ck < 16; ++ck) v[ck] = 0.f;
        int base = (((s*BB + b)*NH + h)*16)*256 + cq*16;
        for (int chunk = 0; chunk < 16; ++chunk) {
            #pragma unroll
            for (int ck = 0; ck < 16; ++ck)
                v[ck] += g_dpart[base + chunk*256 + ck];
        }
        float iq = g_inv[0][b][h*16 + cq];
        float tm = temp[h];
        const float* ik = (s == 0) ? &g_inv[2][b][h*16] : &g_inv[1][b][h*16];
        float mx = -1e30f;
        #pragma unroll
        for (int ck = 0; ck < 16; ++ck) { v[ck] *= iq * ik[ck] * tm; mx = fmaxf(mx, v[ck]); }
        float sum = 0.f;
        #pragma unroll
        for (int ck = 0; ck < 16; ++ck) { v[ck] = expf(v[ck] - mx); sum += v[ck]; }
        float inv = 1.f / sum;
        #pragma unroll
        for (int ck = 0; ck < 16; ++ck) As[tid][ck] = v[ck] * inv;
    }
    __syncthreads();
    for (int idx = tid; idx < 2*BB*CC*CC; idx += blockDim.x) {
        int s = idx / (BB*CC*CC), rem = idx - s*(BB*CC*CC);
        int b = rem / (CC*CC), rem2 = rem - b*(CC*CC);
        int o = rem2 / CC, dg = rem2 - o*CC;
        int h = dg / 16, dd = dg - h*16;
        const float* wv = ((s == 0) ? w1 : w2) + o*CC + h*16;
        int arow = s*96 + b*48 + h*16;
        float acc = 0.f;
        #pragma unroll
        for (int c = 0; c < 16; ++c)
            acc += wv[c] * As[arow + c][dd];
        g_M[idx] = acc;
    }
}

// ---------------- epilogue: out = x + M @ V + bias ----------------
__global__ void k_epilogue(const float* __restrict__ xl, const float* __restrict__ xr,
                           const float* __restrict__ b1, const float* __restrict__ b2,
                           float* __restrict__ out) {
    int s = blockIdx.z, b = blockIdx.y;
    int p = blockIdx.x * blockDim.x + threadIdx.x;
    __shared__ __align__(16) float Ms[CC*CC];
    __shared__ float bs[CC];
    const float* Mg = &g_M[(s*BB + b)*CC*CC];
    for (int i = threadIdx.x; i < CC*CC; i += blockDim.x) Ms[i] = Mg[i];
    for (int i = threadIdx.x; i < CC; i += blockDim.x) bs[i] = (s == 0 ? b1 : b2)[i];
    __syncthreads();
    const float* V = &g_qkv_post[s == 0 ? 0 : 1][b][2*CC][0];
    const float* x = (s == 0 ? xl : xr) + b*CC*HWW;
    float* o = out + (s*BB + b)*CC*HWW;
    float v[CC];
    #pragma unroll
    for (int c = 0; c < CC; ++c) v[c] = V[c*HWW + p];
    for (int oc = 0; oc < CC; ++oc) {
        float acc = bs[oc];
        const float4* m4 = reinterpret_cast<const float4*>(&Ms[oc*CC]);
        #pragma unroll
        for (int c4 = 0; c4 < CC/4; ++c4) {
            float4 mv = m4[c4];
            acc += mv.x*v[4*c4] + mv.y*v[4*c4+1] + mv.z*v[4*c4+2] + mv.w*v[4*c4+3];
        }
        o[oc*HWW + p] = x[oc*HWW + p] + acc;
    }
}

// ---------------- launch ----------------
extern "C" void kernel_launch(void* const* d_in, const int* in_sizes, int n_in,
                              void* d_out, int out_size) {
    const float* x_l    = (const float*)d_in[0];
    const float* x_r    = (const float*)d_in[1];
    const float* ln1_w  = (const float*)d_in[2];
    const float* ln1_b  = (const float*)d_in[3];
    const float* ln2_w  = (const float*)d_in[4];
    const float* ln2_b  = (const float*)d_in[5];
    const float* qkvl_w = (const float*)d_in[6];
    const float* qkvl_b = (const float*)d_in[7];
    const float* qkvr_w = (const float*)d_in[8];
    const float* qkvr_b = (const float*)d_in[9];
    const float* dwl_w  = (const float*)d_in[10];
    const float* dwl_b  = (const float*)d_in[11];
    const float* dwr_w  = (const float*)d_in[12];
    const float* dwr_b  = (const float*)d_in[13];
    const float* dil0_w = (const float*)d_in[14];
    const float* dil0_b = (const float*)d_in[15];
    const float* dil1_w = (const float*)d_in[16];
    const float* dil1_b = (const float*)d_in[17];
    const float* dil2_w = (const float*)d_in[18];
    const float* dil2_b = (const float*)d_in[19];
    const float* convQ_w = (const float*)d_in[20];
    const float* convQ_b = (const float*)d_in[21];
    const float* conv1_w = (const float*)d_in[22];
    const float* conv1_b = (const float*)d_in[23];
    const float* conv2_w = (const float*)d_in[24];
    const float* conv2_b = (const float*)d_in[25];
    const float* temperature = (const float*)d_in[26];

    k_fold_w<<<dim3(CC, 3), 256>>>(convQ_w, dil0_w, dil1_w, dil2_w);
    k_fold_b<<<1, 64>>>(convQ_w, convQ_b, dil0_b, dil1_b, dil2_b);
    k_ln_qkv<<<dim3(HWW/128, BB, 2), 128>>>(x_l, x_r, ln1_w, ln1_b, ln2_w, ln2_b,
                                            qkvl_w, qkvl_b, qkvr_w, qkvr_b);
    k_dw<<<dim3(HH/4, C3, 2*BB), 256>>>(dwl_w, dwl_b, dwr_w, dwr_b);
    k_dilated<<<dim3(2, HH, BB), 128>>>();
    k_norms<<<3*BB*CC, 256>>>();
    k_dots<<<dim3(16, BB*NH, 2), 256>>>();
    k_soft_m<<<1, 256>>>(temperature, conv1_w, conv2_w);
    k_epilogue<<<dim3(HWW/256, BB, 2), 256>>>(x_l, x_r, conv1_b, conv2_b, (float*)d_out);
}

// round 5
// speedup vs baseline: 2.3201x; 2.3201x over previous
#include <cuda_runtime.h>
#include <cuda_bf16.h>
#include <cstdint>
#include <math.h>

#define BB   2
#define CC   48
#define HH   128
#define WW   256
#define HWW  (HH*WW)          // 32768
#define C3   144
#define C2   96
#define NH   3
#define CHD  16

// ---------------- scratch (static device globals; no allocation) ----------------
__device__ float          g_qkv_pre [2][BB][C3][HWW];   // after LN + 1x1 qkv
__device__ float          g_qkv_post[2][BB][C3][HWW];   // after depthwise 3x3 (fp32 K,V path)
__device__ __nv_bfloat16  g_xin     [BB][C2][HWW];      // bf16 [Q_l;Q_r] for dilated MMA
__device__ float          g_qfold   [BB][CC][HWW];      // fused dilated-conv + convQ output
__device__ __nv_bfloat16  g_wbf     [27][64][C2];       // folded bf16 weights, oc-padded to 64
__device__ float          g_beff    [CC];
__device__ float          g_inv     [3][BB][CC];        // 0: Qfold  1: K_l  2: K_r
__device__ float          g_dpart   [2*BB*NH*16*256];   // QK dot partials
__device__ float          g_M       [2*BB*CC*CC];       // folded conv1/2 @ blockdiag(A)

__device__ __forceinline__ uint32_t smem_u32(const void* p) {
    uint32_t a;
    asm("{ .reg .u64 t; cvta.to.shared.u64 t, %1; cvt.u32.u64 %0, t; }" : "=r"(a) : "l"(p));
    return a;
}

// ---------------- zero padded weight scratch ----------------
__global__ void k_zero_w() {
    int i = blockIdx.x * 256 + threadIdx.x;   // 324*256 = 82944 u32 = 27*64*96 bf16
    reinterpret_cast<uint32_t*>(g_wbf)[i] = 0u;
}

// ---------------- weight folding: W_eff = convQ x dil_w -> bf16 [tap][64][96] ----------------
__global__ void k_fold_w(const float* __restrict__ qw, const float* __restrict__ d0,
                         const float* __restrict__ d1, const float* __restrict__ d2) {
    int o = blockIdx.x;        // 0..47
    int d = blockIdx.y;        // 0..2
    const float* dw = (d == 0) ? d0 : (d == 1) ? d1 : d2;
    __shared__ float qr[C2];
    for (int j = threadIdx.x; j < C2; j += blockDim.x)
        qr[j] = qw[o*(3*C2) + d*C2 + j];
    __syncthreads();
    for (int ik = threadIdx.x; ik < C2*9; ik += blockDim.x) {
        float acc = 0.f;
        for (int j = 0; j < C2; ++j)
            acc += qr[j] * dw[j*(C2*9) + ik];
        int i = ik / 9, kk = ik - i*9;
        g_wbf[d*9 + kk][o][i] = __float2bfloat16_rn(acc);
    }
}

__global__ void k_fold_b(const float* __restrict__ qw, const float* __restrict__ qb,
                         const float* __restrict__ b0, const float* __restrict__ b1,
                         const float* __restrict__ b2) {
    int o = threadIdx.x;
    if (o < CC) {
        float acc = qb[o];
        for (int j = 0; j < C2; ++j) {
            acc += qw[o*288 +       j] * b0[j];
            acc += qw[o*288 +  96 + j] * b1[j];
            acc += qw[o*288 + 192 + j] * b2[j];
        }
        g_beff[o] = acc;
    }
}

// ---------------- fused LayerNorm2d + 1x1 qkv (48 -> 144) ----------------
__global__ void k_ln_qkv(const float* __restrict__ xl, const float* __restrict__ xr,
                         const float* __restrict__ ln1w, const float* __restrict__ ln1b,
                         const float* __restrict__ ln2w, const float* __restrict__ ln2b,
                         const float* __restrict__ wl, const float* __restrict__ bl,
                         const float* __restrict__ wr, const float* __restrict__ brb) {
    int branch = blockIdx.z, b = blockIdx.y;
    int p = blockIdx.x * blockDim.x + threadIdx.x;
    const float* x    = (branch == 0 ? xl : xr) + b*CC*HWW;
    const float* lw   = branch == 0 ? ln1w : ln2w;
    const float* lb   = branch == 0 ? ln1b : ln2b;
    const float* w    = branch == 0 ? wl : wr;
    const float* bias = branch == 0 ? bl : brb;
    float* out = &g_qkv_pre[branch][b][0][0];

    __shared__ __align__(16) float ws[C3*CC];
    __shared__ float bs[C3];
    __shared__ float lws[CC], lbs[CC];
    for (int i = threadIdx.x; i < C3*CC; i += blockDim.x) ws[i] = w[i];
    for (int i = threadIdx.x; i < C3; i += blockDim.x)    bs[i] = bias[i];
    for (int i = threadIdx.x; i < CC; i += blockDim.x)  { lws[i] = lw[i]; lbs[i] = lb[i]; }
    __syncthreads();

    float y[CC];
    float mu = 0.f;
    #pragma unroll
    for (int c = 0; c < CC; ++c) { y[c] = x[c*HWW + p]; mu += y[c]; }
    mu *= (1.f/CC);
    float var = 0.f;
    #pragma unroll
    for (int c = 0; c < CC; ++c) { float t = y[c] - mu; var += t*t; }
    var *= (1.f/CC);
    float rstd = rsqrtf(var + 1e-6f);
    #pragma unroll
    for (int c = 0; c < CC; ++c) y[c] = (y[c] - mu)*rstd*lws[c] + lbs[c];

    for (int o = 0; o < C3; ++o) {
        float acc = bs[o];
        const float4* w4 = reinterpret_cast<const float4*>(&ws[o*CC]);
        #pragma unroll
        for (int c4 = 0; c4 < CC/4; ++c4) {
            float4 wv = w4[c4];
            acc += wv.x*y[4*c4] + wv.y*y[4*c4+1] + wv.z*y[4*c4+2] + wv.w*y[4*c4+3];
        }
        out[o*HWW + p] = acc;
    }
}

// ---------------- depthwise 3x3, pad 1 + bf16 Q-copy ----------------
__global__ void k_dw(const float* __restrict__ wl, const float* __restrict__ bl,
                     const float* __restrict__ wr, const float* __restrict__ brb) {
    int z = blockIdx.z; int branch = z >> 1, b = z & 1;
    int ch = blockIdx.y;
    int y0 = blockIdx.x * 4;
    __shared__ __align__(16) float rows[6][264];
    const float* in = &g_qkv_pre[branch][b][ch][0];
    const float* w  = (branch == 0 ? wl : wr) + ch*9;
    float bias = (branch == 0 ? bl : brb)[ch];
    int tid = threadIdx.x;

    for (int idx = tid; idx < 6*64; idx += 256) {
        int r = idx >> 6, c4 = idx & 63;
        int gy = y0 - 1 + r;
        float4 v = make_float4(0.f, 0.f, 0.f, 0.f);
        if (gy >= 0 && gy < HH) v = *reinterpret_cast<const float4*>(&in[gy*WW + c4*4]);
        *reinterpret_cast<float4*>(&rows[r][4 + 4*c4]) = v;
    }
    if (tid < 6) { rows[tid][3] = 0.f; rows[tid][260] = 0.f; }
    __syncthreads();

    int r  = tid >> 6;
    int x0 = (tid & 63) * 4;
    float acc0 = bias, acc1 = bias, acc2 = bias, acc3 = bias;
    #pragma unroll
    for (int ky = 0; ky < 3; ++ky) {
        const float* rp = &rows[r + ky][3 + x0];
        float v0 = rp[0];
        float4 vm = *reinterpret_cast<const float4*>(rp + 1);
        float v5 = rp[5];
        float w0 = w[ky*3], w1 = w[ky*3+1], w2 = w[ky*3+2];
        acc0 += w0*v0   + w1*vm.x + w2*vm.y;
        acc1 += w0*vm.x + w1*vm.y + w2*vm.z;
        acc2 += w0*vm.y + w1*vm.z + w2*vm.w;
        acc3 += w0*vm.z + w1*vm.w + w2*v5;
    }
    int gy = y0 + r;
    int px = gy*WW + x0;
    *reinterpret_cast<float4*>(&g_qkv_post[branch][b][ch][px]) =
        make_float4(acc0, acc1, acc2, acc3);
    if (ch < CC) {   // Q channels -> bf16 input for dilated MMA
        uint32_t u0 = (uint32_t)__bfloat16_as_ushort(__float2bfloat16_rn(acc0))
                    | ((uint32_t)__bfloat16_as_ushort(__float2bfloat16_rn(acc1)) << 16);
        uint32_t u1 = (uint32_t)__bfloat16_as_ushort(__float2bfloat16_rn(acc2))
                    | ((uint32_t)__bfloat16_as_ushort(__float2bfloat16_rn(acc3)) << 16);
        *reinterpret_cast<uint2*>(&g_xin[b][branch*CC + ch][px]) = make_uint2(u0, u1);
    }
}

// ---------------- fused dilated convs (2/4/6) + convQ via mma.sync bf16 ----------------
// Per CTA: batch b, output row y. D[64 oc pad x 256 px]; 27 taps x 6 k-steps of m16n8k16.
// 8 warps: mhalf = wid&1 (32 oc), nq = wid>>2.. (64 px). A smem [64][104], B smem [96][264].
#define SA 104
#define SB 264
#define SM_BYTES (64*SA*2 + 96*SB*2)   // 13312 + 50688 = 64000

__global__ void __launch_bounds__(256) k_dilated_mma() {
    extern __shared__ __align__(16) char sm[];
    __nv_bfloat16* As = reinterpret_cast<__nv_bfloat16*>(sm);
    __nv_bfloat16* Bs = reinterpret_cast<__nv_bfloat16*>(sm + 64*SA*2);
    uint32_t smbA = smem_u32(As), smbB = smem_u32(Bs);
    int y = blockIdx.x, b = blockIdx.y;
    int tid = threadIdx.x, lane = tid & 31, wid = tid >> 5;
    int mhalf = wid & 1, nq = wid >> 1;

    float acc[2][8][4];
    #pragma unroll
    for (int mb = 0; mb < 2; ++mb)
        #pragma unroll
        for (int nt = 0; nt < 8; ++nt)
            #pragma unroll
            for (int q = 0; q < 4; ++q) acc[mb][nt][q] = 0.f;

    const __nv_bfloat16* xin = &g_xin[b][0][0];

    for (int t = 0; t < 27; ++t) {
        __syncthreads();
        // A: 64x96 bf16 = 768 uint4
        {
            const uint4* src = reinterpret_cast<const uint4*>(&g_wbf[t][0][0]);
            for (int i = tid; i < 768; i += 256) {
                int row = i / 12, c = i - row*12;
                *reinterpret_cast<uint4*>(&As[row*SA + c*8]) = src[i];
            }
        }
        // B: [96 ic][256 px] shifted by (dy, dx), zero OOB. dx even -> 4B-aligned u32 pairs.
        {
            int d = t / 9, rr = t - d*9;
            int ky = rr / 3, kx = rr - ky*3;
            int dil = 2*(d+1);
            int gy = y + (ky-1)*dil;
            int dx = (kx-1)*dil;
            bool rowok = (gy >= 0 && gy < HH);
            for (int i = tid; i < 12288; i += 256) {
                int k = i >> 7, cp = i & 127;
                int gx = cp*2 + dx;
                uint32_t v = 0u;
                if (rowok && gx >= 0 && gx < WW)
                    v = *reinterpret_cast<const uint32_t*>(xin + k*HWW + gy*WW + gx);
                *reinterpret_cast<uint32_t*>(&Bs[k*SB + cp*2]) = v;
            }
        }
        __syncthreads();

        #pragma unroll
        for (int kb = 0; kb < 6; ++kb) {
            int k0 = kb*16;
            uint32_t a[2][4];
            #pragma unroll
            for (int mb = 0; mb < 2; ++mb) {
                int row = mhalf*32 + mb*16 + (lane & 7) + ((lane >> 3) & 1)*8;
                int col = k0 + (lane >> 4)*8;
                uint32_t addr = smbA + (uint32_t)(row*SA + col)*2u;
                asm volatile("ldmatrix.sync.aligned.m8n8.x4.shared.b16 {%0,%1,%2,%3}, [%4];"
                    : "=r"(a[mb][0]), "=r"(a[mb][1]), "=r"(a[mb][2]), "=r"(a[mb][3])
                    : "r"(addr));
            }
            #pragma unroll
            for (int np = 0; np < 4; ++np) {
                int krow = k0 + (lane & 7) + ((lane >> 3) & 1)*8;
                int ncol = nq*64 + np*16 + (lane >> 4)*8;
                uint32_t addr = smbB + (uint32_t)(krow*SB + ncol)*2u;
                uint32_t b0, b1, b2, b3;
                asm volatile("ldmatrix.sync.aligned.m8n8.x4.trans.shared.b16 {%0,%1,%2,%3}, [%4];"
                    : "=r"(b0), "=r"(b1), "=r"(b2), "=r"(b3) : "r"(addr));
                #pragma unroll
                for (int mb = 0; mb < 2; ++mb) {
                    float* c0 = acc[mb][np*2];
                    float* c1 = acc[mb][np*2 + 1];
                    asm volatile(
                        "mma.sync.aligned.m16n8k16.row.col.f32.bf16.bf16.f32 "
                        "{%0,%1,%2,%3}, {%4,%5,%6,%7}, {%8,%9}, {%0,%1,%2,%3};"
                        : "+f"(c0[0]), "+f"(c0[1]), "+f"(c0[2]), "+f"(c0[3])
                        : "r"(a[mb][0]), "r"(a[mb][1]), "r"(a[mb][2]), "r"(a[mb][3]),
                          "r"(b0), "r"(b1));
                    asm volatile(
                        "mma.sync.aligned.m16n8k16.row.col.f32.bf16.bf16.f32 "
                        "{%0,%1,%2,%3}, {%4,%5,%6,%7}, {%8,%9}, {%0,%1,%2,%3};"
                        : "+f"(c1[0]), "+f"(c1[1]), "+f"(c1[2]), "+f"(c1[3])
                        : "r"(a[mb][0]), "r"(a[mb][1]), "r"(a[mb][2]), "r"(a[mb][3]),
                          "r"(b2), "r"(b3));
                }
            }
        }
    }

    // epilogue: D frag -> g_qfold (+bias); oc >= 48 discarded
    #pragma unroll
    for (int mb = 0; mb < 2; ++mb) {
        int oc_lo = mhalf*32 + mb*16 + (lane >> 2);
        int oc_hi = oc_lo + 8;
        #pragma unroll
        for (int nt = 0; nt < 8; ++nt) {
            int px = nq*64 + nt*8 + (lane & 3)*2;
            if (oc_lo < CC) {
                float be = g_beff[oc_lo];
                *reinterpret_cast<float2*>(&g_qfold[b][oc_lo][y*WW + px]) =
                    make_float2(acc[mb][nt][0] + be, acc[mb][nt][1] + be);
            }
            if (oc_hi < CC) {
                float be = g_beff[oc_hi];
                *reinterpret_cast<float2*>(&g_qfold[b][oc_hi][y*WW + px]) =
                    make_float2(acc[mb][nt][2] + be, acc[mb][nt][3] + be);
            }
        }
    }
}

// ---------------- per-channel L2 norms over HW ----------------
__global__ void k_norms() {
    int gid = blockIdx.x;
    int t = gid / (BB*CC);
    int r = gid - t*(BB*CC);
    int b = r / CC, c = r - b*CC;
    const float* src;
    if (t == 0)      src = &g_qfold[b][c][0];
    else if (t == 1) src = &g_qkv_post[0][b][CC + c][0];
    else             src = &g_qkv_post[1][b][CC + c][0];
    float ss = 0.f;
    const float4* s4 = reinterpret_cast<const float4*>(src);
    for (int i = threadIdx.x; i < HWW/4; i += blockDim.x) {
        float4 v = s4[i];
        ss += v.x*v.x + v.y*v.y + v.z*v.z + v.w*v.w;
    }
    #pragma unroll
    for (int off = 16; off > 0; off >>= 1)
        ss += __shfl_down_sync(0xffffffffu, ss, off);
    __shared__ float red[8];
    if ((threadIdx.x & 31) == 0) red[threadIdx.x >> 5] = ss;
    __syncthreads();
    if (threadIdx.x == 0) {
        float tot = 0.f;
        for (int i = 0; i < (int)(blockDim.x >> 5); ++i) tot += red[i];
        float n = sqrtf(tot);
        g_inv[t][b][c] = 1.f / fmaxf(n, 1e-12f);
    }
}

// ---------------- QK^T dot partials (deterministic two-stage) ----------------
__global__ void k_dots() {
    int chunk = blockIdx.x;        // 0..15
    int bh    = blockIdx.y;        // 0..5
    int s     = blockIdx.z;        // 0: Q.K_r  1: Q.K_l
    int b = bh / NH, h = bh - b*NH;
    const float* Q = &g_qfold[b][h*CHD][0];
    const float* K = (s == 0) ? &g_qkv_post[1][b][CC + h*CHD][0]
                              : &g_qkv_post[0][b][CC + h*CHD][0];
    __shared__ float Qs[16][257];
    __shared__ float Ks[16][257];
    int tid = threadIdx.x;
    int cq = tid >> 4, ck = tid & 15;
    float acc = 0.f;
    int p0 = chunk * 2048;
    for (int sub = 0; sub < 8; ++sub) {
        __syncthreads();
        int pb = p0 + sub*256;
        #pragma unroll
        for (int e = 0; e < 16; ++e) {
            Qs[e][tid] = Q[e*HWW + pb + tid];
            Ks[e][tid] = K[e*HWW + pb + tid];
        }
        __syncthreads();
        #pragma unroll 16
        for (int i = 0; i < 256; ++i)
            acc += Qs[cq][i] * Ks[ck][i];
    }
    g_dpart[(((s*BB + b)*NH + h)*16 + chunk)*256 + tid] = acc;
}

// ---------------- softmax + fold conv1/2 into M = w @ blockdiag(A) ----------------
__global__ void k_soft_m(const float* __restrict__ temp,
                         const float* __restrict__ w1, const float* __restrict__ w2) {
    __shared__ float As[192][16];
    int tid = threadIdx.x;
    if (tid < 192) {
        int s = tid / 96, rem = tid - s*96;
        int b = rem / 48, rem2 = rem - b*48;
        int h = rem2 / 16, cq = rem2 - h*16;
        float v[16];
        #pragma unroll
        for (int ck = 0; ck < 16; ++ck) v[ck] = 0.f;
        int base = (((s*BB + b)*NH + h)*16)*256 + cq*16;
        for (int chunk = 0; chunk < 16; ++chunk) {
            #pragma unroll
            for (int ck = 0; ck < 16; ++ck)
                v[ck] += g_dpart[base + chunk*256 + ck];
        }
        float iq = g_inv[0][b][h*16 + cq];
        float tm = temp[h];
        const float* ik = (s == 0) ? &g_inv[2][b][h*16] : &g_inv[1][b][h*16];
        float mx = -1e30f;
        #pragma unroll
        for (int ck = 0; ck < 16; ++ck) { v[ck] *= iq * ik[ck] * tm; mx = fmaxf(mx, v[ck]); }
        float sum = 0.f;
        #pragma unroll
        for (int ck = 0; ck < 16; ++ck) { v[ck] = expf(v[ck] - mx); sum += v[ck]; }
        float inv = 1.f / sum;
        #pragma unroll
        for (int ck = 0; ck < 16; ++ck) As[tid][ck] = v[ck] * inv;
    }
    __syncthreads();
    for (int idx = tid; idx < 2*BB*CC*CC; idx += blockDim.x) {
        int s = idx / (BB*CC*CC), rem = idx - s*(BB*CC*CC);
        int b = rem / (CC*CC), rem2 = rem - b*(CC*CC);
        int o = rem2 / CC, dg = rem2 - o*CC;
        int h = dg / 16, dd = dg - h*16;
        const float* wv = ((s == 0) ? w1 : w2) + o*CC + h*16;
        int arow = s*96 + b*48 + h*16;
        float acc = 0.f;
        #pragma unroll
        for (int c = 0; c < 16; ++c)
            acc += wv[c] * As[arow + c][dd];
        g_M[idx] = acc;
    }
}

// ---------------- epilogue: out = x + M @ V + bias ----------------
__global__ void k_epilogue(const float* __restrict__ xl, const float* __restrict__ xr,
                           const float* __restrict__ b1, const float* __restrict__ b2,
                           float* __restrict__ out) {
    int s = blockIdx.z, b = blockIdx.y;
    int p = blockIdx.x * blockDim.x + threadIdx.x;
    __shared__ __align__(16) float Ms[CC*CC];
    __shared__ float bs[CC];
    const float* Mg = &g_M[(s*BB + b)*CC*CC];
    for (int i = threadIdx.x; i < CC*CC; i += blockDim.x) Ms[i] = Mg[i];
    for (int i = threadIdx.x; i < CC; i += blockDim.x) bs[i] = (s == 0 ? b1 : b2)[i];
    __syncthreads();
    const float* V = &g_qkv_post[s == 0 ? 0 : 1][b][2*CC][0];
    const float* x = (s == 0 ? xl : xr) + b*CC*HWW;
    float* o = out + (s*BB + b)*CC*HWW;
    float v[CC];
    #pragma unroll
    for (int c = 0; c < CC; ++c) v[c] = V[c*HWW + p];
    for (int oc = 0; oc < CC; ++oc) {
        float acc = bs[oc];
        const float4* m4 = reinterpret_cast<const float4*>(&Ms[oc*CC]);
        #pragma unroll
        for (int c4 = 0; c4 < CC/4; ++c4) {
            float4 mv = m4[c4];
            acc += mv.x*v[4*c4] + mv.y*v[4*c4+1] + mv.z*v[4*c4+2] + mv.w*v[4*c4+3];
        }
        o[oc*HWW + p] = x[oc*HWW + p] + acc;
    }
}

// ---------------- launch ----------------
extern "C" void kernel_launch(void* const* d_in, const int* in_sizes, int n_in,
                              void* d_out, int out_size) {
    const float* x_l    = (const float*)d_in[0];
    const float* x_r    = (const float*)d_in[1];
    const float* ln1_w  = (const float*)d_in[2];
    const float* ln1_b  = (const float*)d_in[3];
    const float* ln2_w  = (const float*)d_in[4];
    const float* ln2_b  = (const float*)d_in[5];
    const float* qkvl_w = (const float*)d_in[6];
    const float* qkvl_b = (const float*)d_in[7];
    const float* qkvr_w = (const float*)d_in[8];
    const float* qkvr_b = (const float*)d_in[9];
    const float* dwl_w  = (const float*)d_in[10];
    const float* dwl_b  = (const float*)d_in[11];
    const float* dwr_w  = (const float*)d_in[12];
    const float* dwr_b  = (const float*)d_in[13];
    const float* dil0_w = (const float*)d_in[14];
    const float* dil0_b = (const float*)d_in[15];
    const float* dil1_w = (const float*)d_in[16];
    const float* dil1_b = (const float*)d_in[17];
    const float* dil2_w = (const float*)d_in[18];
    const float* dil2_b = (const float*)d_in[19];
    const float* convQ_w = (const float*)d_in[20];
    const float* convQ_b = (const float*)d_in[21];
    const float* conv1_w = (const float*)d_in[22];
    const float* conv1_b = (const float*)d_in[23];
    const float* conv2_w = (const float*)d_in[24];
    const float* conv2_b = (const float*)d_in[25];
    const float* temperature = (const float*)d_in[26];

    cudaFuncSetAttribute(k_dilated_mma, cudaFuncAttributeMaxDynamicSharedMemorySize, SM_BYTES);

    k_zero_w<<<324, 256>>>();
    k_fold_w<<<dim3(CC, 3), 256>>>(convQ_w, dil0_w, dil1_w, dil2_w);
    k_fold_b<<<1, 64>>>(convQ_w, convQ_b, dil0_b, dil1_b, dil2_b);
    k_ln_qkv<<<dim3(HWW/128, BB, 2), 128>>>(x_l, x_r, ln1_w, ln1_b, ln2_w, ln2_b,
                                            qkvl_w, qkvl_b, qkvr_w, qkvr_b);
    k_dw<<<dim3(HH/4, C3, 2*BB), 256>>>(dwl_w, dwl_b, dwr_w, dwr_b);
    k_dilated_mma<<<dim3(HH, BB), 256, SM_BYTES>>>();
    k_norms<<<3*BB*CC, 256>>>();
    k_dots<<<dim3(16, BB*NH, 2), 256>>>();
    k_soft_m<<<1, 256>>>(temperature, conv1_w, conv2_w);
    k_epilogue<<<dim3(HWW/256, BB, 2), 256>>>(x_l, x_r, conv1_b, conv2_b, (float*)d_out);
}

// round 6
// speedup vs baseline: 2.6932x; 1.1608x over previous
#include <cuda_runtime.h>
#include <cuda_bf16.h>
#include <cstdint>
#include <math.h>

#define BB   2
#define CC   48
#define HH   128
#define WW   256
#define HWW  (HH*WW)          // 32768
#define C3   144
#define C2   96
#define NH   3
#define CHD  16
#define BSTR 140              // pair-packed B row stride (u32); 140 % 32 == 12 -> conflict-free
#define ASTR 104              // A tile row stride (bf16)
#define BBUF (48*BSTR)        // u32 per B buffer

// ---------------- scratch (static device globals; no allocation) ----------------
__device__ __nv_bfloat16  g_pre_bf [2][BB][C3][HWW];   // bf16 qkv after LN+1x1
__device__ float          g_kv     [2][BB][C2][HWW];   // fp32 K(0..47), V(48..95) after dw
__device__ uint32_t       g_xp     [BB][CC][HWW];      // pair-packed bf16 [Q_l;Q_r] (96ch -> 48 pairs)
__device__ uint32_t       g_xnp    [2][BB][24][HWW];   // pair-packed bf16 LN output (48ch -> 24 pairs)
__device__ float          g_qfold  [BB][CC][HWW];      // fused dilated-conv + convQ output
__device__ __nv_bfloat16  g_wbf    [27][64][C2];       // folded bf16 weights (oc pad 64)
__device__ __nv_bfloat16  g_wq     [2][C3][CC];        // bf16 qkv weights
__device__ float          g_beff   [CC];
__device__ float          g_inv    [3][BB][CC];
__device__ float          g_dpart  [2*BB*NH*16*256];
__device__ float          g_M      [2*BB*CC*CC];

__device__ __forceinline__ uint32_t smem_u32(const void* p) {
    uint32_t a;
    asm("{ .reg .u64 t; cvta.to.shared.u64 t, %1; cvt.u32.u64 %0, t; }" : "=r"(a) : "l"(p));
    return a;
}
__device__ __forceinline__ void ldsm4(uint32_t* r, uint32_t addr) {
    asm volatile("ldmatrix.sync.aligned.m8n8.x4.shared.b16 {%0,%1,%2,%3}, [%4];"
        : "=r"(r[0]), "=r"(r[1]), "=r"(r[2]), "=r"(r[3]) : "r"(addr));
}
__device__ __forceinline__ void mma16816(float* c, const uint32_t* a, uint32_t b0, uint32_t b1) {
    asm volatile("mma.sync.aligned.m16n8k16.row.col.f32.bf16.bf16.f32 "
        "{%0,%1,%2,%3}, {%4,%5,%6,%7}, {%8,%9}, {%0,%1,%2,%3};"
        : "+f"(c[0]), "+f"(c[1]), "+f"(c[2]), "+f"(c[3])
        : "r"(a[0]), "r"(a[1]), "r"(a[2]), "r"(a[3]), "r"(b0), "r"(b1));
}
__device__ __forceinline__ void st_bf2(__nv_bfloat16* p, float a, float b) {
    uint32_t u = (uint32_t)__bfloat16_as_ushort(__float2bfloat16_rn(a))
               | ((uint32_t)__bfloat16_as_ushort(__float2bfloat16_rn(b)) << 16);
    *reinterpret_cast<uint32_t*>(p) = u;
}

// ---------------- weight prep ----------------
__global__ void k_prep_w(const float* __restrict__ wl, const float* __restrict__ wr) {
    int i = blockIdx.x*256 + threadIdx.x;     // 54*256 >= 13824
    if (i < 2*C3*CC) {
        int s = i / (C3*CC), r = i - s*(C3*CC);
        reinterpret_cast<__nv_bfloat16*>(g_wq)[i] = __float2bfloat16_rn((s ? wr : wl)[r]);
    }
}
__global__ void k_zero_w() {
    int i = blockIdx.x*256 + threadIdx.x;     // 324*256 = 27*64*96/2 u32
    reinterpret_cast<uint32_t*>(g_wbf)[i] = 0u;
}
__global__ void k_fold_w(const float* __restrict__ qw, const float* __restrict__ d0,
                         const float* __restrict__ d1, const float* __restrict__ d2) {
    int o = blockIdx.x, d = blockIdx.y;
    const float* dw = (d == 0) ? d0 : (d == 1) ? d1 : d2;
    __shared__ float qr[C2];
    for (int j = threadIdx.x; j < C2; j += blockDim.x)
        qr[j] = qw[o*(3*C2) + d*C2 + j];
    __syncthreads();
    for (int ik = threadIdx.x; ik < C2*9; ik += blockDim.x) {
        float acc = 0.f;
        for (int j = 0; j < C2; ++j)
            acc += qr[j] * dw[j*(C2*9) + ik];
        int i = ik / 9, kk = ik - i*9;
        g_wbf[d*9 + kk][o][i] = __float2bfloat16_rn(acc);
    }
}
__global__ void k_fold_b(const float* __restrict__ qw, const float* __restrict__ qb,
                         const float* __restrict__ b0, const float* __restrict__ b1,
                         const float* __restrict__ b2) {
    int o = threadIdx.x;
    if (o < CC) {
        float acc = qb[o];
        for (int j = 0; j < C2; ++j) {
            acc += qw[o*288 +       j] * b0[j];
            acc += qw[o*288 +  96 + j] * b1[j];
            acc += qw[o*288 + 192 + j] * b2[j];
        }
        g_beff[o] = acc;
    }
}

// ---------------- LayerNorm2d -> pair-packed bf16 ----------------
__global__ void k_ln(const float* __restrict__ xl, const float* __restrict__ xr,
                     const float* __restrict__ ln1w, const float* __restrict__ ln1b,
                     const float* __restrict__ ln2w, const float* __restrict__ ln2b) {
    int branch = blockIdx.z, b = blockIdx.y;
    int p = blockIdx.x*blockDim.x + threadIdx.x;
    const float* x  = (branch == 0 ? xl : xr) + b*CC*HWW;
    const float* lw = branch == 0 ? ln1w : ln2w;
    const float* lb = branch == 0 ? ln1b : ln2b;
    __shared__ float lws[CC], lbs[CC];
    for (int i = threadIdx.x; i < CC; i += blockDim.x) { lws[i] = lw[i]; lbs[i] = lb[i]; }
    __syncthreads();
    float y[CC]; float mu = 0.f;
    #pragma unroll
    for (int c = 0; c < CC; ++c) { y[c] = x[c*HWW + p]; mu += y[c]; }
    mu *= (1.f/CC);
    float var = 0.f;
    #pragma unroll
    for (int c = 0; c < CC; ++c) { float t = y[c] - mu; var += t*t; }
    float rstd = rsqrtf(var*(1.f/CC) + 1e-6f);
    uint32_t* out = &g_xnp[branch][b][0][p];
    #pragma unroll
    for (int kp = 0; kp < 24; ++kp) {
        float v0 = (y[2*kp]   - mu)*rstd*lws[2*kp]   + lbs[2*kp];
        float v1 = (y[2*kp+1] - mu)*rstd*lws[2*kp+1] + lbs[2*kp+1];
        uint32_t u = (uint32_t)__bfloat16_as_ushort(__float2bfloat16_rn(v0))
                   | ((uint32_t)__bfloat16_as_ushort(__float2bfloat16_rn(v1)) << 16);
        out[kp*HWW] = u;
    }
}

// ---------------- 1x1 qkv GEMM via mma.sync: [144x48] @ [48 x 128px] ----------------
__global__ void __launch_bounds__(288) k_qkv_mma(const float* __restrict__ bl,
                                                 const float* __restrict__ br) {
    __shared__ __align__(16) __nv_bfloat16 As[C3*CC];
    __shared__ uint32_t Bs[24*BSTR];
    __shared__ float bs[C3];
    int p0 = blockIdx.x*128, b = blockIdx.y, branch = blockIdx.z;
    int tid = threadIdx.x, lane = tid & 31, wid = tid >> 5;   // 9 warps
    {
        const uint4* src = reinterpret_cast<const uint4*>(&g_wq[branch][0][0]);
        uint4* dst = reinterpret_cast<uint4*>(As);
        for (int i = tid; i < C3*CC/8; i += 288) dst[i] = src[i];
        const float* bp = branch ? br : bl;
        for (int i = tid; i < C3; i += 288) bs[i] = bp[i];
        const uint32_t* xsrc = &g_xnp[branch][b][0][0];
        for (int i = tid; i < 24*128; i += 288) {
            int kp = i >> 7, col = i & 127;
            Bs[kp*BSTR + col] = xsrc[kp*HWW + p0 + col];
        }
    }
    __syncthreads();
    float acc[8][2][4];
    #pragma unroll
    for (int np = 0; np < 8; ++np)
        #pragma unroll
        for (int f = 0; f < 2; ++f)
            #pragma unroll
            for (int q = 0; q < 4; ++q) acc[np][f][q] = 0.f;
    uint32_t smbA = smem_u32(As);
    #pragma unroll
    for (int kb = 0; kb < 3; ++kb) {
        uint32_t a[4];
        int row = wid*16 + (lane & 15);
        ldsm4(a, smbA + (uint32_t)(row*CC + kb*16 + ((lane >> 4) << 3))*2u);
        const uint32_t* b_lo = Bs + (kb*8 + (lane & 3))*BSTR + (lane >> 2);
        const uint32_t* b_hi = b_lo + 4*BSTR;
        #pragma unroll
        for (int np = 0; np < 8; ++np) {
            uint32_t b0 = b_lo[np*16], b1 = b_hi[np*16];
            uint32_t b2 = b_lo[np*16 + 8], b3 = b_hi[np*16 + 8];
            mma16816(acc[np][0], a, b0, b1);
            mma16816(acc[np][1], a, b2, b3);
        }
    }
    int r0 = lane >> 2, cb = (lane & 3)*2;
    int oc0 = wid*16 + r0, oc1 = oc0 + 8;
    float be0 = bs[oc0], be1 = bs[oc1];
    __nv_bfloat16* o0 = &g_pre_bf[branch][b][oc0][p0];
    __nv_bfloat16* o1 = &g_pre_bf[branch][b][oc1][p0];
    #pragma unroll
    for (int np = 0; np < 8; ++np)
        #pragma unroll
        for (int f = 0; f < 2; ++f) {
            int c = np*16 + f*8 + cb;
            st_bf2(o0 + c, acc[np][f][0] + be0, acc[np][f][1] + be0);
            st_bf2(o1 + c, acc[np][f][2] + be1, acc[np][f][3] + be1);
        }
}

// ---------------- depthwise 3x3 (bf16 in) -> K,V fp32 + Q pair-packed bf16 ----------------
__global__ void k_dw(const float* __restrict__ wl, const float* __restrict__ bl,
                     const float* __restrict__ wr, const float* __restrict__ brb) {
    int z = blockIdx.z; int branch = z >> 1, b = z & 1;
    int ch = blockIdx.y;
    int y0 = blockIdx.x * 4;
    __shared__ __align__(16) float rows[6][264];
    const __nv_bfloat16* in = &g_pre_bf[branch][b][ch][0];
    const float* w  = (branch == 0 ? wl : wr) + ch*9;
    float bias = (branch == 0 ? bl : brb)[ch];
    int tid = threadIdx.x;

    for (int idx = tid; idx < 6*64; idx += 256) {
        int r = idx >> 6, c4 = idx & 63;
        int gy = y0 - 1 + r;
        float4 f = make_float4(0.f, 0.f, 0.f, 0.f);
        if (gy >= 0 && gy < HH) {
            uint2 v = *reinterpret_cast<const uint2*>(&in[gy*WW + c4*4]);
            f.x = __bfloat162float(__ushort_as_bfloat16((unsigned short)(v.x & 0xFFFF)));
            f.y = __bfloat162float(__ushort_as_bfloat16((unsigned short)(v.x >> 16)));
            f.z = __bfloat162float(__ushort_as_bfloat16((unsigned short)(v.y & 0xFFFF)));
            f.w = __bfloat162float(__ushort_as_bfloat16((unsigned short)(v.y >> 16)));
        }
        *reinterpret_cast<float4*>(&rows[r][4 + 4*c4]) = f;
    }
    if (tid < 6) { rows[tid][3] = 0.f; rows[tid][260] = 0.f; }
    __syncthreads();

    int r  = tid >> 6;
    int x0 = (tid & 63) * 4;
    float a0 = bias, a1 = bias, a2 = bias, a3 = bias;
    #pragma unroll
    for (int ky = 0; ky < 3; ++ky) {
        const float* rp = &rows[r + ky][3 + x0];
        float v0 = rp[0];
        float4 vm = *reinterpret_cast<const float4*>(rp + 1);
        float v5 = rp[5];
        float w0 = w[ky*3], w1 = w[ky*3+1], w2 = w[ky*3+2];
        a0 += w0*v0   + w1*vm.x + w2*vm.y;
        a1 += w0*vm.x + w1*vm.y + w2*vm.z;
        a2 += w0*vm.y + w1*vm.z + w2*vm.w;
        a3 += w0*vm.z + w1*vm.w + w2*v5;
    }
    int px = (y0 + r)*WW + x0;
    if (ch < CC) {
        int g = branch*CC + ch;
        unsigned short* xp16 = reinterpret_cast<unsigned short*>(&g_xp[b][g >> 1][0]);
        int half = g & 1;
        xp16[(px  )*2 + half] = __bfloat16_as_ushort(__float2bfloat16_rn(a0));
        xp16[(px+1)*2 + half] = __bfloat16_as_ushort(__float2bfloat16_rn(a1));
        xp16[(px+2)*2 + half] = __bfloat16_as_ushort(__float2bfloat16_rn(a2));
        xp16[(px+3)*2 + half] = __bfloat16_as_ushort(__float2bfloat16_rn(a3));
    } else {
        *reinterpret_cast<float4*>(&g_kv[branch][b][ch - CC][px]) = make_float4(a0, a1, a2, a3);
    }
}

// ---------------- fused dilated convs + convQ: 7-row cp.async pipeline + mma.sync ----------------
// Per CTA: (y, x-half 128px, b). 8 warps: mhalf=wid&1 (32oc), nq=wid>>1 (32px).
__global__ void __launch_bounds__(256) k_dilated_mma() {
    extern __shared__ __align__(16) uint32_t smx[];
    uint32_t* Bs = smx;                                                      // [2][48*140]
    __nv_bfloat16* As = reinterpret_cast<__nv_bfloat16*>(smx + 2*BBUF);      // [3][64][104]
    uint32_t smbB = smem_u32(Bs), smbA = smem_u32(As);
    int y = (int)blockIdx.x >> 1, x0 = ((int)blockIdx.x & 1)*128, b = blockIdx.y;
    int tid = threadIdx.x, lane = tid & 31, wid = tid >> 5;
    int mhalf = wid & 1, nq = wid >> 1;
    const uint32_t* xp = &g_xp[b][0][0];

    float acc[2][2][2][4];
    #pragma unroll
    for (int mb = 0; mb < 2; ++mb)
        #pragma unroll
        for (int np = 0; np < 2; ++np)
            #pragma unroll
            for (int f = 0; f < 2; ++f)
                #pragma unroll
                for (int q = 0; q < 4; ++q) acc[mb][np][f][q] = 0.f;

    auto fill_row = [&](int buf, int gy) {
        bool rowok = (gy >= 0 && gy < HH);
        uint32_t dbase = smbB + (uint32_t)buf*BBUF*4u;
        int gys = rowok ? gy : 0;
        for (int i = tid; i < BBUF; i += 256) {
            int kp = i / BSTR, col = i - kp*BSTR;
            int gx = x0 - 6 + col;
            bool ok = rowok && gx >= 0 && gx < WW;
            const uint32_t* src = xp + kp*HWW + gys*WW + (ok ? gx : 0);
            uint32_t sz = ok ? 4u : 0u;
            asm volatile("cp.async.ca.shared.global [%0], [%1], 4, %2;"
                         :: "r"(dbase + (uint32_t)i*4u), "l"(src), "r"(sz) : "memory");
        }
        asm volatile("cp.async.commit_group;" ::: "memory");
    };

    const int roff[7] = {0, -2, -4, -6, 2, 4, 6};
    fill_row(0, y);
    for (int ri = 0; ri < 7; ++ri) {
        asm volatile("cp.async.wait_group 0;" ::: "memory");
        __syncthreads();
        if (ri < 6) fill_row((ri + 1) & 1, y + roff[ri + 1]);
        const uint32_t* bcur = Bs + (ri & 1)*BBUF;
        int ng = (ri == 0) ? 3 : 1;
        for (int gi = 0; gi < ng; ++gi) {
            int d  = (ri == 0) ? gi : (ri <= 3 ? ri - 1 : ri - 4);
            int ky = (ri == 0) ? 1  : (ri <= 3 ? 0 : 2);
            if (gi) __syncthreads();
            {   // A fill: 3 contiguous taps (kx 0..2), 2304 uint4
                const uint4* src = reinterpret_cast<const uint4*>(&g_wbf[d*9 + ky*3][0][0]);
                for (int i = tid; i < 2304; i += 256) {
                    int tap = i / 768, r2 = i - tap*768;
                    int row = r2 / 12, cu = r2 - row*12;
                    *reinterpret_cast<uint4*>(&As[(tap*64 + row)*ASTR + cu*8]) = src[i];
                }
            }
            __syncthreads();
            int dil = 2*(d + 1);
            #pragma unroll
            for (int kx = 0; kx < 3; ++kx) {
                int coloff = 6 + (kx - 1)*dil + nq*32 + (lane >> 2);
                uint32_t ab = smbA + (uint32_t)(kx*64*ASTR)*2u;
                #pragma unroll
                for (int kb = 0; kb < 6; ++kb) {
                    uint32_t a[2][4];
                    #pragma unroll
                    for (int mb = 0; mb < 2; ++mb) {
                        int row = mhalf*32 + mb*16 + (lane & 15);
                        ldsm4(a[mb], ab + (uint32_t)(row*ASTR + kb*16 + ((lane >> 4) << 3))*2u);
                    }
                    const uint32_t* b_lo = bcur + (kb*8 + (lane & 3))*BSTR + coloff;
                    const uint32_t* b_hi = b_lo + 4*BSTR;
                    #pragma unroll
                    for (int np = 0; np < 2; ++np) {
                        uint32_t b0 = b_lo[np*16], b1 = b_hi[np*16];
                        uint32_t b2 = b_lo[np*16 + 8], b3 = b_hi[np*16 + 8];
                        #pragma unroll
                        for (int mb = 0; mb < 2; ++mb) {
                            mma16816(acc[mb][np][0], a[mb], b0, b1);
                            mma16816(acc[mb][np][1], a[mb], b2, b3);
                        }
                    }
                }
            }
        }
    }
    // epilogue: acc -> g_qfold (+bias); oc >= 48 (mhalf==1 && mb==1) discarded
    #pragma unroll
    for (int mb = 0; mb < 2; ++mb) {
        if (mhalf == 1 && mb == 1) continue;
        int oc = mhalf*32 + mb*16 + (lane >> 2);
        float be0 = g_beff[oc], be1 = g_beff[oc + 8];
        #pragma unroll
        for (int np = 0; np < 2; ++np)
            #pragma unroll
            for (int f = 0; f < 2; ++f) {
                int n = nq*32 + np*16 + f*8 + (lane & 3)*2;
                *reinterpret_cast<float2*>(&g_qfold[b][oc][y*WW + x0 + n]) =
                    make_float2(acc[mb][np][f][0] + be0, acc[mb][np][f][1] + be0);
                *reinterpret_cast<float2*>(&g_qfold[b][oc + 8][y*WW + x0 + n]) =
                    make_float2(acc[mb][np][f][2] + be1, acc[mb][np][f][3] + be1);
            }
    }
}

// ---------------- per-channel L2 norms over HW ----------------
__global__ void k_norms() {
    int gid = blockIdx.x;
    int t = gid / (BB*CC);
    int r = gid - t*(BB*CC);
    int b = r / CC, c = r - b*CC;
    const float* src;
    if (t == 0)      src = &g_qfold[b][c][0];
    else if (t == 1) src = &g_kv[0][b][c][0];
    else             src = &g_kv[1][b][c][0];
    float ss = 0.f;
    const float4* s4 = reinterpret_cast<const float4*>(src);
    for (int i = threadIdx.x; i < HWW/4; i += blockDim.x) {
        float4 v = s4[i];
        ss += v.x*v.x + v.y*v.y + v.z*v.z + v.w*v.w;
    }
    #pragma unroll
    for (int off = 16; off > 0; off >>= 1)
        ss += __shfl_down_sync(0xffffffffu, ss, off);
    __shared__ float red[8];
    if ((threadIdx.x & 31) == 0) red[threadIdx.x >> 5] = ss;
    __syncthreads();
    if (threadIdx.x == 0) {
        float tot = 0.f;
        for (int i = 0; i < (int)(blockDim.x >> 5); ++i) tot += red[i];
        g_inv[t][b][c] = 1.f / fmaxf(sqrtf(tot), 1e-12f);
    }
}

// ---------------- QK^T dot partials (deterministic two-stage) ----------------
__global__ void k_dots() {
    int chunk = blockIdx.x;
    int bh    = blockIdx.y;
    int s     = blockIdx.z;
    int b = bh / NH, h = bh - b*NH;
    const float* Q = &g_qfold[b][h*CHD][0];
    const float* K = (s == 0) ? &g_kv[1][b][h*CHD][0] : &g_kv[0][b][h*CHD][0];
    __shared__ float Qs[16][257];
    __shared__ float Ks[16][257];
    int tid = threadIdx.x;
    int cq = tid >> 4, ck = tid & 15;
    float acc = 0.f;
    int p0 = chunk * 2048;
    for (int sub = 0; sub < 8; ++sub) {
        __syncthreads();
        int pb = p0 + sub*256;
        #pragma unroll
        for (int e = 0; e < 16; ++e) {
            Qs[e][tid] = Q[e*HWW + pb + tid];
            Ks[e][tid] = K[e*HWW + pb + tid];
        }
        __syncthreads();
        #pragma unroll 16
        for (int i = 0; i < 256; ++i)
            acc += Qs[cq][i] * Ks[ck][i];
    }
    g_dpart[(((s*BB + b)*NH + h)*16 + chunk)*256 + tid] = acc;
}

// ---------------- softmax + fold conv1/2 into M ----------------
__global__ void k_soft_m(const float* __restrict__ temp,
                         const float* __restrict__ w1, const float* __restrict__ w2) {
    __shared__ float As2[192][16];
    int tid = threadIdx.x;
    if (tid < 192) {
        int s = tid / 96, rem = tid - s*96;
        int b = rem / 48, rem2 = rem - b*48;
        int h = rem2 / 16, cq = rem2 - h*16;
        float v[16];
        #pragma unroll
        for (int ck = 0; ck < 16; ++ck) v[ck] = 0.f;
        int base = (((s*BB + b)*NH + h)*16)*256 + cq*16;
        for (int chunk = 0; chunk < 16; ++chunk) {
            #pragma unroll
            for (int ck = 0; ck < 16; ++ck)
                v[ck] += g_dpart[base + chunk*256 + ck];
        }
        float iq = g_inv[0][b][h*16 + cq];
        float tm = temp[h];
        const float* ik = (s == 0) ? &g_inv[2][b][h*16] : &g_inv[1][b][h*16];
        float mx = -1e30f;
        #pragma unroll
        for (int ck = 0; ck < 16; ++ck) { v[ck] *= iq * ik[ck] * tm; mx = fmaxf(mx, v[ck]); }
        float sum = 0.f;
        #pragma unroll
        for (int ck = 0; ck < 16; ++ck) { v[ck] = expf(v[ck] - mx); sum += v[ck]; }
        float inv = 1.f / sum;
        #pragma unroll
        for (int ck = 0; ck < 16; ++ck) As2[tid][ck] = v[ck] * inv;
    }
    __syncthreads();
    for (int idx = tid; idx < 2*BB*CC*CC; idx += blockDim.x) {
        int s = idx / (BB*CC*CC), rem = idx - s*(BB*CC*CC);
        int b = rem / (CC*CC), rem2 = rem - b*(CC*CC);
        int o = rem2 / CC, dg = rem2 - o*CC;
        int h = dg / 16, dd = dg - h*16;
        const float* wv = ((s == 0) ? w1 : w2) + o*CC + h*16;
        int arow = s*96 + b*48 + h*16;
        float acc = 0.f;
        #pragma unroll
        for (int c = 0; c < 16; ++c)
            acc += wv[c] * As2[arow + c][dd];
        g_M[idx] = acc;
    }
}

// ---------------- epilogue: out = x + M @ V + bias ----------------
__global__ void k_epilogue(const float* __restrict__ xl, const float* __restrict__ xr,
                           const float* __restrict__ b1, const float* __restrict__ b2,
                           float* __restrict__ out) {
    int s = blockIdx.z, b = blockIdx.y;
    int p = blockIdx.x * blockDim.x + threadIdx.x;
    __shared__ __align__(16) float Ms[CC*CC];
    __shared__ float bss[CC];
    const float* Mg = &g_M[(s*BB + b)*CC*CC];
    for (int i = threadIdx.x; i < CC*CC; i += blockDim.x) Ms[i] = Mg[i];
    for (int i = threadIdx.x; i < CC; i += blockDim.x) bss[i] = (s == 0 ? b1 : b2)[i];
    __syncthreads();
    const float* V = &g_kv[s][b][CC][0];
    const float* x = (s == 0 ? xl : xr) + b*CC*HWW;
    float* o = out + (s*BB + b)*CC*HWW;
    float v[CC];
    #pragma unroll
    for (int c = 0; c < CC; ++c) v[c] = V[c*HWW + p];
    for (int oc = 0; oc < CC; ++oc) {
        float acc = bss[oc];
        const float4* m4 = reinterpret_cast<const float4*>(&Ms[oc*CC]);
        #pragma unroll
        for (int c4 = 0; c4 < CC/4; ++c4) {
            float4 mv = m4[c4];
            acc += mv.x*v[4*c4] + mv.y*v[4*c4+1] + mv.z*v[4*c4+2] + mv.w*v[4*c4+3];
        }
        o[oc*HWW + p] = x[oc*HWW + p] + acc;
    }
}

// ---------------- launch ----------------
extern "C" void kernel_launch(void* const* d_in, const int* in_sizes, int n_in,
                              void* d_out, int out_size) {
    const float* x_l    = (const float*)d_in[0];
    const float* x_r    = (const float*)d_in[1];
    const float* ln1_w  = (const float*)d_in[2];
    const float* ln1_b  = (const float*)d_in[3];
    const float* ln2_w  = (const float*)d_in[4];
    const float* ln2_b  = (const float*)d_in[5];
    const float* qkvl_w = (const float*)d_in[6];
    const float* qkvl_b = (const float*)d_in[7];
    const float* qkvr_w = (const float*)d_in[8];
    const float* qkvr_b = (const float*)d_in[9];
    const float* dwl_w  = (const float*)d_in[10];
    const float* dwl_b  = (const float*)d_in[11];
    const float* dwr_w  = (const float*)d_in[12];
    const float* dwr_b  = (const float*)d_in[13];
    const float* dil0_w = (const float*)d_in[14];
    const float* dil0_b = (const float*)d_in[15];
    const float* dil1_w = (const float*)d_in[16];
    const float* dil1_b = (const float*)d_in[17];
    const float* dil2_w = (const float*)d_in[18];
    const float* dil2_b = (const float*)d_in[19];
    const float* convQ_w = (const float*)d_in[20];
    const float* convQ_b = (const float*)d_in[21];
    const float* conv1_w = (const float*)d_in[22];
    const float* conv1_b = (const float*)d_in[23];
    const float* conv2_w = (const float*)d_in[24];
    const float* conv2_b = (const float*)d_in[25];
    const float* temperature = (const float*)d_in[26];

    const int SMD = (2*BBUF)*4 + 3*64*ASTR*2;   // 53760 + 39936 = 93696
    cudaFuncSetAttribute(k_dilated_mma, cudaFuncAttributeMaxDynamicSharedMemorySize, SMD);

    k_prep_w<<<54, 256>>>(qkvl_w, qkvr_w);
    k_zero_w<<<324, 256>>>();
    k_fold_w<<<dim3(CC, 3), 256>>>(convQ_w, dil0_w, dil1_w, dil2_w);
    k_fold_b<<<1, 64>>>(convQ_w, convQ_b, dil0_b, dil1_b, dil2_b);
    k_ln<<<dim3(HWW/256, BB, 2), 256>>>(x_l, x_r, ln1_w, ln1_b, ln2_w, ln2_b);
    k_qkv_mma<<<dim3(HWW/128, BB, 2), 288>>>(qkvl_b, qkvr_b);
    k_dw<<<dim3(HH/4, C3, 2*BB), 256>>>(dwl_w, dwl_b, dwr_w, dwr_b);
    k_dilated_mma<<<dim3(2*HH, BB), 256, SMD>>>();
    k_norms<<<3*BB*CC, 256>>>();
    k_dots<<<dim3(16, BB*NH, 2), 256>>>();
    k_soft_m<<<1, 256>>>(temperature, conv1_w, conv2_w);
    k_epilogue<<<dim3(HWW/256, BB, 2), 256>>>(x_l, x_r, conv1_b, conv2_b, (float*)d_out);
}

// round 7
// speedup vs baseline: 3.0725x; 1.1408x over previous
#include <cuda_runtime.h>
#include <cuda_bf16.h>
#include <cstdint>
#include <math.h>

#define BB   2
#define CC   48
#define HH   128
#define WW   256
#define HWW  (HH*WW)          // 32768
#define C3   144
#define C2   96
#define NH   3
#define CHD  16
#define BSTR 140              // pair-packed B row stride (u32); 140 % 32 == 12 -> conflict-free
#define ASTR 104              // A tile row stride (bf16)
#define BBUF (48*BSTR)        // u32 per B buffer
#define VSTR 260              // epilogue V row stride (u32); 260 % 32 == 4 -> conflict-free

// ---------------- scratch (static device globals; no allocation) ----------------
__device__ __nv_bfloat16  g_pre_bf [2][BB][C3][HWW];   // bf16 qkv after LN+1x1
__device__ float          g_kv     [2][BB][CC][HWW];   // fp32 K after dw
__device__ uint32_t       g_vp     [2][BB][24][HWW];   // pair-packed bf16 V after dw
__device__ uint32_t       g_xp     [BB][CC][HWW];      // pair-packed bf16 [Q_l;Q_r] (96ch -> 48 pairs)
__device__ uint32_t       g_xnp    [2][BB][24][HWW];   // pair-packed bf16 LN output
__device__ float          g_qfold  [BB][CC][HWW];      // fused dilated-conv + convQ output
__device__ __nv_bfloat16  g_wbf    [27][64][C2];       // folded bf16 weights (oc pad 64)
__device__ __nv_bfloat16  g_wq     [2][C3][CC];        // bf16 qkv weights
__device__ float          g_beff   [CC];
__device__ float          g_inv    [3][BB][CC];
__device__ float          g_dpart  [2*BB*NH*16*256];
__device__ __nv_bfloat16  g_Mbf    [2*BB][CC*CC];      // folded conv1/2 @ blockdiag(A), bf16

__device__ __forceinline__ uint32_t smem_u32(const void* p) {
    uint32_t a;
    asm("{ .reg .u64 t; cvta.to.shared.u64 t, %1; cvt.u32.u64 %0, t; }" : "=r"(a) : "l"(p));
    return a;
}
__device__ __forceinline__ void ldsm4(uint32_t* r, uint32_t addr) {
    asm volatile("ldmatrix.sync.aligned.m8n8.x4.shared.b16 {%0,%1,%2,%3}, [%4];"
        : "=r"(r[0]), "=r"(r[1]), "=r"(r[2]), "=r"(r[3]) : "r"(addr));
}
__device__ __forceinline__ void mma16816(float* c, const uint32_t* a, uint32_t b0, uint32_t b1) {
    asm volatile("mma.sync.aligned.m16n8k16.row.col.f32.bf16.bf16.f32 "
        "{%0,%1,%2,%3}, {%4,%5,%6,%7}, {%8,%9}, {%0,%1,%2,%3};"
        : "+f"(c[0]), "+f"(c[1]), "+f"(c[2]), "+f"(c[3])
        : "r"(a[0]), "r"(a[1]), "r"(a[2]), "r"(a[3]), "r"(b0), "r"(b1));
}
__device__ __forceinline__ void st_bf2(__nv_bfloat16* p, float a, float b) {
    uint32_t u = (uint32_t)__bfloat16_as_ushort(__float2bfloat16_rn(a))
               | ((uint32_t)__bfloat16_as_ushort(__float2bfloat16_rn(b)) << 16);
    *reinterpret_cast<uint32_t*>(p) = u;
}

// ---------------- merged prelude: prep_w + pad-zero + fold_b ----------------
__global__ void k_misc(const float* __restrict__ wl, const float* __restrict__ wr,
                       const float* __restrict__ cqw, const float* __restrict__ cqb,
                       const float* __restrict__ d0b, const float* __restrict__ d1b,
                       const float* __restrict__ d2b) {
    int blk = blockIdx.x, tid = threadIdx.x;
    if (blk < 54) {                               // qkv weights -> bf16
        int i = blk*256 + tid;                    // 54*256 = 13824 = 2*C3*CC
        int s = i / (C3*CC), r = i - s*(C3*CC);
        reinterpret_cast<__nv_bfloat16*>(g_wq)[i] = __float2bfloat16_rn((s ? wr : wl)[r]);
    } else if (blk < 95) {                        // zero pad rows 48..63 of g_wbf
        int j = (blk - 54)*256 + tid;             // 27*384 = 10368 u32
        if (j < 27*384) {
            int tap = j / 384, r = j - tap*384;
            reinterpret_cast<uint32_t*>(g_wbf)[tap*3072 + 2304 + r] = 0u;
        }
    } else {                                      // fold_b, parallel
        __shared__ float racc[192];
        if (tid < 192) {
            int o = tid >> 2, q = tid & 3;
            float acc = 0.f;
            for (int j = q*72; j < q*72 + 72; ++j) {
                int dd = j / 96, jj = j - dd*96;
                const float* bp = (dd == 0) ? d0b : (dd == 1) ? d1b : d2b;
                acc += cqw[o*288 + j] * bp[jj];
            }
            racc[tid] = acc;
        }
        __syncthreads();
        if (tid < CC)
            g_beff[tid] = cqb[tid] + racc[tid*4] + racc[tid*4+1] + racc[tid*4+2] + racc[tid*4+3];
    }
}

// ---------------- weight folding: W_eff = convQ x dil_w -> bf16 [tap][64][96] ----------------
__global__ void k_fold_w(const float* __restrict__ qw, const float* __restrict__ d0,
                         const float* __restrict__ d1, const float* __restrict__ d2) {
    int o = blockIdx.x, d = blockIdx.y;
    const float* dw = (d == 0) ? d0 : (d == 1) ? d1 : d2;
    __shared__ float qr[C2];
    for (int j = threadIdx.x; j < C2; j += blockDim.x)
        qr[j] = qw[o*(3*C2) + d*C2 + j];
    __syncthreads();
    for (int ik = threadIdx.x; ik < C2*9; ik += blockDim.x) {
        float acc = 0.f;
        for (int j = 0; j < C2; ++j)
            acc += qr[j] * dw[j*(C2*9) + ik];
        int i = ik / 9, kk = ik - i*9;
        g_wbf[d*9 + kk][o][i] = __float2bfloat16_rn(acc);
    }
}

// ---------------- LayerNorm2d -> pair-packed bf16 ----------------
__global__ void k_ln(const float* __restrict__ xl, const float* __restrict__ xr,
                     const float* __restrict__ ln1w, const float* __restrict__ ln1b,
                     const float* __restrict__ ln2w, const float* __restrict__ ln2b) {
    int branch = blockIdx.z, b = blockIdx.y;
    int p = blockIdx.x*blockDim.x + threadIdx.x;
    const float* x  = (branch == 0 ? xl : xr) + b*CC*HWW;
    const float* lw = branch == 0 ? ln1w : ln2w;
    const float* lb = branch == 0 ? ln1b : ln2b;
    __shared__ float lws[CC], lbs[CC];
    for (int i = threadIdx.x; i < CC; i += blockDim.x) { lws[i] = lw[i]; lbs[i] = lb[i]; }
    __syncthreads();
    float y[CC]; float mu = 0.f;
    #pragma unroll
    for (int c = 0; c < CC; ++c) { y[c] = x[c*HWW + p]; mu += y[c]; }
    mu *= (1.f/CC);
    float var = 0.f;
    #pragma unroll
    for (int c = 0; c < CC; ++c) { float t = y[c] - mu; var += t*t; }
    float rstd = rsqrtf(var*(1.f/CC) + 1e-6f);
    uint32_t* out = &g_xnp[branch][b][0][p];
    #pragma unroll
    for (int kp = 0; kp < 24; ++kp) {
        float v0 = (y[2*kp]   - mu)*rstd*lws[2*kp]   + lbs[2*kp];
        float v1 = (y[2*kp+1] - mu)*rstd*lws[2*kp+1] + lbs[2*kp+1];
        uint32_t u = (uint32_t)__bfloat16_as_ushort(__float2bfloat16_rn(v0))
                   | ((uint32_t)__bfloat16_as_ushort(__float2bfloat16_rn(v1)) << 16);
        out[kp*HWW] = u;
    }
}

// ---------------- 1x1 qkv GEMM via mma.sync: [144x48] @ [48 x 128px] ----------------
__global__ void __launch_bounds__(288) k_qkv_mma(const float* __restrict__ bl,
                                                 const float* __restrict__ br) {
    __shared__ __align__(16) __nv_bfloat16 As[C3*CC];
    __shared__ uint32_t Bs[24*BSTR];
    __shared__ float bs[C3];
    int p0 = blockIdx.x*128, b = blockIdx.y, branch = blockIdx.z;
    int tid = threadIdx.x, lane = tid & 31, wid = tid >> 5;   // 9 warps
    {
        const uint4* src = reinterpret_cast<const uint4*>(&g_wq[branch][0][0]);
        uint4* dst = reinterpret_cast<uint4*>(As);
        for (int i = tid; i < C3*CC/8; i += 288) dst[i] = src[i];
        const float* bp = branch ? br : bl;
        for (int i = tid; i < C3; i += 288) bs[i] = bp[i];
        const uint32_t* xsrc = &g_xnp[branch][b][0][0];
        for (int i = tid; i < 24*128; i += 288) {
            int kp = i >> 7, col = i & 127;
            Bs[kp*BSTR + col] = xsrc[kp*HWW + p0 + col];
        }
    }
    __syncthreads();
    float acc[8][2][4];
    #pragma unroll
    for (int np = 0; np < 8; ++np)
        #pragma unroll
        for (int f = 0; f < 2; ++f)
            #pragma unroll
            for (int q = 0; q < 4; ++q) acc[np][f][q] = 0.f;
    uint32_t smbA = smem_u32(As);
    #pragma unroll
    for (int kb = 0; kb < 3; ++kb) {
        uint32_t a[4];
        int row = wid*16 + (lane & 15);
        ldsm4(a, smbA + (uint32_t)(row*CC + kb*16 + ((lane >> 4) << 3))*2u);
        const uint32_t* b_lo = Bs + (kb*8 + (lane & 3))*BSTR + (lane >> 2);
        const uint32_t* b_hi = b_lo + 4*BSTR;
        #pragma unroll
        for (int np = 0; np < 8; ++np) {
            uint32_t b0 = b_lo[np*16], b1 = b_hi[np*16];
            uint32_t b2 = b_lo[np*16 + 8], b3 = b_hi[np*16 + 8];
            mma16816(acc[np][0], a, b0, b1);
            mma16816(acc[np][1], a, b2, b3);
        }
    }
    int r0 = lane >> 2, cb = (lane & 3)*2;
    int oc0 = wid*16 + r0, oc1 = oc0 + 8;
    float be0 = bs[oc0], be1 = bs[oc1];
    __nv_bfloat16* o0 = &g_pre_bf[branch][b][oc0][p0];
    __nv_bfloat16* o1 = &g_pre_bf[branch][b][oc1][p0];
    #pragma unroll
    for (int np = 0; np < 8; ++np)
        #pragma unroll
        for (int f = 0; f < 2; ++f) {
            int c = np*16 + f*8 + cb;
            st_bf2(o0 + c, acc[np][f][0] + be0, acc[np][f][1] + be0);
            st_bf2(o1 + c, acc[np][f][2] + be1, acc[np][f][3] + be1);
        }
}

// ---------------- depthwise 3x3 (bf16 in) -> K fp32 + Q,V pair-packed bf16 ----------------
__global__ void k_dw(const float* __restrict__ wl, const float* __restrict__ bl,
                     const float* __restrict__ wr, const float* __restrict__ brb) {
    int z = blockIdx.z; int branch = z >> 1, b = z & 1;
    int ch = blockIdx.y;
    int y0 = blockIdx.x * 4;
    __shared__ __align__(16) float rows[6][264];
    const __nv_bfloat16* in = &g_pre_bf[branch][b][ch][0];
    const float* w  = (branch == 0 ? wl : wr) + ch*9;
    float bias = (branch == 0 ? bl : brb)[ch];
    int tid = threadIdx.x;

    for (int idx = tid; idx < 6*64; idx += 256) {
        int r = idx >> 6, c4 = idx & 63;
        int gy = y0 - 1 + r;
        float4 f = make_float4(0.f, 0.f, 0.f, 0.f);
        if (gy >= 0 && gy < HH) {
            uint2 v = *reinterpret_cast<const uint2*>(&in[gy*WW + c4*4]);
            f.x = __bfloat162float(__ushort_as_bfloat16((unsigned short)(v.x & 0xFFFF)));
            f.y = __bfloat162float(__ushort_as_bfloat16((unsigned short)(v.x >> 16)));
            f.z = __bfloat162float(__ushort_as_bfloat16((unsigned short)(v.y & 0xFFFF)));
            f.w = __bfloat162float(__ushort_as_bfloat16((unsigned short)(v.y >> 16)));
        }
        *reinterpret_cast<float4*>(&rows[r][4 + 4*c4]) = f;
    }
    if (tid < 6) { rows[tid][3] = 0.f; rows[tid][260] = 0.f; }
    __syncthreads();

    int r  = tid >> 6;
    int x0 = (tid & 63) * 4;
    float a0 = bias, a1 = bias, a2 = bias, a3 = bias;
    #pragma unroll
    for (int ky = 0; ky < 3; ++ky) {
        const float* rp = &rows[r + ky][3 + x0];
        float v0 = rp[0];
        float4 vm = *reinterpret_cast<const float4*>(rp + 1);
        float v5 = rp[5];
        float w0 = w[ky*3], w1 = w[ky*3+1], w2 = w[ky*3+2];
        a0 += w0*v0   + w1*vm.x + w2*vm.y;
        a1 += w0*vm.x + w1*vm.y + w2*vm.z;
        a2 += w0*vm.y + w1*vm.z + w2*vm.w;
        a3 += w0*vm.z + w1*vm.w + w2*v5;
    }
    int px = (y0 + r)*WW + x0;
    if (ch < CC) {                 // Q -> pair-packed bf16
        int g = branch*CC + ch;
        unsigned short* xp16 = reinterpret_cast<unsigned short*>(&g_xp[b][g >> 1][0]);
        int half = g & 1;
        xp16[(px  )*2 + half] = __bfloat16_as_ushort(__float2bfloat16_rn(a0));
        xp16[(px+1)*2 + half] = __bfloat16_as_ushort(__float2bfloat16_rn(a1));
        xp16[(px+2)*2 + half] = __bfloat16_as_ushort(__float2bfloat16_rn(a2));
        xp16[(px+3)*2 + half] = __bfloat16_as_ushort(__float2bfloat16_rn(a3));
    } else if (ch < 2*CC) {        // K -> fp32
        *reinterpret_cast<float4*>(&g_kv[branch][b][ch - CC][px]) = make_float4(a0, a1, a2, a3);
    } else {                       // V -> pair-packed bf16
        int v = ch - 2*CC;
        unsigned short* vp16 = reinterpret_cast<unsigned short*>(&g_vp[branch][b][v >> 1][0]);
        int half = v & 1;
        vp16[(px  )*2 + half] = __bfloat16_as_ushort(__float2bfloat16_rn(a0));
        vp16[(px+1)*2 + half] = __bfloat16_as_ushort(__float2bfloat16_rn(a1));
        vp16[(px+2)*2 + half] = __bfloat16_as_ushort(__float2bfloat16_rn(a2));
        vp16[(px+3)*2 + half] = __bfloat16_as_ushort(__float2bfloat16_rn(a3));
    }
}

// ---------------- fused dilated convs + convQ: 7-row cp.async pipeline + mma.sync ----------------
__global__ void __launch_bounds__(256) k_dilated_mma() {
    extern __shared__ __align__(16) uint32_t smx[];
    uint32_t* Bs = smx;                                                      // [2][48*140]
    __nv_bfloat16* As = reinterpret_cast<__nv_bfloat16*>(smx + 2*BBUF);      // [3][64][104]
    uint32_t smbB = smem_u32(Bs), smbA = smem_u32(As);
    int y = (int)blockIdx.x >> 1, x0 = ((int)blockIdx.x & 1)*128, b = blockIdx.y;
    int tid = threadIdx.x, lane = tid & 31, wid = tid >> 5;
    int mhalf = wid & 1, nq = wid >> 1;
    const uint32_t* xp = &g_xp[b][0][0];

    float acc[2][2][2][4];
    #pragma unroll
    for (int mb = 0; mb < 2; ++mb)
        #pragma unroll
        for (int np = 0; np < 2; ++np)
            #pragma unroll
            for (int f = 0; f < 2; ++f)
                #pragma unroll
                for (int q = 0; q < 4; ++q) acc[mb][np][f][q] = 0.f;

    auto fill_row = [&](int buf, int gy) {
        bool rowok = (gy >= 0 && gy < HH);
        uint32_t dbase = smbB + (uint32_t)buf*BBUF*4u;
        int gys = rowok ? gy : 0;
        for (int i = tid; i < BBUF; i += 256) {
            int kp = i / BSTR, col = i - kp*BSTR;
            int gx = x0 - 6 + col;
            bool ok = rowok && gx >= 0 && gx < WW;
            const uint32_t* src = xp + kp*HWW + gys*WW + (ok ? gx : 0);
            uint32_t sz = ok ? 4u : 0u;
            asm volatile("cp.async.ca.shared.global [%0], [%1], 4, %2;"
                         :: "r"(dbase + (uint32_t)i*4u), "l"(src), "r"(sz) : "memory");
        }
        asm volatile("cp.async.commit_group;" ::: "memory");
    };

    const int roff[7] = {0, -2, -4, -6, 2, 4, 6};
    fill_row(0, y);
    for (int ri = 0; ri < 7; ++ri) {
        asm volatile("cp.async.wait_group 0;" ::: "memory");
        __syncthreads();
        if (ri < 6) fill_row((ri + 1) & 1, y + roff[ri + 1]);
        const uint32_t* bcur = Bs + (ri & 1)*BBUF;
        int ng = (ri == 0) ? 3 : 1;
        for (int gi = 0; gi < ng; ++gi) {
            int d  = (ri == 0) ? gi : (ri <= 3 ? ri - 1 : ri - 4);
            int ky = (ri == 0) ? 1  : (ri <= 3 ? 0 : 2);
            if (gi) __syncthreads();
            {   // A fill: 3 contiguous taps (kx 0..2)
                const uint4* src = reinterpret_cast<const uint4*>(&g_wbf[d*9 + ky*3][0][0]);
                for (int i = tid; i < 2304; i += 256) {
                    int tap = i / 768, r2 = i - tap*768;
                    int row = r2 / 12, cu = r2 - row*12;
                    *reinterpret_cast<uint4*>(&As[(tap*64 + row)*ASTR + cu*8]) = src[i];
                }
            }
            __syncthreads();
            int dil = 2*(d + 1);
            #pragma unroll
            for (int kx = 0; kx < 3; ++kx) {
                int coloff = 6 + (kx - 1)*dil + nq*32 + (lane >> 2);
                uint32_t ab = smbA + (uint32_t)(kx*64*ASTR)*2u;
                #pragma unroll
                for (int kb = 0; kb < 6; ++kb) {
                    uint32_t a[2][4];
                    #pragma unroll
                    for (int mb = 0; mb < 2; ++mb) {
                        int row = mhalf*32 + mb*16 + (lane & 15);
                        ldsm4(a[mb], ab + (uint32_t)(row*ASTR + kb*16 + ((lane >> 4) << 3))*2u);
                    }
                    const uint32_t* b_lo = bcur + (kb*8 + (lane & 3))*BSTR + coloff;
                    const uint32_t* b_hi = b_lo + 4*BSTR;
                    #pragma unroll
                    for (int np = 0; np < 2; ++np) {
                        uint32_t b0 = b_lo[np*16], b1 = b_hi[np*16];
                        uint32_t b2 = b_lo[np*16 + 8], b3 = b_hi[np*16 + 8];
                        #pragma unroll
                        for (int mb = 0; mb < 2; ++mb) {
                            mma16816(acc[mb][np][0], a[mb], b0, b1);
                            mma16816(acc[mb][np][1], a[mb], b2, b3);
                        }
                    }
                }
            }
        }
    }
    #pragma unroll
    for (int mb = 0; mb < 2; ++mb) {
        if (mhalf == 1 && mb == 1) continue;
        int oc = mhalf*32 + mb*16 + (lane >> 2);
        float be0 = g_beff[oc], be1 = g_beff[oc + 8];
        #pragma unroll
        for (int np = 0; np < 2; ++np)
            #pragma unroll
            for (int f = 0; f < 2; ++f) {
                int n = nq*32 + np*16 + f*8 + (lane & 3)*2;
                *reinterpret_cast<float2*>(&g_qfold[b][oc][y*WW + x0 + n]) =
                    make_float2(acc[mb][np][f][0] + be0, acc[mb][np][f][1] + be0);
                *reinterpret_cast<float2*>(&g_qfold[b][oc + 8][y*WW + x0 + n]) =
                    make_float2(acc[mb][np][f][2] + be1, acc[mb][np][f][3] + be1);
            }
    }
}

// ---------------- per-channel L2 norms over HW ----------------
__global__ void k_norms() {
    int gid = blockIdx.x;
    int t = gid / (BB*CC);
    int r = gid - t*(BB*CC);
    int b = r / CC, c = r - b*CC;
    const float* src;
    if (t == 0)      src = &g_qfold[b][c][0];
    else if (t == 1) src = &g_kv[0][b][c][0];
    else             src = &g_kv[1][b][c][0];
    float ss = 0.f;
    const float4* s4 = reinterpret_cast<const float4*>(src);
    for (int i = threadIdx.x; i < HWW/4; i += blockDim.x) {
        float4 v = s4[i];
        ss += v.x*v.x + v.y*v.y + v.z*v.z + v.w*v.w;
    }
    #pragma unroll
    for (int off = 16; off > 0; off >>= 1)
        ss += __shfl_down_sync(0xffffffffu, ss, off);
    __shared__ float red[8];
    if ((threadIdx.x & 31) == 0) red[threadIdx.x >> 5] = ss;
    __syncthreads();
    if (threadIdx.x == 0) {
        float tot = 0.f;
        for (int i = 0; i < (int)(blockDim.x >> 5); ++i) tot += red[i];
        g_inv[t][b][c] = 1.f / fmaxf(sqrtf(tot), 1e-12f);
    }
}

// ---------------- QK^T dot partials, 2x2 register-blocked ----------------
__global__ void k_dots() {
    int chunk = blockIdx.x;
    int bh    = blockIdx.y;
    int s     = blockIdx.z;
    int b = bh / NH, h = bh - b*NH;
    const float* Q = &g_qfold[b][h*CHD][0];
    const float* K = (s == 0) ? &g_kv[1][b][h*CHD][0] : &g_kv[0][b][h*CHD][0];
    __shared__ float Qs[16][257];
    __shared__ float Ks[16][257];
    __shared__ float red[4][64][4];
    int tid = threadIdx.x;
    int pos = tid & 63, seg = tid >> 6;
    int cq = pos >> 3, ck = pos & 7;
    float a00 = 0.f, a01 = 0.f, a10 = 0.f, a11 = 0.f;
    int p0 = chunk * 2048;
    for (int sub = 0; sub < 8; ++sub) {
        __syncthreads();
        int pb = p0 + sub*256;
        #pragma unroll
        for (int e = 0; e < 16; ++e) {
            Qs[e][tid] = Q[e*HWW + pb + tid];
            Ks[e][tid] = K[e*HWW + pb + tid];
        }
        __syncthreads();
        int i0 = seg*64;
        #pragma unroll 16
        for (int i = 0; i < 64; ++i) {
            float q0 = Qs[cq][i0 + i], q1 = Qs[cq + 8][i0 + i];
            float k0 = Ks[ck][i0 + i], k1 = Ks[ck + 8][i0 + i];
            a00 += q0*k0; a01 += q0*k1; a10 += q1*k0; a11 += q1*k1;
        }
    }
    red[seg][pos][0] = a00; red[seg][pos][1] = a01;
    red[seg][pos][2] = a10; red[seg][pos][3] = a11;
    __syncthreads();
    if (tid < 64) {
        float v[4];
        #pragma unroll
        for (int q = 0; q < 4; ++q)
            v[q] = red[0][tid][q] + red[1][tid][q] + red[2][tid][q] + red[3][tid][q];
        int base = (((s*BB + b)*NH + h)*16 + chunk)*256;
        int cq0 = tid >> 3, ck0 = tid & 7;
        g_dpart[base + (cq0    )*16 + ck0    ] = v[0];
        g_dpart[base + (cq0    )*16 + ck0 + 8] = v[1];
        g_dpart[base + (cq0 + 8)*16 + ck0    ] = v[2];
        g_dpart[base + (cq0 + 8)*16 + ck0 + 8] = v[3];
    }
}

// ---------------- softmax + fold conv1/2 into bf16 M ----------------
__global__ void k_soft_m(const float* __restrict__ temp,
                         const float* __restrict__ w1, const float* __restrict__ w2) {
    __shared__ float As2[192][16];
    int tid = threadIdx.x;
    if (tid < 192) {
        int s = tid / 96, rem = tid - s*96;
        int b = rem / 48, rem2 = rem - b*48;
        int h = rem2 / 16, cq = rem2 - h*16;
        float v[16];
        #pragma unroll
        for (int ck = 0; ck < 16; ++ck) v[ck] = 0.f;
        int base = (((s*BB + b)*NH + h)*16)*256 + cq*16;
        for (int chunk = 0; chunk < 16; ++chunk) {
            #pragma unroll
            for (int ck = 0; ck < 16; ++ck)
                v[ck] += g_dpart[base + chunk*256 + ck];
        }
        float iq = g_inv[0][b][h*16 + cq];
        float tm = temp[h];
        const float* ik = (s == 0) ? &g_inv[2][b][h*16] : &g_inv[1][b][h*16];
        float mx = -1e30f;
        #pragma unroll
        for (int ck = 0; ck < 16; ++ck) { v[ck] *= iq * ik[ck] * tm; mx = fmaxf(mx, v[ck]); }
        float sum = 0.f;
        #pragma unroll
        for (int ck = 0; ck < 16; ++ck) { v[ck] = expf(v[ck] - mx); sum += v[ck]; }
        float inv = 1.f / sum;
        #pragma unroll
        for (int ck = 0; ck < 16; ++ck) As2[tid][ck] = v[ck] * inv;
    }
    __syncthreads();
    for (int idx = tid; idx < 2*BB*CC*CC; idx += blockDim.x) {
        int s = idx / (BB*CC*CC), rem = idx - s*(BB*CC*CC);
        int b = rem / (CC*CC), rem2 = rem - b*(CC*CC);
        int o = rem2 / CC, dg = rem2 - o*CC;
        int h = dg / 16, dd = dg - h*16;
        const float* wv = ((s == 0) ? w1 : w2) + o*CC + h*16;
        int arow = s*96 + b*48 + h*16;
        float acc = 0.f;
        #pragma unroll
        for (int c = 0; c < 16; ++c)
            acc += wv[c] * As2[arow + c][dd];
        g_Mbf[s*BB + b][o*CC + dg] = __float2bfloat16_rn(acc);
    }
}

// ---------------- epilogue: out = x + M @ V + bias via mma.sync ----------------
__global__ void __launch_bounds__(256) k_epilogue(const float* __restrict__ xl,
                                                  const float* __restrict__ xr,
                                                  const float* __restrict__ b1,
                                                  const float* __restrict__ b2,
                                                  float* __restrict__ out) {
    __shared__ __align__(16) __nv_bfloat16 Ms[CC*CC];
    __shared__ uint32_t Vs[24*VSTR];
    __shared__ float bss[CC];
    int p0 = blockIdx.x*256, b = blockIdx.y, s = blockIdx.z;
    int tid = threadIdx.x, lane = tid & 31, nq = tid >> 5;
    {
        const uint4* src = reinterpret_cast<const uint4*>(&g_Mbf[s*BB + b][0]);
        uint4* dst = reinterpret_cast<uint4*>(Ms);
        for (int i = tid; i < CC*CC/8; i += 256) dst[i] = src[i];
        const uint32_t* vsrc = &g_vp[s][b][0][0];
        for (int i = tid; i < 24*256; i += 256) {
            int kp = i >> 8, col = i & 255;
            Vs[kp*VSTR + col] = vsrc[kp*HWW + p0 + col];
        }
        const float* bp = s ? b2 : b1;
        for (int i = tid; i < CC; i += 256) bss[i] = bp[i];
    }
    __syncthreads();
    float acc[3][2][2][4];
    #pragma unroll
    for (int mb = 0; mb < 3; ++mb)
        #pragma unroll
        for (int np = 0; np < 2; ++np)
            #pragma unroll
            for (int f = 0; f < 2; ++f)
                #pragma unroll
                for (int q = 0; q < 4; ++q) acc[mb][np][f][q] = 0.f;
    uint32_t smbA = smem_u32(Ms);
    #pragma unroll
    for (int kb = 0; kb < 3; ++kb) {
        uint32_t a[3][4];
        #pragma unroll
        for (int mb = 0; mb < 3; ++mb) {
            int row = mb*16 + (lane & 15);
            ldsm4(a[mb], smbA + (uint32_t)(row*CC + kb*16 + ((lane >> 4) << 3))*2u);
        }
        const uint32_t* b_lo = Vs + (kb*8 + (lane & 3))*VSTR + nq*32 + (lane >> 2);
        const uint32_t* b_hi = b_lo + 4*VSTR;
        #pragma unroll
        for (int np = 0; np < 2; ++np) {
            uint32_t b0 = b_lo[np*16], b1 = b_hi[np*16];
            uint32_t b2v = b_lo[np*16 + 8], b3 = b_hi[np*16 + 8];
            #pragma unroll
            for (int mb = 0; mb < 3; ++mb) {
                mma16816(acc[mb][np][0], a[mb], b0, b1);
                mma16816(acc[mb][np][1], a[mb], b2v, b3);
            }
        }
    }
    const float* x = (s == 0 ? xl : xr) + b*CC*HWW;
    float* o = out + (s*BB + b)*CC*HWW;
    #pragma unroll
    for (int mb = 0; mb < 3; ++mb) {
        int oc0 = mb*16 + (lane >> 2), oc1 = oc0 + 8;
        float be0 = bss[oc0], be1 = bss[oc1];
        #pragma unroll
        for (int np = 0; np < 2; ++np)
            #pragma unroll
            for (int f = 0; f < 2; ++f) {
                int px = p0 + nq*32 + np*16 + f*8 + (lane & 3)*2;
                float2 x0 = *reinterpret_cast<const float2*>(&x[oc0*HWW + px]);
                float2 x1 = *reinterpret_cast<const float2*>(&x[oc1*HWW + px]);
                *reinterpret_cast<float2*>(&o[oc0*HWW + px]) =
                    make_float2(x0.x + acc[mb][np][f][0] + be0, x0.y + acc[mb][np][f][1] + be0);
                *reinterpret_cast<float2*>(&o[oc1*HWW + px]) =
                    make_float2(x1.x + acc[mb][np][f][2] + be1, x1.y + acc[mb][np][f][3] + be1);
            }
    }
}

// ---------------- launch ----------------
extern "C" void kernel_launch(void* const* d_in, const int* in_sizes, int n_in,
                              void* d_out, int out_size) {
    const float* x_l    = (const float*)d_in[0];
    const float* x_r    = (const float*)d_in[1];
    const float* ln1_w  = (const float*)d_in[2];
    const float* ln1_b  = (const float*)d_in[3];
    const float* ln2_w  = (const float*)d_in[4];
    const float* ln2_b  = (const float*)d_in[5];
    const float* qkvl_w = (const float*)d_in[6];
    const float* qkvl_b = (const float*)d_in[7];
    const float* qkvr_w = (const float*)d_in[8];
    const float* qkvr_b = (const float*)d_in[9];
    const float* dwl_w  = (const float*)d_in[10];
    const float* dwl_b  = (const float*)d_in[11];
    const float* dwr_w  = (const float*)d_in[12];
    const float* dwr_b  = (const float*)d_in[13];
    const float* dil0_w = (const float*)d_in[14];
    const float* dil0_b = (const float*)d_in[15];
    const float* dil1_w = (const float*)d_in[16];
    const float* dil1_b = (const float*)d_in[17];
    const float* dil2_w = (const float*)d_in[18];
    const float* dil2_b = (const float*)d_in[19];
    const float* convQ_w = (const float*)d_in[20];
    const float* convQ_b = (const float*)d_in[21];
    const float* conv1_w = (const float*)d_in[22];
    const float* conv1_b = (const float*)d_in[23];
    const float* conv2_w = (const float*)d_in[24];
    const float* conv2_b = (const float*)d_in[25];
    const float* temperature = (const float*)d_in[26];

    const int SMD = (2*BBUF)*4 + 3*64*ASTR*2;   // 53760 + 39936 = 93696
    cudaFuncSetAttribute(k_dilated_mma, cudaFuncAttributeMaxDynamicSharedMemorySize, SMD);

    k_misc<<<96, 256>>>(qkvl_w, qkvr_w, convQ_w, convQ_b, dil0_b, dil1_b, dil2_b);
    k_fold_w<<<dim3(CC, 3), 256>>>(convQ_w, dil0_w, dil1_w, dil2_w);
    k_ln<<<dim3(HWW/256, BB, 2), 256>>>(x_l, x_r, ln1_w, ln1_b, ln2_w, ln2_b);
    k_qkv_mma<<<dim3(HWW/128, BB, 2), 288>>>(qkvl_b, qkvr_b);
    k_dw<<<dim3(HH/4, C3, 2*BB), 256>>>(dwl_w, dwl_b, dwr_w, dwr_b);
    k_dilated_mma<<<dim3(2*HH, BB), 256, SMD>>>();
    k_norms<<<3*BB*CC, 256>>>();
    k_dots<<<dim3(16, BB*NH, 2), 256>>>();
    k_soft_m<<<1, 256>>>(temperature, conv1_w, conv2_w);
    k_epilogue<<<dim3(HWW/256, BB, 2), 256>>>(x_l, x_r, conv1_b, conv2_b, (float*)d_out);
}

// round 8
// speedup vs baseline: 3.4503x; 1.1230x over previous
#include <cuda_runtime.h>
#include <cuda_bf16.h>
#include <cstdint>
#include <math.h>

#define BB   2
#define CC   48
#define HH   128
#define WW   256
#define HWW  (HH*WW)          // 32768
#define C3   144
#define C2   96
#define NH   3
#define CHD  16
#define BSTR 140              // qkv B row stride (u32); 140 % 32 == 12 -> conflict-free
#define ASTR 104              // A tile row stride (bf16)
#define DSTR 268              // dilated B row stride (u32); 268 % 32 == 12 -> conflict-free
#define DBUF (48*DSTR)        // u32 per dilated B buffer
#define VSTR 260              // epilogue V row stride (u32)

// ---------------- scratch (static device globals; no allocation) ----------------
__device__ __nv_bfloat16  g_pre_bf [2][BB][C3][HWW];   // bf16 qkv after LN+1x1
__device__ float          g_kv     [2][BB][CC][HWW];   // fp32 K after dw
__device__ uint32_t       g_vp     [2][BB][24][HWW];   // pair-packed bf16 V after dw
__device__ uint32_t       g_xp     [BB][CC][HWW];      // pair-packed bf16 [Q_l;Q_r]
__device__ uint32_t       g_xnp    [2][BB][24][HWW];   // pair-packed bf16 LN output
__device__ float          g_qfold  [BB][CC][HWW];      // fused dilated-conv + convQ output
__device__ __nv_bfloat16  g_wbf    [27][64][C2];       // folded bf16 weights (oc pad 64)
__device__ __nv_bfloat16  g_wq     [2][C3][CC];        // bf16 qkv weights
__device__ float          g_beff   [CC];
__device__ float          g_inv    [3][BB][CC];
__device__ float          g_dpart  [2*BB*NH*16*256];
__device__ __nv_bfloat16  g_Mbf    [2*BB][CC*CC];      // folded conv1/2 @ blockdiag(A), bf16

__device__ __forceinline__ uint32_t smem_u32(const void* p) {
    uint32_t a;
    asm("{ .reg .u64 t; cvta.to.shared.u64 t, %1; cvt.u32.u64 %0, t; }" : "=r"(a) : "l"(p));
    return a;
}
__device__ __forceinline__ void ldsm4(uint32_t* r, uint32_t addr) {
    asm volatile("ldmatrix.sync.aligned.m8n8.x4.shared.b16 {%0,%1,%2,%3}, [%4];"
        : "=r"(r[0]), "=r"(r[1]), "=r"(r[2]), "=r"(r[3]) : "r"(addr));
}
__device__ __forceinline__ void mma16816(float* c, const uint32_t* a, uint32_t b0, uint32_t b1) {
    asm volatile("mma.sync.aligned.m16n8k16.row.col.f32.bf16.bf16.f32 "
        "{%0,%1,%2,%3}, {%4,%5,%6,%7}, {%8,%9}, {%0,%1,%2,%3};"
        : "+f"(c[0]), "+f"(c[1]), "+f"(c[2]), "+f"(c[3])
        : "r"(a[0]), "r"(a[1]), "r"(a[2]), "r"(a[3]), "r"(b0), "r"(b1));
}
__device__ __forceinline__ void st_bf2(__nv_bfloat16* p, float a, float b) {
    uint32_t u = (uint32_t)__bfloat16_as_ushort(__float2bfloat16_rn(a))
               | ((uint32_t)__bfloat16_as_ushort(__float2bfloat16_rn(b)) << 16);
    *reinterpret_cast<uint32_t*>(p) = u;
}

// ---------------- merged prelude: prep_w + pad-zero + fold_b ----------------
__global__ void k_misc(const float* __restrict__ wl, const float* __restrict__ wr,
                       const float* __restrict__ cqw, const float* __restrict__ cqb,
                       const float* __restrict__ d0b, const float* __restrict__ d1b,
                       const float* __restrict__ d2b) {
    int blk = blockIdx.x, tid = threadIdx.x;
    if (blk < 54) {
        int i = blk*256 + tid;
        int s = i / (C3*CC), r = i - s*(C3*CC);
        reinterpret_cast<__nv_bfloat16*>(g_wq)[i] = __float2bfloat16_rn((s ? wr : wl)[r]);
    } else if (blk < 95) {
        int j = (blk - 54)*256 + tid;
        if (j < 27*384) {
            int tap = j / 384, r = j - tap*384;
            reinterpret_cast<uint32_t*>(g_wbf)[tap*3072 + 2304 + r] = 0u;
        }
    } else {
        __shared__ float racc[192];
        if (tid < 192) {
            int o = tid >> 2, q = tid & 3;
            float acc = 0.f;
            for (int j = q*72; j < q*72 + 72; ++j) {
                int dd = j / 96, jj = j - dd*96;
                const float* bp = (dd == 0) ? d0b : (dd == 1) ? d1b : d2b;
                acc += cqw[o*288 + j] * bp[jj];
            }
            racc[tid] = acc;
        }
        __syncthreads();
        if (tid < CC)
            g_beff[tid] = cqb[tid] + racc[tid*4] + racc[tid*4+1] + racc[tid*4+2] + racc[tid*4+3];
    }
}

// ---------------- weight folding ----------------
__global__ void k_fold_w(const float* __restrict__ qw, const float* __restrict__ d0,
                         const float* __restrict__ d1, const float* __restrict__ d2) {
    int o = blockIdx.x, d = blockIdx.y;
    const float* dw = (d == 0) ? d0 : (d == 1) ? d1 : d2;
    __shared__ float qr[C2];
    for (int j = threadIdx.x; j < C2; j += blockDim.x)
        qr[j] = qw[o*(3*C2) + d*C2 + j];
    __syncthreads();
    for (int ik = threadIdx.x; ik < C2*9; ik += blockDim.x) {
        float acc = 0.f;
        for (int j = 0; j < C2; ++j)
            acc += qr[j] * dw[j*(C2*9) + ik];
        int i = ik / 9, kk = ik - i*9;
        g_wbf[d*9 + kk][o][i] = __float2bfloat16_rn(acc);
    }
}

// ---------------- LayerNorm2d -> pair-packed bf16 ----------------
__global__ void k_ln(const float* __restrict__ xl, const float* __restrict__ xr,
                     const float* __restrict__ ln1w, const float* __restrict__ ln1b,
                     const float* __restrict__ ln2w, const float* __restrict__ ln2b) {
    int branch = blockIdx.z, b = blockIdx.y;
    int p = blockIdx.x*blockDim.x + threadIdx.x;
    const float* x  = (branch == 0 ? xl : xr) + b*CC*HWW;
    const float* lw = branch == 0 ? ln1w : ln2w;
    const float* lb = branch == 0 ? ln1b : ln2b;
    __shared__ float lws[CC], lbs[CC];
    for (int i = threadIdx.x; i < CC; i += blockDim.x) { lws[i] = lw[i]; lbs[i] = lb[i]; }
    __syncthreads();
    float y[CC]; float mu = 0.f;
    #pragma unroll
    for (int c = 0; c < CC; ++c) { y[c] = x[c*HWW + p]; mu += y[c]; }
    mu *= (1.f/CC);
    float var = 0.f;
    #pragma unroll
    for (int c = 0; c < CC; ++c) { float t = y[c] - mu; var += t*t; }
    float rstd = rsqrtf(var*(1.f/CC) + 1e-6f);
    uint32_t* out = &g_xnp[branch][b][0][p];
    #pragma unroll
    for (int kp = 0; kp < 24; ++kp) {
        float v0 = (y[2*kp]   - mu)*rstd*lws[2*kp]   + lbs[2*kp];
        float v1 = (y[2*kp+1] - mu)*rstd*lws[2*kp+1] + lbs[2*kp+1];
        uint32_t u = (uint32_t)__bfloat16_as_ushort(__float2bfloat16_rn(v0))
                   | ((uint32_t)__bfloat16_as_ushort(__float2bfloat16_rn(v1)) << 16);
        out[kp*HWW] = u;
    }
}

// ---------------- 1x1 qkv GEMM, two n-half passes (lower reg pressure) ----------------
__global__ void __launch_bounds__(288) k_qkv_mma(const float* __restrict__ bl,
                                                 const float* __restrict__ br) {
    __shared__ __align__(16) __nv_bfloat16 As[C3*CC];
    __shared__ uint32_t Bs[24*BSTR];
    __shared__ float bs[C3];
    int p0 = blockIdx.x*128, b = blockIdx.y, branch = blockIdx.z;
    int tid = threadIdx.x, lane = tid & 31, wid = tid >> 5;
    {
        const uint4* src = reinterpret_cast<const uint4*>(&g_wq[branch][0][0]);
        uint4* dst = reinterpret_cast<uint4*>(As);
        for (int i = tid; i < C3*CC/8; i += 288) dst[i] = src[i];
        const float* bp = branch ? br : bl;
        for (int i = tid; i < C3; i += 288) bs[i] = bp[i];
        const uint32_t* xsrc = &g_xnp[branch][b][0][0];
        for (int i = tid; i < 24*128; i += 288) {
            int kp = i >> 7, col = i & 127;
            Bs[kp*BSTR + col] = xsrc[kp*HWW + p0 + col];
        }
    }
    __syncthreads();
    uint32_t smbA = smem_u32(As);
    int r0 = lane >> 2, cb = (lane & 3)*2;
    int oc0 = wid*16 + r0, oc1 = oc0 + 8;
    float be0 = bs[oc0], be1 = bs[oc1];
    __nv_bfloat16* o0 = &g_pre_bf[branch][b][oc0][p0];
    __nv_bfloat16* o1 = &g_pre_bf[branch][b][oc1][p0];
    #pragma unroll
    for (int half = 0; half < 2; ++half) {
        float acc[4][2][4];
        #pragma unroll
        for (int np = 0; np < 4; ++np)
            #pragma unroll
            for (int f = 0; f < 2; ++f)
                #pragma unroll
                for (int q = 0; q < 4; ++q) acc[np][f][q] = 0.f;
        #pragma unroll
        for (int kb = 0; kb < 3; ++kb) {
            uint32_t a[4];
            int row = wid*16 + (lane & 15);
            ldsm4(a, smbA + (uint32_t)(row*CC + kb*16 + ((lane >> 4) << 3))*2u);
            const uint32_t* b_lo = Bs + (kb*8 + (lane & 3))*BSTR + (lane >> 2) + half*64;
            const uint32_t* b_hi = b_lo + 4*BSTR;
            #pragma unroll
            for (int np = 0; np < 4; ++np) {
                uint32_t b0 = b_lo[np*16], b1 = b_hi[np*16];
                uint32_t b2 = b_lo[np*16 + 8], b3 = b_hi[np*16 + 8];
                mma16816(acc[np][0], a, b0, b1);
                mma16816(acc[np][1], a, b2, b3);
            }
        }
        #pragma unroll
        for (int np = 0; np < 4; ++np)
            #pragma unroll
            for (int f = 0; f < 2; ++f) {
                int c = half*64 + np*16 + f*8 + cb;
                st_bf2(o0 + c, acc[np][f][0] + be0, acc[np][f][1] + be0);
                st_bf2(o1 + c, acc[np][f][2] + be1, acc[np][f][3] + be1);
            }
    }
}

// ---------------- depthwise 3x3 (bf16 in) -> K fp32 + Q,V pair-packed bf16 ----------------
__global__ void k_dw(const float* __restrict__ wl, const float* __restrict__ bl,
                     const float* __restrict__ wr, const float* __restrict__ brb) {
    int z = blockIdx.z; int branch = z >> 1, b = z & 1;
    int ch = blockIdx.y;
    int y0 = blockIdx.x * 4;
    __shared__ __align__(16) float rows[6][264];
    const __nv_bfloat16* in = &g_pre_bf[branch][b][ch][0];
    const float* w  = (branch == 0 ? wl : wr) + ch*9;
    float bias = (branch == 0 ? bl : brb)[ch];
    int tid = threadIdx.x;

    for (int idx = tid; idx < 6*64; idx += 256) {
        int r = idx >> 6, c4 = idx & 63;
        int gy = y0 - 1 + r;
        float4 f = make_float4(0.f, 0.f, 0.f, 0.f);
        if (gy >= 0 && gy < HH) {
            uint2 v = *reinterpret_cast<const uint2*>(&in[gy*WW + c4*4]);
            f.x = __bfloat162float(__ushort_as_bfloat16((unsigned short)(v.x & 0xFFFF)));
            f.y = __bfloat162float(__ushort_as_bfloat16((unsigned short)(v.x >> 16)));
            f.z = __bfloat162float(__ushort_as_bfloat16((unsigned short)(v.y & 0xFFFF)));
            f.w = __bfloat162float(__ushort_as_bfloat16((unsigned short)(v.y >> 16)));
        }
        *reinterpret_cast<float4*>(&rows[r][4 + 4*c4]) = f;
    }
    if (tid < 6) { rows[tid][3] = 0.f; rows[tid][260] = 0.f; }
    __syncthreads();

    int r  = tid >> 6;
    int x0 = (tid & 63) * 4;
    float a0 = bias, a1 = bias, a2 = bias, a3 = bias;
    #pragma unroll
    for (int ky = 0; ky < 3; ++ky) {
        const float* rp = &rows[r + ky][3 + x0];
        float v0 = rp[0];
        float4 vm = *reinterpret_cast<const float4*>(rp + 1);
        float v5 = rp[5];
        float w0 = w[ky*3], w1 = w[ky*3+1], w2 = w[ky*3+2];
        a0 += w0*v0   + w1*vm.x + w2*vm.y;
        a1 += w0*vm.x + w1*vm.y + w2*vm.z;
        a2 += w0*vm.y + w1*vm.z + w2*vm.w;
        a3 += w0*vm.z + w1*vm.w + w2*v5;
    }
    int px = (y0 + r)*WW + x0;
    if (ch < CC) {
        int g = branch*CC + ch;
        unsigned short* xp16 = reinterpret_cast<unsigned short*>(&g_xp[b][g >> 1][0]);
        int half = g & 1;
        xp16[(px  )*2 + half] = __bfloat16_as_ushort(__float2bfloat16_rn(a0));
        xp16[(px+1)*2 + half] = __bfloat16_as_ushort(__float2bfloat16_rn(a1));
        xp16[(px+2)*2 + half] = __bfloat16_as_ushort(__float2bfloat16_rn(a2));
        xp16[(px+3)*2 + half] = __bfloat16_as_ushort(__float2bfloat16_rn(a3));
    } else if (ch < 2*CC) {
        *reinterpret_cast<float4*>(&g_kv[branch][b][ch - CC][px]) = make_float4(a0, a1, a2, a3);
    } else {
        int v = ch - 2*CC;
        unsigned short* vp16 = reinterpret_cast<unsigned short*>(&g_vp[branch][b][v >> 1][0]);
        int half = v & 1;
        vp16[(px  )*2 + half] = __bfloat16_as_ushort(__float2bfloat16_rn(a0));
        vp16[(px+1)*2 + half] = __bfloat16_as_ushort(__float2bfloat16_rn(a1));
        vp16[(px+2)*2 + half] = __bfloat16_as_ushort(__float2bfloat16_rn(a2));
        vp16[(px+3)*2 + half] = __bfloat16_as_ushort(__float2bfloat16_rn(a3));
    }
}

// ---------------- fused dilated convs + convQ: full-row CTA, 8B cp.async ----------------
// Per CTA: (y, b), 256 px. 8 warps: mhalf = wid&1 (32 oc), nq = wid>>1 (64 px).
__global__ void __launch_bounds__(256) k_dilated_mma() {
    extern __shared__ __align__(16) uint32_t smx[];
    uint32_t* Bs = smx;                                                      // [2][48*268]
    __nv_bfloat16* As = reinterpret_cast<__nv_bfloat16*>(smx + 2*DBUF);      // [3][64][104]
    uint32_t smbB = smem_u32(Bs), smbA = smem_u32(As);
    int y = blockIdx.x, b = blockIdx.y;
    int tid = threadIdx.x, lane = tid & 31, wid = tid >> 5;
    int mhalf = wid & 1, nq = wid >> 1;
    const uint32_t* xp = &g_xp[b][0][0];

    float acc[2][4][2][4];
    #pragma unroll
    for (int mb = 0; mb < 2; ++mb)
        #pragma unroll
        for (int np = 0; np < 4; ++np)
            #pragma unroll
            for (int f = 0; f < 2; ++f)
                #pragma unroll
                for (int q = 0; q < 4; ++q) acc[mb][np][f][q] = 0.f;

    auto fill_row = [&](int buf, int gy) {
        bool rowok = (gy >= 0 && gy < HH);
        uint32_t dbase = smbB + (uint32_t)buf*DBUF*4u;
        int gys = rowok ? gy : 0;
        for (int i = tid; i < 48*134; i += 256) {
            int kp = i / 134, c2 = i - kp*134;
            int gx = c2*2 - 6;
            bool ok = rowok && gx >= 0 && gx < WW;
            const uint32_t* src = xp + kp*HWW + gys*WW + (ok ? gx : 0);
            uint32_t sz = ok ? 8u : 0u;
            asm volatile("cp.async.ca.shared.global [%0], [%1], 8, %2;"
                         :: "r"(dbase + (uint32_t)(kp*DSTR + c2*2)*4u), "l"(src), "r"(sz)
                         : "memory");
        }
        asm volatile("cp.async.commit_group;" ::: "memory");
    };

    const int roff[7] = {0, -2, -4, -6, 2, 4, 6};
    fill_row(0, y);
    for (int ri = 0; ri < 7; ++ri) {
        asm volatile("cp.async.wait_group 0;" ::: "memory");
        __syncthreads();
        if (ri < 6) fill_row((ri + 1) & 1, y + roff[ri + 1]);
        const uint32_t* bcur = Bs + (ri & 1)*DBUF;
        int ng = (ri == 0) ? 3 : 1;
        for (int gi = 0; gi < ng; ++gi) {
            int d  = (ri == 0) ? gi : (ri <= 3 ? ri - 1 : ri - 4);
            int ky = (ri == 0) ? 1  : (ri <= 3 ? 0 : 2);
            if (gi) __syncthreads();
            {   // A fill: 3 contiguous taps (kx 0..2)
                const uint4* src = reinterpret_cast<const uint4*>(&g_wbf[d*9 + ky*3][0][0]);
                for (int i = tid; i < 2304; i += 256) {
                    int tap = i / 768, r2 = i - tap*768;
                    int row = r2 / 12, cu = r2 - row*12;
                    *reinterpret_cast<uint4*>(&As[(tap*64 + row)*ASTR + cu*8]) = src[i];
                }
            }
            __syncthreads();
            int dil = 2*(d + 1);
            #pragma unroll
            for (int kx = 0; kx < 3; ++kx) {
                int coloff = 6 + (kx - 1)*dil + nq*64 + (lane >> 2);
                uint32_t ab = smbA + (uint32_t)(kx*64*ASTR)*2u;
                #pragma unroll
                for (int kb = 0; kb < 6; ++kb) {
                    uint32_t a[2][4];
                    #pragma unroll
                    for (int mb = 0; mb < 2; ++mb) {
                        int row = mhalf*32 + mb*16 + (lane & 15);
                        ldsm4(a[mb], ab + (uint32_t)(row*ASTR + kb*16 + ((lane >> 4) << 3))*2u);
                    }
                    const uint32_t* b_lo = bcur + (kb*8 + (lane & 3))*DSTR + coloff;
                    const uint32_t* b_hi = b_lo + 4*DSTR;
                    #pragma unroll
                    for (int np = 0; np < 4; ++np) {
                        uint32_t b0 = b_lo[np*16], b1 = b_hi[np*16];
                        uint32_t b2 = b_lo[np*16 + 8], b3 = b_hi[np*16 + 8];
                        #pragma unroll
                        for (int mb = 0; mb < 2; ++mb) {
                            mma16816(acc[mb][np][0], a[mb], b0, b1);
                            mma16816(acc[mb][np][1], a[mb], b2, b3);
                        }
                    }
                }
            }
        }
    }
    #pragma unroll
    for (int mb = 0; mb < 2; ++mb) {
        if (mhalf == 1 && mb == 1) continue;
        int oc = mhalf*32 + mb*16 + (lane >> 2);
        float be0 = g_beff[oc], be1 = g_beff[oc + 8];
        #pragma unroll
        for (int np = 0; np < 4; ++np)
            #pragma unroll
            for (int f = 0; f < 2; ++f) {
                int n = nq*64 + np*16 + f*8 + (lane & 3)*2;
                *reinterpret_cast<float2*>(&g_qfold[b][oc][y*WW + n]) =
                    make_float2(acc[mb][np][f][0] + be0, acc[mb][np][f][1] + be0);
                *reinterpret_cast<float2*>(&g_qfold[b][oc + 8][y*WW + n]) =
                    make_float2(acc[mb][np][f][2] + be1, acc[mb][np][f][3] + be1);
            }
    }
}

// ---------------- per-channel L2 norms over HW ----------------
__global__ void k_norms() {
    int gid = blockIdx.x;
    int t = gid / (BB*CC);
    int r = gid - t*(BB*CC);
    int b = r / CC, c = r - b*CC;
    const float* src;
    if (t == 0)      src = &g_qfold[b][c][0];
    else if (t == 1) src = &g_kv[0][b][c][0];
    else             src = &g_kv[1][b][c][0];
    float ss = 0.f;
    const float4* s4 = reinterpret_cast<const float4*>(src);
    for (int i = threadIdx.x; i < HWW/4; i += blockDim.x) {
        float4 v = s4[i];
        ss += v.x*v.x + v.y*v.y + v.z*v.z + v.w*v.w;
    }
    #pragma unroll
    for (int off = 16; off > 0; off >>= 1)
        ss += __shfl_down_sync(0xffffffffu, ss, off);
    __shared__ float red[8];
    if ((threadIdx.x & 31) == 0) red[threadIdx.x >> 5] = ss;
    __syncthreads();
    if (threadIdx.x == 0) {
        float tot = 0.f;
        for (int i = 0; i < (int)(blockDim.x >> 5); ++i) tot += red[i];
        g_inv[t][b][c] = 1.f / fmaxf(sqrtf(tot), 1e-12f);
    }
}

// ---------------- QK^T dot partials, 2x2 register-blocked ----------------
__global__ void k_dots() {
    int chunk = blockIdx.x;
    int bh    = blockIdx.y;
    int s     = blockIdx.z;
    int b = bh / NH, h = bh - b*NH;
    const float* Q = &g_qfold[b][h*CHD][0];
    const float* K = (s == 0) ? &g_kv[1][b][h*CHD][0] : &g_kv[0][b][h*CHD][0];
    __shared__ float Qs[16][257];
    __shared__ float Ks[16][257];
    __shared__ float red[4][64][4];
    int tid = threadIdx.x;
    int pos = tid & 63, seg = tid >> 6;
    int cq = pos >> 3, ck = pos & 7;
    float a00 = 0.f, a01 = 0.f, a10 = 0.f, a11 = 0.f;
    int p0 = chunk * 2048;
    for (int sub = 0; sub < 8; ++sub) {
        __syncthreads();
        int pb = p0 + sub*256;
        #pragma unroll
        for (int e = 0; e < 16; ++e) {
            Qs[e][tid] = Q[e*HWW + pb + tid];
            Ks[e][tid] = K[e*HWW + pb + tid];
        }
        __syncthreads();
        int i0 = seg*64;
        #pragma unroll 16
        for (int i = 0; i < 64; ++i) {
            float q0 = Qs[cq][i0 + i], q1 = Qs[cq + 8][i0 + i];
            float k0 = Ks[ck][i0 + i], k1 = Ks[ck + 8][i0 + i];
            a00 += q0*k0; a01 += q0*k1; a10 += q1*k0; a11 += q1*k1;
        }
    }
    red[seg][pos][0] = a00; red[seg][pos][1] = a01;
    red[seg][pos][2] = a10; red[seg][pos][3] = a11;
    __syncthreads();
    if (tid < 64) {
        float v[4];
        #pragma unroll
        for (int q = 0; q < 4; ++q)
            v[q] = red[0][tid][q] + red[1][tid][q] + red[2][tid][q] + red[3][tid][q];
        int base = (((s*BB + b)*NH + h)*16 + chunk)*256;
        int cq0 = tid >> 3, ck0 = tid & 7;
        g_dpart[base + (cq0    )*16 + ck0    ] = v[0];
        g_dpart[base + (cq0    )*16 + ck0 + 8] = v[1];
        g_dpart[base + (cq0 + 8)*16 + ck0    ] = v[2];
        g_dpart[base + (cq0 + 8)*16 + ck0 + 8] = v[3];
    }
}

// ---------------- softmax + fold conv1/2 into bf16 M ----------------
__global__ void k_soft_m(const float* __restrict__ temp,
                         const float* __restrict__ w1, const float* __restrict__ w2) {
    __shared__ float As2[192][16];
    int tid = threadIdx.x;
    if (tid < 192) {
        int s = tid / 96, rem = tid - s*96;
        int b = rem / 48, rem2 = rem - b*48;
        int h = rem2 / 16, cq = rem2 - h*16;
        float v[16];
        #pragma unroll
        for (int ck = 0; ck < 16; ++ck) v[ck] = 0.f;
        int base = (((s*BB + b)*NH + h)*16)*256 + cq*16;
        for (int chunk = 0; chunk < 16; ++chunk) {
            #pragma unroll
            for (int ck = 0; ck < 16; ++ck)
                v[ck] += g_dpart[base + chunk*256 + ck];
        }
        float iq = g_inv[0][b][h*16 + cq];
        float tm = temp[h];
        const float* ik = (s == 0) ? &g_inv[2][b][h*16] : &g_inv[1][b][h*16];
        float mx = -1e30f;
        #pragma unroll
        for (int ck = 0; ck < 16; ++ck) { v[ck] *= iq * ik[ck] * tm; mx = fmaxf(mx, v[ck]); }
        float sum = 0.f;
        #pragma unroll
        for (int ck = 0; ck < 16; ++ck) { v[ck] = expf(v[ck] - mx); sum += v[ck]; }
        float inv = 1.f / sum;
        #pragma unroll
        for (int ck = 0; ck < 16; ++ck) As2[tid][ck] = v[ck] * inv;
    }
    __syncthreads();
    for (int idx = tid; idx < 2*BB*CC*CC; idx += blockDim.x) {
        int s = idx / (BB*CC*CC), rem = idx - s*(BB*CC*CC);
        int b = rem / (CC*CC), rem2 = rem - b*(CC*CC);
        int o = rem2 / CC, dg = rem2 - o*CC;
        int h = dg / 16, dd = dg - h*16;
        const float* wv = ((s == 0) ? w1 : w2) + o*CC + h*16;
        int arow = s*96 + b*48 + h*16;
        float acc = 0.f;
        #pragma unroll
        for (int c = 0; c < 16; ++c)
            acc += wv[c] * As2[arow + c][dd];
        g_Mbf[s*BB + b][o*CC + dg] = __float2bfloat16_rn(acc);
    }
}

// ---------------- epilogue: out = x + M @ V + bias via mma.sync ----------------
__global__ void __launch_bounds__(256) k_epilogue(const float* __restrict__ xl,
                                                  const float* __restrict__ xr,
                                                  const float* __restrict__ b1,
                                                  const float* __restrict__ b2,
                                                  float* __restrict__ out) {
    __shared__ __align__(16) __nv_bfloat16 Ms[CC*CC];
    __shared__ uint32_t Vs[24*VSTR];
    __shared__ float bss[CC];
    int p0 = blockIdx.x*256, b = blockIdx.y, s = blockIdx.z;
    int tid = threadIdx.x, lane = tid & 31, nq = tid >> 5;
    {
        const uint4* src = reinterpret_cast<const uint4*>(&g_Mbf[s*BB + b][0]);
        uint4* dst = reinterpret_cast<uint4*>(Ms);
        for (int i = tid; i < CC*CC/8; i += 256) dst[i] = src[i];
        const uint32_t* vsrc = &g_vp[s][b][0][0];
        for (int i = tid; i < 24*256; i += 256) {
            int kp = i >> 8, col = i & 255;
            Vs[kp*VSTR + col] = vsrc[kp*HWW + p0 + col];
        }
        const float* bp = s ? b2 : b1;
        for (int i = tid; i < CC; i += 256) bss[i] = bp[i];
    }
    __syncthreads();
    float acc[3][2][2][4];
    #pragma unroll
    for (int mb = 0; mb < 3; ++mb)
        #pragma unroll
        for (int np = 0; np < 2; ++np)
            #pragma unroll
            for (int f = 0; f < 2; ++f)
                #pragma unroll
                for (int q = 0; q < 4; ++q) acc[mb][np][f][q] = 0.f;
    uint32_t smbA = smem_u32(Ms);
    #pragma unroll
    for (int kb = 0; kb < 3; ++kb) {
        uint32_t a[3][4];
        #pragma unroll
        for (int mb = 0; mb < 3; ++mb) {
            int row = mb*16 + (lane & 15);
            ldsm4(a[mb], smbA + (uint32_t)(row*CC + kb*16 + ((lane >> 4) << 3))*2u);
        }
        const uint32_t* b_lo = Vs + (kb*8 + (lane & 3))*VSTR + nq*32 + (lane >> 2);
        const uint32_t* b_hi = b_lo + 4*VSTR;
        #pragma unroll
        for (int np = 0; np < 2; ++np) {
            uint32_t b0 = b_lo[np*16], b1 = b_hi[np*16];
            uint32_t b2v = b_lo[np*16 + 8], b3 = b_hi[np*16 + 8];
            #pragma unroll
            for (int mb = 0; mb < 3; ++mb) {
                mma16816(acc[mb][np][0], a[mb], b0, b1);
                mma16816(acc[mb][np][1], a[mb], b2v, b3);
            }
        }
    }
    const float* x = (s == 0 ? xl : xr) + b*CC*HWW;
    float* o = out + (s*BB + b)*CC*HWW;
    #pragma unroll
    for (int mb = 0; mb < 3; ++mb) {
        int oc0 = mb*16 + (lane >> 2), oc1 = oc0 + 8;
        float be0 = bss[oc0], be1 = bss[oc1];
        #pragma unroll
        for (int np = 0; np < 2; ++np)
            #pragma unroll
            for (int f = 0; f < 2; ++f) {
                int px = p0 + nq*32 + np*16 + f*8 + (lane & 3)*2;
                float2 x0 = *reinterpret_cast<const float2*>(&x[oc0*HWW + px]);
                float2 x1 = *reinterpret_cast<const float2*>(&x[oc1*HWW + px]);
                *reinterpret_cast<float2*>(&o[oc0*HWW + px]) =
                    make_float2(x0.x + acc[mb][np][f][0] + be0, x0.y + acc[mb][np][f][1] + be0);
                *reinterpret_cast<float2*>(&o[oc1*HWW + px]) =
                    make_float2(x1.x + acc[mb][np][f][2] + be1, x1.y + acc[mb][np][f][3] + be1);
            }
    }
}

// ---------------- launch ----------------
extern "C" void kernel_launch(void* const* d_in, const int* in_sizes, int n_in,
                              void* d_out, int out_size) {
    const float* x_l    = (const float*)d_in[0];
    const float* x_r    = (const float*)d_in[1];
    const float* ln1_w  = (const float*)d_in[2];
    const float* ln1_b  = (const float*)d_in[3];
    const float* ln2_w  = (const float*)d_in[4];
    const float* ln2_b  = (const float*)d_in[5];
    const float* qkvl_w = (const float*)d_in[6];
    const float* qkvl_b = (const float*)d_in[7];
    const float* qkvr_w = (const float*)d_in[8];
    const float* qkvr_b = (const float*)d_in[9];
    const float* dwl_w  = (const float*)d_in[10];
    const float* dwl_b  = (const float*)d_in[11];
    const float* dwr_w  = (const float*)d_in[12];
    const float* dwr_b  = (const float*)d_in[13];
    const float* dil0_w = (const float*)d_in[14];
    const float* dil0_b = (const float*)d_in[15];
    const float* dil1_w = (const float*)d_in[16];
    const float* dil1_b = (const float*)d_in[17];
    const float* dil2_w = (const float*)d_in[18];
    const float* dil2_b = (const float*)d_in[19];
    const float* convQ_w = (const float*)d_in[20];
    const float* convQ_b = (const float*)d_in[21];
    const float* conv1_w = (const float*)d_in[22];
    const float* conv1_b = (const float*)d_in[23];
    const float* conv2_w = (const float*)d_in[24];
    const float* conv2_b = (const float*)d_in[25];
    const float* temperature = (const float*)d_in[26];

    const int SMD = (2*DBUF)*4 + 3*64*ASTR*2;   // 102912 + 39936 = 142848
    cudaFuncSetAttribute(k_dilated_mma, cudaFuncAttributeMaxDynamicSharedMemorySize, SMD);

    k_misc<<<96, 256>>>(qkvl_w, qkvr_w, convQ_w, convQ_b, dil0_b, dil1_b, dil2_b);
    k_fold_w<<<dim3(CC, 3), 256>>>(convQ_w, dil0_w, dil1_w, dil2_w);
    k_ln<<<dim3(HWW/256, BB, 2), 256>>>(x_l, x_r, ln1_w, ln1_b, ln2_w, ln2_b);
    k_qkv_mma<<<dim3(HWW/128, BB, 2), 288>>>(qkvl_b, qkvr_b);
    k_dw<<<dim3(HH/4, C3, 2*BB), 256>>>(dwl_w, dwl_b, dwr_w, dwr_b);
    k_dilated_mma<<<dim3(HH, BB), 256, SMD>>>();
    k_norms<<<3*BB*CC, 256>>>();
    k_dots<<<dim3(16, BB*NH, 2), 256>>>();
    k_soft_m<<<1, 256>>>(temperature, conv1_w, conv2_w);
    k_epilogue<<<dim3(HWW/256, BB, 2), 256>>>(x_l, x_r, conv1_b, conv2_b, (float*)d_out);
}

// round 9
// speedup vs baseline: 3.5112x; 1.0176x over previous
#include <cuda_runtime.h>
#include <cuda_bf16.h>
#include <cstdint>
#include <math.h>

#define BB   2
#define CC   48
#define HH   128
#define WW   256
#define HWW  (HH*WW)          // 32768
#define C3   144
#define C2   96
#define NH   3
#define CHD  16
#define BSTR 140              // qkv B row stride (u32)
#define ASTR 104              // A tile row stride (bf16)
#define DSTR 268              // dilated B row stride (u32); 268 % 32 == 12 -> conflict-free
#define DBUF (48*DSTR)        // u32 per dilated B buffer
#define VSTR 260              // epilogue V row stride (u32)

// ---------------- scratch (static device globals; no allocation) ----------------
__device__ __nv_bfloat16  g_pre_bf [2][BB][C3][HWW];   // bf16 qkv after LN+1x1
__device__ float          g_kv     [2][BB][CC][HWW];   // fp32 K after dw
__device__ uint32_t       g_vp     [2][BB][24][HWW];   // pair-packed bf16 V after dw
__device__ uint32_t       g_xp     [BB][CC][HWW];      // pair-packed bf16 [Q_l;Q_r]
__device__ float          g_qfold  [BB][CC][HWW];      // fused dilated-conv + convQ output
__device__ __nv_bfloat16  g_wbf    [27][64][C2];       // folded bf16 weights (rows 48..63 unused)
__device__ __nv_bfloat16  g_wq     [2][C3][CC];        // bf16 qkv weights
__device__ float          g_beff   [CC];
__device__ float          g_inv    [3][BB][CC];
__device__ float          g_dpart  [2*BB*NH*16*256];
__device__ __nv_bfloat16  g_Mbf    [2*BB][CC*CC];      // folded conv1/2 @ blockdiag(A), bf16

__device__ __forceinline__ uint32_t smem_u32(const void* p) {
    uint32_t a;
    asm("{ .reg .u64 t; cvta.to.shared.u64 t, %1; cvt.u32.u64 %0, t; }" : "=r"(a) : "l"(p));
    return a;
}
__device__ __forceinline__ void ldsm4(uint32_t* r, uint32_t addr) {
    asm volatile("ldmatrix.sync.aligned.m8n8.x4.shared.b16 {%0,%1,%2,%3}, [%4];"
        : "=r"(r[0]), "=r"(r[1]), "=r"(r[2]), "=r"(r[3]) : "r"(addr));
}
__device__ __forceinline__ void mma16816(float* c, const uint32_t* a, uint32_t b0, uint32_t b1) {
    asm volatile("mma.sync.aligned.m16n8k16.row.col.f32.bf16.bf16.f32 "
        "{%0,%1,%2,%3}, {%4,%5,%6,%7}, {%8,%9}, {%0,%1,%2,%3};"
        : "+f"(c[0]), "+f"(c[1]), "+f"(c[2]), "+f"(c[3])
        : "r"(a[0]), "r"(a[1]), "r"(a[2]), "r"(a[3]), "r"(b0), "r"(b1));
}
__device__ __forceinline__ uint32_t pack_bf2(float a, float b) {
    return (uint32_t)__bfloat16_as_ushort(__float2bfloat16_rn(a))
         | ((uint32_t)__bfloat16_as_ushort(__float2bfloat16_rn(b)) << 16);
}
__device__ __forceinline__ void st_bf2(__nv_bfloat16* p, float a, float b) {
    *reinterpret_cast<uint32_t*>(p) = pack_bf2(a, b);
}

// ---------------- merged prelude: prep_w + fold_w + fold_b ----------------
__global__ void k_misc(const float* __restrict__ wl, const float* __restrict__ wr,
                       const float* __restrict__ cqw, const float* __restrict__ cqb,
                       const float* __restrict__ d0w, const float* __restrict__ d1w,
                       const float* __restrict__ d2w,
                       const float* __restrict__ d0b, const float* __restrict__ d1b,
                       const float* __restrict__ d2b) {
    int blk = blockIdx.x, tid = threadIdx.x;
    if (blk < 54) {                               // qkv weights -> bf16
        int i = blk*256 + tid;
        int s = i / (C3*CC), r = i - s*(C3*CC);
        reinterpret_cast<__nv_bfloat16*>(g_wq)[i] = __float2bfloat16_rn((s ? wr : wl)[r]);
    } else if (blk < 198) {                       // fold_w: 144 blocks (o, d)
        int idx = blk - 54;
        int o = idx % CC, d = idx / CC;
        const float* dw = (d == 0) ? d0w : (d == 1) ? d1w : d2w;
        __shared__ float qr[C2];
        for (int j = tid; j < C2; j += 256)
            qr[j] = cqw[o*(3*C2) + d*C2 + j];
        __syncthreads();
        for (int ik = tid; ik < C2*9; ik += 256) {
            float acc = 0.f;
            for (int j = 0; j < C2; ++j)
                acc += qr[j] * dw[j*(C2*9) + ik];
            int i = ik / 9, kk = ik - i*9;
            g_wbf[d*9 + kk][o][i] = __float2bfloat16_rn(acc);
        }
    } else {                                      // fold_b
        __shared__ float racc[192];
        if (tid < 192) {
            int o = tid >> 2, q = tid & 3;
            float acc = 0.f;
            for (int j = q*72; j < q*72 + 72; ++j) {
                int dd = j / 96, jj = j - dd*96;
                const float* bp = (dd == 0) ? d0b : (dd == 1) ? d1b : d2b;
                acc += cqw[o*288 + j] * bp[jj];
            }
            racc[tid] = acc;
        }
        __syncthreads();
        if (tid < CC)
            g_beff[tid] = cqb[tid] + racc[tid*4] + racc[tid*4+1] + racc[tid*4+2] + racc[tid*4+3];
    }
}

// ---------------- fused LayerNorm2d + 1x1 qkv GEMM ----------------
// dyn smem: xs f32[48*132] | Bs u32[24*140] | As bf16[C3*CC] | bs f32[C3]
#define LQ_XS   0
#define LQ_BS   (48*132*4)
#define LQ_AS   (LQ_BS + 24*BSTR*4)
#define LQ_BIAS (LQ_AS + C3*CC*2)
#define LQ_SM   (LQ_BIAS + C3*4)

__global__ void __launch_bounds__(288) k_lnqkv(const float* __restrict__ xl,
                                               const float* __restrict__ xr,
                                               const float* __restrict__ ln1w, const float* __restrict__ ln1b,
                                               const float* __restrict__ ln2w, const float* __restrict__ ln2b,
                                               const float* __restrict__ bl, const float* __restrict__ br) {
    extern __shared__ __align__(16) char smraw[];
    float*    xs = reinterpret_cast<float*>(smraw + LQ_XS);
    uint32_t* Bs = reinterpret_cast<uint32_t*>(smraw + LQ_BS);
    __nv_bfloat16* As = reinterpret_cast<__nv_bfloat16*>(smraw + LQ_AS);
    float*    bs = reinterpret_cast<float*>(smraw + LQ_BIAS);
    int p0 = blockIdx.x*128, b = blockIdx.y, branch = blockIdx.z;
    int tid = threadIdx.x, lane = tid & 31, wid = tid >> 5;
    const float* x = (branch == 0 ? xl : xr) + b*CC*HWW;
    {
        const uint4* src = reinterpret_cast<const uint4*>(&g_wq[branch][0][0]);
        uint4* dst = reinterpret_cast<uint4*>(As);
        for (int i = tid; i < C3*CC/8; i += 288) dst[i] = src[i];
        const float* bp = branch ? br : bl;
        for (int i = tid; i < C3; i += 288) bs[i] = bp[i];
        for (int i = tid; i < CC*128; i += 288) {
            int c = i >> 7, p = i & 127;
            xs[c*132 + p] = x[c*HWW + p0 + p];
        }
    }
    __syncthreads();
    if (tid < 128) {
        const float* lw = branch == 0 ? ln1w : ln2w;
        const float* lb = branch == 0 ? ln1b : ln2b;
        float mu = 0.f;
        #pragma unroll
        for (int c = 0; c < CC; ++c) mu += xs[c*132 + tid];
        mu *= (1.f/CC);
        float var = 0.f;
        #pragma unroll
        for (int c = 0; c < CC; ++c) { float t = xs[c*132 + tid] - mu; var += t*t; }
        float rstd = rsqrtf(var*(1.f/CC) + 1e-6f);
        #pragma unroll
        for (int kp = 0; kp < 24; ++kp) {
            float v0 = (xs[(2*kp  )*132 + tid] - mu)*rstd*lw[2*kp  ] + lb[2*kp  ];
            float v1 = (xs[(2*kp+1)*132 + tid] - mu)*rstd*lw[2*kp+1] + lb[2*kp+1];
            Bs[kp*BSTR + tid] = pack_bf2(v0, v1);
        }
    }
    __syncthreads();
    uint32_t smbA = smem_u32(As);
    int r0 = lane >> 2, cb = (lane & 3)*2;
    int oc0 = wid*16 + r0, oc1 = oc0 + 8;
    float be0 = bs[oc0], be1 = bs[oc1];
    __nv_bfloat16* o0 = &g_pre_bf[branch][b][oc0][p0];
    __nv_bfloat16* o1 = &g_pre_bf[branch][b][oc1][p0];
    #pragma unroll
    for (int half = 0; half < 2; ++half) {
        float acc[4][2][4];
        #pragma unroll
        for (int np = 0; np < 4; ++np)
            #pragma unroll
            for (int f = 0; f < 2; ++f)
                #pragma unroll
                for (int q = 0; q < 4; ++q) acc[np][f][q] = 0.f;
        #pragma unroll
        for (int kb = 0; kb < 3; ++kb) {
            uint32_t a[4];
            int row = wid*16 + (lane & 15);
            ldsm4(a, smbA + (uint32_t)(row*CC + kb*16 + ((lane >> 4) << 3))*2u);
            const uint32_t* b_lo = Bs + (kb*8 + (lane & 3))*BSTR + (lane >> 2) + half*64;
            const uint32_t* b_hi = b_lo + 4*BSTR;
            #pragma unroll
            for (int np = 0; np < 4; ++np) {
                uint32_t b0 = b_lo[np*16], b1 = b_hi[np*16];
                uint32_t b2 = b_lo[np*16 + 8], b3 = b_hi[np*16 + 8];
                mma16816(acc[np][0], a, b0, b1);
                mma16816(acc[np][1], a, b2, b3);
            }
        }
        #pragma unroll
        for (int np = 0; np < 4; ++np)
            #pragma unroll
            for (int f = 0; f < 2; ++f) {
                int c = half*64 + np*16 + f*8 + cb;
                st_bf2(o0 + c, acc[np][f][0] + be0, acc[np][f][1] + be0);
                st_bf2(o1 + c, acc[np][f][2] + be1, acc[np][f][3] + be1);
            }
    }
}

// ---------------- depthwise 3x3, channel-pair blocks -> packed stores ----------------
__global__ void k_dw(const float* __restrict__ wl, const float* __restrict__ bl,
                     const float* __restrict__ wr, const float* __restrict__ brb) {
    int z = blockIdx.z; int branch = z >> 1, b = z & 1;
    int chp = blockIdx.y;                  // 0..71 (channel pair)
    int c0 = 2*chp;
    int y0 = blockIdx.x * 4;
    __shared__ __align__(16) float rows[2][6][264];
    const float* wbase = (branch == 0 ? wl : wr);
    const float* bbase = (branch == 0 ? bl : brb);
    int tid = threadIdx.x;

    for (int idx = tid; idx < 2*6*64; idx += 256) {
        int cc = idx / 384, rem = idx - cc*384;
        int r = rem >> 6, c4 = rem & 63;
        int gy = y0 - 1 + r;
        float4 f = make_float4(0.f, 0.f, 0.f, 0.f);
        if (gy >= 0 && gy < HH) {
            const __nv_bfloat16* in = &g_pre_bf[branch][b][c0 + cc][0];
            uint2 v = *reinterpret_cast<const uint2*>(&in[gy*WW + c4*4]);
            f.x = __bfloat162float(__ushort_as_bfloat16((unsigned short)(v.x & 0xFFFF)));
            f.y = __bfloat162float(__ushort_as_bfloat16((unsigned short)(v.x >> 16)));
            f.z = __bfloat162float(__ushort_as_bfloat16((unsigned short)(v.y & 0xFFFF)));
            f.w = __bfloat162float(__ushort_as_bfloat16((unsigned short)(v.y >> 16)));
        }
        *reinterpret_cast<float4*>(&rows[cc][r][4 + 4*c4]) = f;
    }
    if (tid < 12) { int cc = tid / 6, r = tid % 6; rows[cc][r][3] = 0.f; rows[cc][r][260] = 0.f; }
    __syncthreads();

    int r  = tid >> 6;
    int x0 = (tid & 63) * 4;
    float out[2][4];
    #pragma unroll
    for (int cc = 0; cc < 2; ++cc) {
        const float* w = wbase + (c0 + cc)*9;
        float bias = bbase[c0 + cc];
        float a0 = bias, a1 = bias, a2 = bias, a3 = bias;
        #pragma unroll
        for (int ky = 0; ky < 3; ++ky) {
            const float* rp = &rows[cc][r + ky][3 + x0];
            float v0 = rp[0];
            float4 vm = *reinterpret_cast<const float4*>(rp + 1);
            float v5 = rp[5];
            float w0 = w[ky*3], w1 = w[ky*3+1], w2 = w[ky*3+2];
            a0 += w0*v0   + w1*vm.x + w2*vm.y;
            a1 += w0*vm.x + w1*vm.y + w2*vm.z;
            a2 += w0*vm.y + w1*vm.z + w2*vm.w;
            a3 += w0*vm.z + w1*vm.w + w2*v5;
        }
        out[cc][0] = a0; out[cc][1] = a1; out[cc][2] = a2; out[cc][3] = a3;
    }
    int px = (y0 + r)*WW + x0;
    if (chp < 24) {              // Q pair -> g_xp
        uint4 u;
        u.x = pack_bf2(out[0][0], out[1][0]); u.y = pack_bf2(out[0][1], out[1][1]);
        u.z = pack_bf2(out[0][2], out[1][2]); u.w = pack_bf2(out[0][3], out[1][3]);
        *reinterpret_cast<uint4*>(&g_xp[b][branch*24 + chp][px]) = u;
    } else if (chp < 48) {       // K fp32
        int kc = c0 - CC;
        *reinterpret_cast<float4*>(&g_kv[branch][b][kc][px]) =
            make_float4(out[0][0], out[0][1], out[0][2], out[0][3]);
        *reinterpret_cast<float4*>(&g_kv[branch][b][kc + 1][px]) =
            make_float4(out[1][0], out[1][1], out[1][2], out[1][3]);
    } else {                     // V pair -> g_vp
        uint4 u;
        u.x = pack_bf2(out[0][0], out[1][0]); u.y = pack_bf2(out[0][1], out[1][1]);
        u.z = pack_bf2(out[0][2], out[1][2]); u.w = pack_bf2(out[0][3], out[1][3]);
        *reinterpret_cast<uint4*>(&g_vp[branch][b][chp - 48][px]) = u;
    }
}

// ---------------- fused dilated convs + convQ: full-row CTA, warp=32px x 48oc ----------------
__global__ void __launch_bounds__(256) k_dilated_mma() {
    extern __shared__ __align__(16) uint32_t smx[];
    uint32_t* Bs = smx;                                                      // [2][48*268]
    __nv_bfloat16* As = reinterpret_cast<__nv_bfloat16*>(smx + 2*DBUF);      // [3][64][104] (48 rows used)
    uint32_t smbB = smem_u32(Bs), smbA = smem_u32(As);
    int y = blockIdx.x, b = blockIdx.y;
    int tid = threadIdx.x, lane = tid & 31, nq = tid >> 5;
    const uint32_t* xp = &g_xp[b][0][0];

    float acc[3][2][2][4];
    #pragma unroll
    for (int mb = 0; mb < 3; ++mb)
        #pragma unroll
        for (int np = 0; np < 2; ++np)
            #pragma unroll
            for (int f = 0; f < 2; ++f)
                #pragma unroll
                for (int q = 0; q < 4; ++q) acc[mb][np][f][q] = 0.f;

    auto fill_row = [&](int buf, int gy) {
        bool rowok = (gy >= 0 && gy < HH);
        uint32_t dbase = smbB + (uint32_t)buf*DBUF*4u;
        int gys = rowok ? gy : 0;
        for (int i = tid; i < 48*134; i += 256) {
            int kp = i / 134, c2 = i - kp*134;
            int gx = c2*2 - 6;
            bool ok = rowok && gx >= 0 && gx < WW;
            const uint32_t* src = xp + kp*HWW + gys*WW + (ok ? gx : 0);
            uint32_t sz = ok ? 8u : 0u;
            asm volatile("cp.async.ca.shared.global [%0], [%1], 8, %2;"
                         :: "r"(dbase + (uint32_t)(kp*DSTR + c2*2)*4u), "l"(src), "r"(sz)
                         : "memory");
        }
        asm volatile("cp.async.commit_group;" ::: "memory");
    };

    const int roff[7] = {0, -2, -4, -6, 2, 4, 6};
    fill_row(0, y);
    for (int ri = 0; ri < 7; ++ri) {
        asm volatile("cp.async.wait_group 0;" ::: "memory");
        __syncthreads();
        if (ri < 6) fill_row((ri + 1) & 1, y + roff[ri + 1]);
        const uint32_t* bcur = Bs + (ri & 1)*DBUF;
        int ng = (ri == 0) ? 3 : 1;
        for (int gi = 0; gi < ng; ++gi) {
            int d  = (ri == 0) ? gi : (ri <= 3 ? ri - 1 : ri - 4);
            int ky = (ri == 0) ? 1  : (ri <= 3 ? 0 : 2);
            if (gi) __syncthreads();
            {   // A fill: 3 taps x 48 rows x 96 K (uint4 = 8 bf16)
                const uint4* src = reinterpret_cast<const uint4*>(&g_wbf[d*9 + ky*3][0][0]);
                for (int i = tid; i < 1728; i += 256) {
                    int tap = i / 576, r2 = i - tap*576;
                    int row = r2 / 12, cu = r2 - row*12;
                    *reinterpret_cast<uint4*>(&As[(tap*64 + row)*ASTR + cu*8]) =
                        src[tap*768 + row*12 + cu];
                }
            }
            __syncthreads();
            int dil = 2*(d + 1);
            #pragma unroll
            for (int kx = 0; kx < 3; ++kx) {
                int coloff = 6 + (kx - 1)*dil + nq*32 + (lane >> 2);
                uint32_t ab = smbA + (uint32_t)(kx*64*ASTR)*2u;
                #pragma unroll
                for (int kb = 0; kb < 6; ++kb) {
                    uint32_t a[3][4];
                    #pragma unroll
                    for (int mb = 0; mb < 3; ++mb) {
                        int row = mb*16 + (lane & 15);
                        ldsm4(a[mb], ab + (uint32_t)(row*ASTR + kb*16 + ((lane >> 4) << 3))*2u);
                    }
                    const uint32_t* b_lo = bcur + (kb*8 + (lane & 3))*DSTR + coloff;
                    const uint32_t* b_hi = b_lo + 4*DSTR;
                    #pragma unroll
                    for (int np = 0; np < 2; ++np) {
                        uint32_t b0 = b_lo[np*16], b1 = b_hi[np*16];
                        uint32_t b2 = b_lo[np*16 + 8], b3 = b_hi[np*16 + 8];
                        #pragma unroll
                        for (int mb = 0; mb < 3; ++mb) {
                            mma16816(acc[mb][np][0], a[mb], b0, b1);
                            mma16816(acc[mb][np][1], a[mb], b2, b3);
                        }
                    }
                }
            }
        }
    }
    #pragma unroll
    for (int mb = 0; mb < 3; ++mb) {
        int oc = mb*16 + (lane >> 2);
        float be0 = g_beff[oc], be1 = g_beff[oc + 8];
        #pragma unroll
        for (int np = 0; np < 2; ++np)
            #pragma unroll
            for (int f = 0; f < 2; ++f) {
                int n = nq*32 + np*16 + f*8 + (lane & 3)*2;
                *reinterpret_cast<float2*>(&g_qfold[b][oc][y*WW + n]) =
                    make_float2(acc[mb][np][f][0] + be0, acc[mb][np][f][1] + be0);
                *reinterpret_cast<float2*>(&g_qfold[b][oc + 8][y*WW + n]) =
                    make_float2(acc[mb][np][f][2] + be1, acc[mb][np][f][3] + be1);
            }
    }
}

// ---------------- per-channel L2 norms over HW ----------------
__global__ void k_norms() {
    int gid = blockIdx.x;
    int t = gid / (BB*CC);
    int r = gid - t*(BB*CC);
    int b = r / CC, c = r - b*CC;
    const float* src;
    if (t == 0)      src = &g_qfold[b][c][0];
    else if (t == 1) src = &g_kv[0][b][c][0];
    else             src = &g_kv[1][b][c][0];
    float ss = 0.f;
    const float4* s4 = reinterpret_cast<const float4*>(src);
    for (int i = threadIdx.x; i < HWW/4; i += blockDim.x) {
        float4 v = s4[i];
        ss += v.x*v.x + v.y*v.y + v.z*v.z + v.w*v.w;
    }
    #pragma unroll
    for (int off = 16; off > 0; off >>= 1)
        ss += __shfl_down_sync(0xffffffffu, ss, off);
    __shared__ float red[8];
    if ((threadIdx.x & 31) == 0) red[threadIdx.x >> 5] = ss;
    __syncthreads();
    if (threadIdx.x == 0) {
        float tot = 0.f;
        for (int i = 0; i < (int)(blockDim.x >> 5); ++i) tot += red[i];
        g_inv[t][b][c] = 1.f / fmaxf(sqrtf(tot), 1e-12f);
    }
}

// ---------------- QK^T dot partials, 2x2 register-blocked ----------------
__global__ void k_dots() {
    int chunk = blockIdx.x;
    int bh    = blockIdx.y;
    int s     = blockIdx.z;
    int b = bh / NH, h = bh - b*NH;
    const float* Q = &g_qfold[b][h*CHD][0];
    const float* K = (s == 0) ? &g_kv[1][b][h*CHD][0] : &g_kv[0][b][h*CHD][0];
    __shared__ float Qs[16][257];
    __shared__ float Ks[16][257];
    __shared__ float red[4][64][4];
    int tid = threadIdx.x;
    int pos = tid & 63, seg = tid >> 6;
    int cq = pos >> 3, ck = pos & 7;
    float a00 = 0.f, a01 = 0.f, a10 = 0.f, a11 = 0.f;
    int p0 = chunk * 2048;
    for (int sub = 0; sub < 8; ++sub) {
        __syncthreads();
        int pb = p0 + sub*256;
        #pragma unroll
        for (int e = 0; e < 16; ++e) {
            Qs[e][tid] = Q[e*HWW + pb + tid];
            Ks[e][tid] = K[e*HWW + pb + tid];
        }
        __syncthreads();
        int i0 = seg*64;
        #pragma unroll 16
        for (int i = 0; i < 64; ++i) {
            float q0 = Qs[cq][i0 + i], q1 = Qs[cq + 8][i0 + i];
            float k0 = Ks[ck][i0 + i], k1 = Ks[ck + 8][i0 + i];
            a00 += q0*k0; a01 += q0*k1; a10 += q1*k0; a11 += q1*k1;
        }
    }
    red[seg][pos][0] = a00; red[seg][pos][1] = a01;
    red[seg][pos][2] = a10; red[seg][pos][3] = a11;
    __syncthreads();
    if (tid < 64) {
        float v[4];
        #pragma unroll
        for (int q = 0; q < 4; ++q)
            v[q] = red[0][tid][q] + red[1][tid][q] + red[2][tid][q] + red[3][tid][q];
        int base = (((s*BB + b)*NH + h)*16 + chunk)*256;
        int cq0 = tid >> 3, ck0 = tid & 7;
        g_dpart[base + (cq0    )*16 + ck0    ] = v[0];
        g_dpart[base + (cq0    )*16 + ck0 + 8] = v[1];
        g_dpart[base + (cq0 + 8)*16 + ck0    ] = v[2];
        g_dpart[base + (cq0 + 8)*16 + ck0 + 8] = v[3];
    }
}

// ---------------- softmax + fold conv1/2 into bf16 M ----------------
__global__ void k_soft_m(const float* __restrict__ temp,
                         const float* __restrict__ w1, const float* __restrict__ w2) {
    __shared__ float As2[192][16];
    int tid = threadIdx.x;
    if (tid < 192) {
        int s = tid / 96, rem = tid - s*96;
        int b = rem / 48, rem2 = rem - b*48;
        int h = rem2 / 16, cq = rem2 - h*16;
        float v[16];
        #pragma unroll
        for (int ck = 0; ck < 16; ++ck) v[ck] = 0.f;
        int base = (((s*BB + b)*NH + h)*16)*256 + cq*16;
        for (int chunk = 0; chunk < 16; ++chunk) {
            #pragma unroll
            for (int ck = 0; ck < 16; ++ck)
                v[ck] += g_dpart[base + chunk*256 + ck];
        }
        float iq = g_inv[0][b][h*16 + cq];
        float tm = temp[h];
        const float* ik = (s == 0) ? &g_inv[2][b][h*16] : &g_inv[1][b][h*16];
        float mx = -1e30f;
        #pragma unroll
        for (int ck = 0; ck < 16; ++ck) { v[ck] *= iq * ik[ck] * tm; mx = fmaxf(mx, v[ck]); }
        float sum = 0.f;
        #pragma unroll
        for (int ck = 0; ck < 16; ++ck) { v[ck] = expf(v[ck] - mx); sum += v[ck]; }
        float inv = 1.f / sum;
        #pragma unroll
        for (int ck = 0; ck < 16; ++ck) As2[tid][ck] = v[ck] * inv;
    }
    __syncthreads();
    for (int idx = tid; idx < 2*BB*CC*CC; idx += blockDim.x) {
        int s = idx / (BB*CC*CC), rem = idx - s*(BB*CC*CC);
        int b = rem / (CC*CC), rem2 = rem - b*(CC*CC);
        int o = rem2 / CC, dg = rem2 - o*CC;
        int h = dg / 16, dd = dg - h*16;
        const float* wv = ((s == 0) ? w1 : w2) + o*CC + h*16;
        int arow = s*96 + b*48 + h*16;
        float acc = 0.f;
        #pragma unroll
        for (int c = 0; c < 16; ++c)
            acc += wv[c] * As2[arow + c][dd];
        g_Mbf[s*BB + b][o*CC + dg] = __float2bfloat16_rn(acc);
    }
}

// ---------------- epilogue: out = x + M @ V + bias via mma.sync ----------------
__global__ void __launch_bounds__(256) k_epilogue(const float* __restrict__ xl,
                                                  const float* __restrict__ xr,
                                                  const float* __restrict__ b1,
                                                  const float* __restrict__ b2,
                                                  float* __restrict__ out) {
    __shared__ __align__(16) __nv_bfloat16 Ms[CC*CC];
    __shared__ uint32_t Vs[24*VSTR];
    __shared__ float bss[CC];
    int p0 = blockIdx.x*256, b = blockIdx.y, s = blockIdx.z;
    int tid = threadIdx.x, lane = tid & 31, nq = tid >> 5;
    {
        const uint4* src = reinterpret_cast<const uint4*>(&g_Mbf[s*BB + b][0]);
        uint4* dst = reinterpret_cast<uint4*>(Ms);
        for (int i = tid; i < CC*CC/8; i += 256) dst[i] = src[i];
        const uint32_t* vsrc = &g_vp[s][b][0][0];
        for (int i = tid; i < 24*256; i += 256) {
            int kp = i >> 8, col = i & 255;
            Vs[kp*VSTR + col] = vsrc[kp*HWW + p0 + col];
        }
        const float* bp = s ? b2 : b1;
        for (int i = tid; i < CC; i += 256) bss[i] = bp[i];
    }
    __syncthreads();
    float acc[3][2][2][4];
    #pragma unroll
    for (int mb = 0; mb < 3; ++mb)
        #pragma unroll
        for (int np = 0; np < 2; ++np)
            #pragma unroll
            for (int f = 0; f < 2; ++f)
                #pragma unroll
                for (int q = 0; q < 4; ++q) acc[mb][np][f][q] = 0.f;
    uint32_t smbA = smem_u32(Ms);
    #pragma unroll
    for (int kb = 0; kb < 3; ++kb) {
        uint32_t a[3][4];
        #pragma unroll
        for (int mb = 0; mb < 3; ++mb) {
            int row = mb*16 + (lane & 15);
            ldsm4(a[mb], smbA + (uint32_t)(row*CC + kb*16 + ((lane >> 4) << 3))*2u);
        }
        const uint32_t* b_lo = Vs + (kb*8 + (lane & 3))*VSTR + nq*32 + (lane >> 2);
        const uint32_t* b_hi = b_lo + 4*VSTR;
        #pragma unroll
        for (int np = 0; np < 2; ++np) {
            uint32_t b0 = b_lo[np*16], b1 = b_hi[np*16];
            uint32_t b2v = b_lo[np*16 + 8], b3 = b_hi[np*16 + 8];
            #pragma unroll
            for (int mb = 0; mb < 3; ++mb) {
                mma16816(acc[mb][np][0], a[mb], b0, b1);
                mma16816(acc[mb][np][1], a[mb], b2v, b3);
            }
        }
    }
    const float* x = (s == 0 ? xl : xr) + b*CC*HWW;
    float* o = out + (s*BB + b)*CC*HWW;
    #pragma unroll
    for (int mb = 0; mb < 3; ++mb) {
        int oc0 = mb*16 + (lane >> 2), oc1 = oc0 + 8;
        float be0 = bss[oc0], be1 = bss[oc1];
        #pragma unroll
        for (int np = 0; np < 2; ++np)
            #pragma unroll
            for (int f = 0; f < 2; ++f) {
                int px = p0 + nq*32 + np*16 + f*8 + (lane & 3)*2;
                float2 x0 = *reinterpret_cast<const float2*>(&x[oc0*HWW + px]);
                float2 x1 = *reinterpret_cast<const float2*>(&x[oc1*HWW + px]);
                *reinterpret_cast<float2*>(&o[oc0*HWW + px]) =
                    make_float2(x0.x + acc[mb][np][f][0] + be0, x0.y + acc[mb][np][f][1] + be0);
                *reinterpret_cast<float2*>(&o[oc1*HWW + px]) =
                    make_float2(x1.x + acc[mb][np][f][2] + be1, x1.y + acc[mb][np][f][3] + be1);
            }
    }
}

// ---------------- launch ----------------
extern "C" void kernel_launch(void* const* d_in, const int* in_sizes, int n_in,
                              void* d_out, int out_size) {
    const float* x_l    = (const float*)d_in[0];
    const float* x_r    = (const float*)d_in[1];
    const float* ln1_w  = (const float*)d_in[2];
    const float* ln1_b  = (const float*)d_in[3];
    const float* ln2_w  = (const float*)d_in[4];
    const float* ln2_b  = (const float*)d_in[5];
    const float* qkvl_w = (const float*)d_in[6];
    const float* qkvl_b = (const float*)d_in[7];
    const float* qkvr_w = (const float*)d_in[8];
    const float* qkvr_b = (const float*)d_in[9];
    const float* dwl_w  = (const float*)d_in[10];
    const float* dwl_b  = (const float*)d_in[11];
    const float* dwr_w  = (const float*)d_in[12];
    const float* dwr_b  = (const float*)d_in[13];
    const float* dil0_w = (const float*)d_in[14];
    const float* dil0_b = (const float*)d_in[15];
    const float* dil1_w = (const float*)d_in[16];
    const float* dil1_b = (const float*)d_in[17];
    const float* dil2_w = (const float*)d_in[18];
    const float* dil2_b = (const float*)d_in[19];
    const float* convQ_w = (const float*)d_in[20];
    const float* convQ_b = (const float*)d_in[21];
    const float* conv1_w = (const float*)d_in[22];
    const float* conv1_b = (const float*)d_in[23];
    const float* conv2_w = (const float*)d_in[24];
    const float* conv2_b = (const float*)d_in[25];
    const float* temperature = (const float*)d_in[26];

    const int SMD = (2*DBUF)*4 + 3*64*ASTR*2;   // 102912 + 39936 = 142848
    cudaFuncSetAttribute(k_dilated_mma, cudaFuncAttributeMaxDynamicSharedMemorySize, SMD);
    cudaFuncSetAttribute(k_lnqkv, cudaFuncAttributeMaxDynamicSharedMemorySize, LQ_SM);

    k_misc<<<199, 256>>>(qkvl_w, qkvr_w, convQ_w, convQ_b,
                         dil0_w, dil1_w, dil2_w, dil0_b, dil1_b, dil2_b);
    k_lnqkv<<<dim3(HWW/128, BB, 2), 288, LQ_SM>>>(x_l, x_r, ln1_w, ln1_b, ln2_w, ln2_b,
                                                  qkvl_b, qkvr_b);
    k_dw<<<dim3(HH/4, 72, 2*BB), 256>>>(dwl_w, dwl_b, dwr_w, dwr_b);
    k_dilated_mma<<<dim3(HH, BB), 256, SMD>>>();
    k_norms<<<3*BB*CC, 256>>>();
    k_dots<<<dim3(16, BB*NH, 2), 256>>>();
    k_soft_m<<<1, 256>>>(temperature, conv1_w, conv2_w);
    k_epilogue<<<dim3(HWW/256, BB, 2), 256>>>(x_l, x_r, conv1_b, conv2_b, (float*)d_out);
}

// round 11
// speedup vs baseline: 3.5524x; 1.0117x over previous
#include <cuda_runtime.h>
#include <cuda_bf16.h>
#include <cstdint>
#include <math.h>

#define BB   2
#define CC   48
#define HH   128
#define WW   256
#define HWW  (HH*WW)          // 32768
#define C3   144
#define C2   96
#define NH   3
#define CHD  16
#define BSTR 140              // qkv B row stride (u32)
#define ASTR 104              // A tile row stride (bf16)
#define DSTR 140              // dilated B row stride (u32); 140 % 32 == 12 -> conflict-free
#define DBUF (48*DSTR)        // u32 per dilated B buffer (half-row + halo)
#define VSTR 260              // epilogue V row stride (u32)

// ---------------- scratch (static device globals; no allocation) ----------------
__device__ __nv_bfloat16  g_pre_bf [2][BB][C3][HWW];   // bf16 qkv after LN+1x1
__device__ float          g_kv     [2][BB][CC][HWW];   // fp32 K after dw
__device__ uint32_t       g_vp     [2][BB][24][HWW];   // pair-packed bf16 V after dw
__device__ uint32_t       g_xp     [BB][CC][HWW];      // pair-packed bf16 [Q_l;Q_r]
__device__ float          g_qfold  [BB][CC][HWW];      // fused dilated-conv + convQ output
__device__ __nv_bfloat16  g_wbf    [27][64][C2];       // folded bf16 weights (rows 48..63 unused)
__device__ __nv_bfloat16  g_wq     [2][C3][CC];        // bf16 qkv weights
__device__ float          g_beff   [CC];
__device__ float          g_inv    [3][BB][CC];
__device__ float          g_dpart  [2*BB*NH*16*256];
__device__ __nv_bfloat16  g_Mbf    [2*BB][CC*CC];      // folded conv1/2 @ blockdiag(A), bf16

__device__ __forceinline__ uint32_t smem_u32(const void* p) {
    uint32_t a;
    asm("{ .reg .u64 t; cvta.to.shared.u64 t, %1; cvt.u32.u64 %0, t; }" : "=r"(a) : "l"(p));
    return a;
}
__device__ __forceinline__ void ldsm4(uint32_t* r, uint32_t addr) {
    asm volatile("ldmatrix.sync.aligned.m8n8.x4.shared.b16 {%0,%1,%2,%3}, [%4];"
        : "=r"(r[0]), "=r"(r[1]), "=r"(r[2]), "=r"(r[3]) : "r"(addr));
}
__device__ __forceinline__ void mma16816(float* c, const uint32_t* a, uint32_t b0, uint32_t b1) {
    asm volatile("mma.sync.aligned.m16n8k16.row.col.f32.bf16.bf16.f32 "
        "{%0,%1,%2,%3}, {%4,%5,%6,%7}, {%8,%9}, {%0,%1,%2,%3};"
        : "+f"(c[0]), "+f"(c[1]), "+f"(c[2]), "+f"(c[3])
        : "r"(a[0]), "r"(a[1]), "r"(a[2]), "r"(a[3]), "r"(b0), "r"(b1));
}
__device__ __forceinline__ uint32_t pack_bf2(float a, float b) {
    return (uint32_t)__bfloat16_as_ushort(__float2bfloat16_rn(a))
         | ((uint32_t)__bfloat16_as_ushort(__float2bfloat16_rn(b)) << 16);
}
__device__ __forceinline__ void st_bf2(__nv_bfloat16* p, float a, float b) {
    *reinterpret_cast<uint32_t*>(p) = pack_bf2(a, b);
}

// ---------------- merged prelude: prep_w + fold_w + fold_b ----------------
__global__ void k_misc(const float* __restrict__ wl, const float* __restrict__ wr,
                       const float* __restrict__ cqw, const float* __restrict__ cqb,
                       const float* __restrict__ d0w, const float* __restrict__ d1w,
                       const float* __restrict__ d2w,
                       const float* __restrict__ d0b, const float* __restrict__ d1b,
                       const float* __restrict__ d2b) {
    int blk = blockIdx.x, tid = threadIdx.x;
    if (blk < 54) {                               // qkv weights -> bf16
        int i = blk*256 + tid;
        int s = i / (C3*CC), r = i - s*(C3*CC);
        reinterpret_cast<__nv_bfloat16*>(g_wq)[i] = __float2bfloat16_rn((s ? wr : wl)[r]);
    } else if (blk < 198) {                       // fold_w: 144 blocks (o, d)
        int idx = blk - 54;
        int o = idx % CC, d = idx / CC;
        const float* dw = (d == 0) ? d0w : (d == 1) ? d1w : d2w;
        __shared__ float qr[C2];
        for (int j = tid; j < C2; j += 256)
            qr[j] = cqw[o*(3*C2) + d*C2 + j];
        __syncthreads();
        for (int ik = tid; ik < C2*9; ik += 256) {
            float acc = 0.f;
            for (int j = 0; j < C2; ++j)
                acc += qr[j] * dw[j*(C2*9) + ik];
            int i = ik / 9, kk = ik - i*9;
            g_wbf[d*9 + kk][o][i] = __float2bfloat16_rn(acc);
        }
    } else {                                      // fold_b
        __shared__ float racc[192];
        if (tid < 192) {
            int o = tid >> 2, q = tid & 3;
            float acc = 0.f;
            for (int j = q*72; j < q*72 + 72; ++j) {
                int dd = j / 96, jj = j - dd*96;
                const float* bp = (dd == 0) ? d0b : (dd == 1) ? d1b : d2b;
                acc += cqw[o*288 + j] * bp[jj];
            }
            racc[tid] = acc;
        }
        __syncthreads();
        if (tid < CC)
            g_beff[tid] = cqb[tid] + racc[tid*4] + racc[tid*4+1] + racc[tid*4+2] + racc[tid*4+3];
    }
}

// ---------------- fused LayerNorm2d + 1x1 qkv GEMM ----------------
#define LQ_XS   0
#define LQ_BS   (48*132*4)
#define LQ_AS   (LQ_BS + 24*BSTR*4)
#define LQ_BIAS (LQ_AS + C3*CC*2)
#define LQ_SM   (LQ_BIAS + C3*4)

__global__ void __launch_bounds__(288) k_lnqkv(const float* __restrict__ xl,
                                               const float* __restrict__ xr,
                                               const float* __restrict__ ln1w, const float* __restrict__ ln1b,
                                               const float* __restrict__ ln2w, const float* __restrict__ ln2b,
                                               const float* __restrict__ bl, const float* __restrict__ br) {
    extern __shared__ __align__(16) char smraw[];
    float*    xs = reinterpret_cast<float*>(smraw + LQ_XS);
    uint32_t* Bs = reinterpret_cast<uint32_t*>(smraw + LQ_BS);
    __nv_bfloat16* As = reinterpret_cast<__nv_bfloat16*>(smraw + LQ_AS);
    float*    bs = reinterpret_cast<float*>(smraw + LQ_BIAS);
    int p0 = blockIdx.x*128, b = blockIdx.y, branch = blockIdx.z;
    int tid = threadIdx.x, lane = tid & 31, wid = tid >> 5;
    const float* x = (branch == 0 ? xl : xr) + b*CC*HWW;
    {
        const uint4* src = reinterpret_cast<const uint4*>(&g_wq[branch][0][0]);
        uint4* dst = reinterpret_cast<uint4*>(As);
        for (int i = tid; i < C3*CC/8; i += 288) dst[i] = src[i];
        const float* bp = branch ? br : bl;
        for (int i = tid; i < C3; i += 288) bs[i] = bp[i];
        for (int i = tid; i < CC*128; i += 288) {
            int c = i >> 7, p = i & 127;
            xs[c*132 + p] = x[c*HWW + p0 + p];
        }
    }
    __syncthreads();
    if (tid < 128) {
        const float* lw = branch == 0 ? ln1w : ln2w;
        const float* lb = branch == 0 ? ln1b : ln2b;
        float mu = 0.f;
        #pragma unroll
        for (int c = 0; c < CC; ++c) mu += xs[c*132 + tid];
        mu *= (1.f/CC);
        float var = 0.f;
        #pragma unroll
        for (int c = 0; c < CC; ++c) { float t = xs[c*132 + tid] - mu; var += t*t; }
        float rstd = rsqrtf(var*(1.f/CC) + 1e-6f);
        #pragma unroll
        for (int kp = 0; kp < 24; ++kp) {
            float v0 = (xs[(2*kp  )*132 + tid] - mu)*rstd*lw[2*kp  ] + lb[2*kp  ];
            float v1 = (xs[(2*kp+1)*132 + tid] - mu)*rstd*lw[2*kp+1] + lb[2*kp+1];
            Bs[kp*BSTR + tid] = pack_bf2(v0, v1);
        }
    }
    __syncthreads();
    uint32_t smbA = smem_u32(As);
    int r0 = lane >> 2, cb = (lane & 3)*2;
    int oc0 = wid*16 + r0, oc1 = oc0 + 8;
    float be0 = bs[oc0], be1 = bs[oc1];
    __nv_bfloat16* o0 = &g_pre_bf[branch][b][oc0][p0];
    __nv_bfloat16* o1 = &g_pre_bf[branch][b][oc1][p0];
    #pragma unroll
    for (int half = 0; half < 2; ++half) {
        float acc[4][2][4];
        #pragma unroll
        for (int np = 0; np < 4; ++np)
            #pragma unroll
            for (int f = 0; f < 2; ++f)
                #pragma unroll
                for (int q = 0; q < 4; ++q) acc[np][f][q] = 0.f;
        #pragma unroll
        for (int kb = 0; kb < 3; ++kb) {
            uint32_t a[4];
            int row = wid*16 + (lane & 15);
            ldsm4(a, smbA + (uint32_t)(row*CC + kb*16 + ((lane >> 4) << 3))*2u);
            const uint32_t* b_lo = Bs + (kb*8 + (lane & 3))*BSTR + (lane >> 2) + half*64;
            const uint32_t* b_hi = b_lo + 4*BSTR;
            #pragma unroll
            for (int np = 0; np < 4; ++np) {
                uint32_t b0 = b_lo[np*16], b1 = b_hi[np*16];
                uint32_t b2 = b_lo[np*16 + 8], b3 = b_hi[np*16 + 8];
                mma16816(acc[np][0], a, b0, b1);
                mma16816(acc[np][1], a, b2, b3);
            }
        }
        #pragma unroll
        for (int np = 0; np < 4; ++np)
            #pragma unroll
            for (int f = 0; f < 2; ++f) {
                int c = half*64 + np*16 + f*8 + cb;
                st_bf2(o0 + c, acc[np][f][0] + be0, acc[np][f][1] + be0);
                st_bf2(o1 + c, acc[np][f][2] + be1, acc[np][f][3] + be1);
            }
    }
}

// ---------------- depthwise 3x3, channel-pair blocks -> packed stores ----------------
__global__ void k_dw(const float* __restrict__ wl, const float* __restrict__ bl,
                     const float* __restrict__ wr, const float* __restrict__ brb) {
    int z = blockIdx.z; int branch = z >> 1, b = z & 1;
    int chp = blockIdx.y;                  // 0..71 (channel pair)
    int c0 = 2*chp;
    int y0 = blockIdx.x * 4;
    __shared__ __align__(16) float rows[2][6][264];
    const float* wbase = (branch == 0 ? wl : wr);
    const float* bbase = (branch == 0 ? bl : brb);
    int tid = threadIdx.x;

    for (int idx = tid; idx < 2*6*64; idx += 256) {
        int cc = idx / 384, rem = idx - cc*384;
        int r = rem >> 6, c4 = rem & 63;
        int gy = y0 - 1 + r;
        float4 f = make_float4(0.f, 0.f, 0.f, 0.f);
        if (gy >= 0 && gy < HH) {
            const __nv_bfloat16* in = &g_pre_bf[branch][b][c0 + cc][0];
            uint2 v = *reinterpret_cast<const uint2*>(&in[gy*WW + c4*4]);
            f.x = __bfloat162float(__ushort_as_bfloat16((unsigned short)(v.x & 0xFFFF)));
            f.y = __bfloat162float(__ushort_as_bfloat16((unsigned short)(v.x >> 16)));
            f.z = __bfloat162float(__ushort_as_bfloat16((unsigned short)(v.y & 0xFFFF)));
            f.w = __bfloat162float(__ushort_as_bfloat16((unsigned short)(v.y >> 16)));
        }
        *reinterpret_cast<float4*>(&rows[cc][r][4 + 4*c4]) = f;
    }
    if (tid < 12) { int cc = tid / 6, r = tid % 6; rows[cc][r][3] = 0.f; rows[cc][r][260] = 0.f; }
    __syncthreads();

    int r  = tid >> 6;
    int x0 = (tid & 63) * 4;
    float out[2][4];
    #pragma unroll
    for (int cc = 0; cc < 2; ++cc) {
        const float* w = wbase + (c0 + cc)*9;
        float bias = bbase[c0 + cc];
        float a0 = bias, a1 = bias, a2 = bias, a3 = bias;
        #pragma unroll
        for (int ky = 0; ky < 3; ++ky) {
            const float* rp = &rows[cc][r + ky][3 + x0];
            float v0 = rp[0];
            float4 vm = *reinterpret_cast<const float4*>(rp + 1);
            float v5 = rp[5];
            float w0 = w[ky*3], w1 = w[ky*3+1], w2 = w[ky*3+2];
            a0 += w0*v0   + w1*vm.x + w2*vm.y;
            a1 += w0*vm.x + w1*vm.y + w2*vm.z;
            a2 += w0*vm.y + w1*vm.z + w2*vm.w;
            a3 += w0*vm.z + w1*vm.w + w2*v5;
        }
        out[cc][0] = a0; out[cc][1] = a1; out[cc][2] = a2; out[cc][3] = a3;
    }
    int px = (y0 + r)*WW + x0;
    if (chp < 24) {
        uint4 u;
        u.x = pack_bf2(out[0][0], out[1][0]); u.y = pack_bf2(out[0][1], out[1][1]);
        u.z = pack_bf2(out[0][2], out[1][2]); u.w = pack_bf2(out[0][3], out[1][3]);
        *reinterpret_cast<uint4*>(&g_xp[b][branch*24 + chp][px]) = u;
    } else if (chp < 48) {
        int kc = c0 - CC;
        *reinterpret_cast<float4*>(&g_kv[branch][b][kc][px]) =
            make_float4(out[0][0], out[0][1], out[0][2], out[0][3]);
        *reinterpret_cast<float4*>(&g_kv[branch][b][kc + 1][px]) =
            make_float4(out[1][0], out[1][1], out[1][2], out[1][3]);
    } else {
        uint4 u;
        u.x = pack_bf2(out[0][0], out[1][0]); u.y = pack_bf2(out[0][1], out[1][1]);
        u.z = pack_bf2(out[0][2], out[1][2]); u.w = pack_bf2(out[0][3], out[1][3]);
        *reinterpret_cast<uint4*>(&g_vp[branch][b][chp - 48][px]) = u;
    }
}

// ---------------- fused dilated convs + convQ: half-row CTA, 2 CTAs/SM ----------------
// Per CTA: (y, x-half 128 px, b). 8 warps: warp = 48 oc x 16 px.
__global__ void __launch_bounds__(256, 2) k_dilated_mma() {
    extern __shared__ __align__(16) uint32_t smx[];
    uint32_t* Bs = smx;                                                      // [2][48*140]
    __nv_bfloat16* As = reinterpret_cast<__nv_bfloat16*>(smx + 2*DBUF);      // [3][48][104]
    uint32_t smbB = smem_u32(Bs), smbA = smem_u32(As);
    int y = (int)blockIdx.x >> 1, x0 = ((int)blockIdx.x & 1)*128, b = blockIdx.y;
    int tid = threadIdx.x, lane = tid & 31, nq = tid >> 5;
    const uint32_t* xp = &g_xp[b][0][0];

    float acc[3][2][4];
    #pragma unroll
    for (int mb = 0; mb < 3; ++mb)
        #pragma unroll
        for (int f = 0; f < 2; ++f)
            #pragma unroll
            for (int q = 0; q < 4; ++q) acc[mb][f][q] = 0.f;

    auto fill_row = [&](int buf, int gy) {
        bool rowok = (gy >= 0 && gy < HH);
        uint32_t dbase = smbB + (uint32_t)buf*DBUF*4u;
        int gys = rowok ? gy : 0;
        for (int i = tid; i < 48*70; i += 256) {
            int kp = i / 70, c2 = i - kp*70;
            int gx = x0 - 6 + c2*2;
            bool ok = rowok && gx >= 0 && gx < WW;
            const uint32_t* src = xp + kp*HWW + gys*WW + (ok ? gx : 0);
            uint32_t sz = ok ? 8u : 0u;
            asm volatile("cp.async.ca.shared.global [%0], [%1], 8, %2;"
                         :: "r"(dbase + (uint32_t)(kp*DSTR + c2*2)*4u), "l"(src), "r"(sz)
                         : "memory");
        }
        asm volatile("cp.async.commit_group;" ::: "memory");
    };

    const int roff[7] = {0, -2, -4, -6, 2, 4, 6};
    fill_row(0, y);
    for (int ri = 0; ri < 7; ++ri) {
        asm volatile("cp.async.wait_group 0;" ::: "memory");
        __syncthreads();
        if (ri < 6) fill_row((ri + 1) & 1, y + roff[ri + 1]);
        const uint32_t* bcur = Bs + (ri & 1)*DBUF;
        int ng = (ri == 0) ? 3 : 1;
        for (int gi = 0; gi < ng; ++gi) {
            int d  = (ri == 0) ? gi : (ri <= 3 ? ri - 1 : ri - 4);
            int ky = (ri == 0) ? 1  : (ri <= 3 ? 0 : 2);
            if (gi) __syncthreads();
            {   // A fill: 3 taps x 48 rows x 96 K
                const uint4* src = reinterpret_cast<const uint4*>(&g_wbf[d*9 + ky*3][0][0]);
                for (int i = tid; i < 1728; i += 256) {
                    int tap = i / 576, r2 = i - tap*576;
                    int row = r2 / 12, cu = r2 - row*12;
                    *reinterpret_cast<uint4*>(&As[(tap*48 + row)*ASTR + cu*8]) =
                        src[tap*768 + row*12 + cu];
                }
            }
            __syncthreads();
            int dil = 2*(d + 1);
            #pragma unroll
            for (int kx = 0; kx < 3; ++kx) {
                int coloff = 6 + (kx - 1)*dil + nq*16 + (lane >> 2);
                uint32_t ab = smbA + (uint32_t)(kx*48*ASTR)*2u;
                #pragma unroll
                for (int kb = 0; kb < 6; ++kb) {
                    uint32_t a[3][4];
                    #pragma unroll
                    for (int mb = 0; mb < 3; ++mb) {
                        int row = mb*16 + (lane & 15);
                        ldsm4(a[mb], ab + (uint32_t)(row*ASTR + kb*16 + ((lane >> 4) << 3))*2u);
                    }
                    const uint32_t* b_lo = bcur + (kb*8 + (lane & 3))*DSTR + coloff;
                    const uint32_t* b_hi = b_lo + 4*DSTR;
                    uint32_t b0 = b_lo[0], b1 = b_hi[0];
                    uint32_t b2 = b_lo[8], b3 = b_hi[8];
                    #pragma unroll
                    for (int mb = 0; mb < 3; ++mb) {
                        mma16816(acc[mb][0], a[mb], b0, b1);
                        mma16816(acc[mb][1], a[mb], b2, b3);
                    }
                }
            }
        }
    }
    #pragma unroll
    for (int mb = 0; mb < 3; ++mb) {
        int oc = mb*16 + (lane >> 2);
        float be0 = g_beff[oc], be1 = g_beff[oc + 8];
        #pragma unroll
        for (int f = 0; f < 2; ++f) {
            int n = x0 + nq*16 + f*8 + (lane & 3)*2;
            *reinterpret_cast<float2*>(&g_qfold[b][oc][y*WW + n]) =
                make_float2(acc[mb][f][0] + be0, acc[mb][f][1] + be0);
            *reinterpret_cast<float2*>(&g_qfold[b][oc + 8][y*WW + n]) =
                make_float2(acc[mb][f][2] + be1, acc[mb][f][3] + be1);
        }
    }
}

// ---------------- per-channel L2 norms over HW ----------------
__global__ void k_norms() {
    int gid = blockIdx.x;
    int t = gid / (BB*CC);
    int r = gid - t*(BB*CC);
    int b = r / CC, c = r - b*CC;
    const float* src;
    if (t == 0)      src = &g_qfold[b][c][0];
    else if (t == 1) src = &g_kv[0][b][c][0];
    else             src = &g_kv[1][b][c][0];
    float ss = 0.f;
    const float4* s4 = reinterpret_cast<const float4*>(src);
    for (int i = threadIdx.x; i < HWW/4; i += blockDim.x) {
        float4 v = s4[i];
        ss += v.x*v.x + v.y*v.y + v.z*v.z + v.w*v.w;
    }
    #pragma unroll
    for (int off = 16; off > 0; off >>= 1)
        ss += __shfl_down_sync(0xffffffffu, ss, off);
    __shared__ float red[8];
    if ((threadIdx.x & 31) == 0) red[threadIdx.x >> 5] = ss;
    __syncthreads();
    if (threadIdx.x == 0) {
        float tot = 0.f;
        for (int i = 0; i < (int)(blockDim.x >> 5); ++i) tot += red[i];
        g_inv[t][b][c] = 1.f / fmaxf(sqrtf(tot), 1e-12f);
    }
}

// ---------------- QK^T dot partials, 2x2 register-blocked ----------------
__global__ void k_dots() {
    int chunk = blockIdx.x;
    int bh    = blockIdx.y;
    int s     = blockIdx.z;
    int b = bh / NH, h = bh - b*NH;
    const float* Q = &g_qfold[b][h*CHD][0];
    const float* K = (s == 0) ? &g_kv[1][b][h*CHD][0] : &g_kv[0][b][h*CHD][0];
    __shared__ float Qs[16][257];
    __shared__ float Ks[16][257];
    __shared__ float red[4][64][4];
    int tid = threadIdx.x;
    int pos = tid & 63, seg = tid >> 6;
    int cq = pos >> 3, ck = pos & 7;
    float a00 = 0.f, a01 = 0.f, a10 = 0.f, a11 = 0.f;
    int p0 = chunk * 2048;
    for (int sub = 0; sub < 8; ++sub) {
        __syncthreads();
        int pb = p0 + sub*256;
        #pragma unroll
        for (int e = 0; e < 16; ++e) {
            Qs[e][tid] = Q[e*HWW + pb + tid];
            Ks[e][tid] = K[e*HWW + pb + tid];
        }
        __syncthreads();
        int i0 = seg*64;
        #pragma unroll 16
        for (int i = 0; i < 64; ++i) {
            float q0 = Qs[cq][i0 + i], q1 = Qs[cq + 8][i0 + i];
            float k0 = Ks[ck][i0 + i], k1 = Ks[ck + 8][i0 + i];
            a00 += q0*k0; a01 += q0*k1; a10 += q1*k0; a11 += q1*k1;
        }
    }
    red[seg][pos][0] = a00; red[seg][pos][1] = a01;
    red[seg][pos][2] = a10; red[seg][pos][3] = a11;
    __syncthreads();
    if (tid < 64) {
        float v[4];
        #pragma unroll
        for (int q = 0; q < 4; ++q)
            v[q] = red[0][tid][q] + red[1][tid][q] + red[2][tid][q] + red[3][tid][q];
        int base = (((s*BB + b)*NH + h)*16 + chunk)*256;
        int cq0 = tid >> 3, ck0 = tid & 7;
        g_dpart[base + (cq0    )*16 + ck0    ] = v[0];
        g_dpart[base + (cq0    )*16 + ck0 + 8] = v[1];
        g_dpart[base + (cq0 + 8)*16 + ck0    ] = v[2];
        g_dpart[base + (cq0 + 8)*16 + ck0 + 8] = v[3];
    }
}

// ---------------- softmax + fold conv1/2 into bf16 M ----------------
__global__ void k_soft_m(const float* __restrict__ temp,
                         const float* __restrict__ w1, const float* __restrict__ w2) {
    __shared__ float As2[192][16];
    int tid = threadIdx.x;
    if (tid < 192) {
        int s = tid / 96, rem = tid - s*96;
        int b = rem / 48, rem2 = rem - b*48;
        int h = rem2 / 16, cq = rem2 - h*16;
        float v[16];
        #pragma unroll
        for (int ck = 0; ck < 16; ++ck) v[ck] = 0.f;
        int base = (((s*BB + b)*NH + h)*16)*256 + cq*16;
        for (int chunk = 0; chunk < 16; ++chunk) {
            #pragma unroll
            for (int ck = 0; ck < 16; ++ck)
                v[ck] += g_dpart[base + chunk*256 + ck];
        }
        float iq = g_inv[0][b][h*16 + cq];
        float tm = temp[h];
        const float* ik = (s == 0) ? &g_inv[2][b][h*16] : &g_inv[1][b][h*16];
        float mx = -1e30f;
        #pragma unroll
        for (int ck = 0; ck < 16; ++ck) { v[ck] *= iq * ik[ck] * tm; mx = fmaxf(mx, v[ck]); }
        float sum = 0.f;
        #pragma unroll
        for (int ck = 0; ck < 16; ++ck) { v[ck] = expf(v[ck] - mx); sum += v[ck]; }
        float inv = 1.f / sum;
        #pragma unroll
        for (int ck = 0; ck < 16; ++ck) As2[tid][ck] = v[ck] * inv;
    }
    __syncthreads();
    for (int idx = tid; idx < 2*BB*CC*CC; idx += blockDim.x) {
        int s = idx / (BB*CC*CC), rem = idx - s*(BB*CC*CC);
        int b = rem / (CC*CC), rem2 = rem - b*(CC*CC);
        int o = rem2 / CC, dg = rem2 - o*CC;
        int h = dg / 16, dd = dg - h*16;
        const float* wv = ((s == 0) ? w1 : w2) + o*CC + h*16;
        int arow = s*96 + b*48 + h*16;
        float acc = 0.f;
        #pragma unroll
        for (int c = 0; c < 16; ++c)
            acc += wv[c] * As2[arow + c][dd];
        g_Mbf[s*BB + b][o*CC + dg] = __float2bfloat16_rn(acc);
    }
}

// ---------------- epilogue: out = x + M @ V + bias via mma.sync ----------------
__global__ void __launch_bounds__(256) k_epilogue(const float* __restrict__ xl,
                                                  const float* __restrict__ xr,
                                                  const float* __restrict__ b1,
                                                  const float* __restrict__ b2,
                                                  float* __restrict__ out) {
    __shared__ __align__(16) __nv_bfloat16 Ms[CC*CC];
    __shared__ uint32_t Vs[24*VSTR];
    __shared__ float bss[CC];
    int p0 = blockIdx.x*256, b = blockIdx.y, s = blockIdx.z;
    int tid = threadIdx.x, lane = tid & 31, nq = tid >> 5;
    {
        const uint4* src = reinterpret_cast<const uint4*>(&g_Mbf[s*BB + b][0]);
        uint4* dst = reinterpret_cast<uint4*>(Ms);
        for (int i = tid; i < CC*CC/8; i += 256) dst[i] = src[i];
        const uint32_t* vsrc = &g_vp[s][b][0][0];
        for (int i = tid; i < 24*256; i += 256) {
            int kp = i >> 8, col = i & 255;
            Vs[kp*VSTR + col] = vsrc[kp*HWW + p0 + col];
        }
        const float* bp = s ? b2 : b1;
        for (int i = tid; i < CC; i += 256) bss[i] = bp[i];
    }
    __syncthreads();
    float acc[3][2][2][4];
    #pragma unroll
    for (int mb = 0; mb < 3; ++mb)
        #pragma unroll
        for (int np = 0; np < 2; ++np)
            #pragma unroll
            for (int f = 0; f < 2; ++f)
                #pragma unroll
                for (int q = 0; q < 4; ++q) acc[mb][np][f][q] = 0.f;
    uint32_t smbA = smem_u32(Ms);
    #pragma unroll
    for (int kb = 0; kb < 3; ++kb) {
        uint32_t a[3][4];
        #pragma unroll
        for (int mb = 0; mb < 3; ++mb) {
            int row = mb*16 + (lane & 15);
            ldsm4(a[mb], smbA + (uint32_t)(row*CC + kb*16 + ((lane >> 4) << 3))*2u);
        }
        const uint32_t* b_lo = Vs + (kb*8 + (lane & 3))*VSTR + nq*32 + (lane >> 2);
        const uint32_t* b_hi = b_lo + 4*VSTR;
        #pragma unroll
        for (int np = 0; np < 2; ++np) {
            uint32_t b0 = b_lo[np*16], b1 = b_hi[np*16];
            uint32_t b2v = b_lo[np*16 + 8], b3 = b_hi[np*16 + 8];
            #pragma unroll
            for (int mb = 0; mb < 3; ++mb) {
                mma16816(acc[mb][np][0], a[mb], b0, b1);
                mma16816(acc[mb][np][1], a[mb], b2v, b3);
            }
        }
    }
    const float* x = (s == 0 ? xl : xr) + b*CC*HWW;
    float* o = out + (s*BB + b)*CC*HWW;
    #pragma unroll
    for (int mb = 0; mb < 3; ++mb) {
        int oc0 = mb*16 + (lane >> 2), oc1 = oc0 + 8;
        float be0 = bss[oc0], be1 = bss[oc1];
        #pragma unroll
        for (int np = 0; np < 2; ++np)
            #pragma unroll
            for (int f = 0; f < 2; ++f) {
                int px = p0 + nq*32 + np*16 + f*8 + (lane & 3)*2;
                float2 x0 = *reinterpret_cast<const float2*>(&x[oc0*HWW + px]);
                float2 x1 = *reinterpret_cast<const float2*>(&x[oc1*HWW + px]);
                *reinterpret_cast<float2*>(&o[oc0*HWW + px]) =
                    make_float2(x0.x + acc[mb][np][f][0] + be0, x0.y + acc[mb][np][f][1] + be0);
                *reinterpret_cast<float2*>(&o[oc1*HWW + px]) =
                    make_float2(x1.x + acc[mb][np][f][2] + be1, x1.y + acc[mb][np][f][3] + be1);
            }
    }
}

// ---------------- launch ----------------
extern "C" void kernel_launch(void* const* d_in, const int* in_sizes, int n_in,
                              void* d_out, int out_size) {
    const float* x_l    = (const float*)d_in[0];
    const float* x_r    = (const float*)d_in[1];
    const float* ln1_w  = (const float*)d_in[2];
    const float* ln1_b  = (const float*)d_in[3];
    const float* ln2_w  = (const float*)d_in[4];
    const float* ln2_b  = (const float*)d_in[5];
    const float* qkvl_w = (const float*)d_in[6];
    const float* qkvl_b = (const float*)d_in[7];
    const float* qkvr_w = (const float*)d_in[8];
    const float* qkvr_b = (const float*)d_in[9];
    const float* dwl_w  = (const float*)d_in[10];
    const float* dwl_b  = (const float*)d_in[11];
    const float* dwr_w  = (const float*)d_in[12];
    const float* dwr_b  = (const float*)d_in[13];
    const float* dil0_w = (const float*)d_in[14];
    const float* dil0_b = (const float*)d_in[15];
    const float* dil1_w = (const float*)d_in[16];
    const float* dil1_b = (const float*)d_in[17];
    const float* dil2_w = (const float*)d_in[18];
    const float* dil2_b = (const float*)d_in[19];
    const float* convQ_w = (const float*)d_in[20];
    const float* convQ_b = (const float*)d_in[21];
    const float* conv1_w = (const float*)d_in[22];
    const float* conv1_b = (const float*)d_in[23];
    const float* conv2_w = (const float*)d_in[24];
    const float* conv2_b = (const float*)d_in[25];
    const float* temperature = (const float*)d_in[26];

    const int SMD = (2*DBUF)*4 + 3*48*ASTR*2;   // 53760 + 29952 = 83712 -> 2 CTAs/SM
    cudaFuncSetAttribute(k_dilated_mma, cudaFuncAttributeMaxDynamicSharedMemorySize, SMD);
    cudaFuncSetAttribute(k_lnqkv, cudaFuncAttributeMaxDynamicSharedMemorySize, LQ_SM);

    k_misc<<<199, 256>>>(qkvl_w, qkvr_w, convQ_w, convQ_b,
                         dil0_w, dil1_w, dil2_w, dil0_b, dil1_b, dil2_b);
    k_lnqkv<<<dim3(HWW/128, BB, 2), 288, LQ_SM>>>(x_l, x_r, ln1_w, ln1_b, ln2_w, ln2_b,
                                                  qkvl_b, qkvr_b);
    k_dw<<<dim3(HH/4, 72, 2*BB), 256>>>(dwl_w, dwl_b, dwr_w, dwr_b);
    k_dilated_mma<<<dim3(2*HH, BB), 256, SMD>>>();
    k_norms<<<3*BB*CC, 256>>>();
    k_dots<<<dim3(16, BB*NH, 2), 256>>>();
    k_soft_m<<<1, 256>>>(temperature, conv1_w, conv2_w);
    k_epilogue<<<dim3(HWW/256, BB, 2), 256>>>(x_l, x_r, conv1_b, conv2_b, (float*)d_out);
}

// round 12
// speedup vs baseline: 4.0407x; 1.1375x over previous
#include <cuda_runtime.h>
#include <cuda_bf16.h>
#include <cstdint>
#include <math.h>

#define BB   2
#define CC   48
#define HH   128
#define WW   256
#define HWW  (HH*WW)          // 32768
#define C3   144
#define C2   96
#define NH   3
#define CHD  16
#define BSTR 140              // qkv B row stride (u32)
#define ASTR 104              // A tile row stride (bf16)
#define DSTR 140              // dilated B row stride (u32); full row 134 pairs + pad; 140%32==12
#define DBUF (48*DSTR)        // u32 per dilated B buffer
#define ATILE (48*ASTR)       // bf16 per dilated A buffer (one tap)
#define VSTR 260              // epilogue V row stride (u32)

// ---------------- scratch (static device globals; no allocation) ----------------
__device__ __nv_bfloat16  g_pre_bf [2][BB][C3][HWW];   // bf16 qkv after LN+1x1
__device__ float          g_kv     [2][BB][CC][HWW];   // fp32 K after dw
__device__ uint32_t       g_vp     [2][BB][24][HWW];   // pair-packed bf16 V after dw
__device__ uint32_t       g_xp     [BB][CC][HWW];      // pair-packed bf16 [Q_l;Q_r]
__device__ float          g_qfold  [BB][CC][HWW];      // fused dilated-conv + convQ output
__device__ __nv_bfloat16  g_wbf    [27][64][C2];       // folded bf16 weights (rows 48..63 unused)
__device__ __nv_bfloat16  g_wq     [2][C3][CC];        // bf16 qkv weights
__device__ float          g_beff   [CC];
__device__ float          g_inv    [3][BB][CC];
__device__ float          g_dpart  [2*BB*NH*16*256];
__device__ __nv_bfloat16  g_Mbf    [2*BB][CC*CC];      // folded conv1/2 @ blockdiag(A), bf16

__device__ __forceinline__ uint32_t smem_u32(const void* p) {
    uint32_t a;
    asm("{ .reg .u64 t; cvta.to.shared.u64 t, %1; cvt.u32.u64 %0, t; }" : "=r"(a) : "l"(p));
    return a;
}
__device__ __forceinline__ void ldsm4(uint32_t* r, uint32_t addr) {
    asm volatile("ldmatrix.sync.aligned.m8n8.x4.shared.b16 {%0,%1,%2,%3}, [%4];"
        : "=r"(r[0]), "=r"(r[1]), "=r"(r[2]), "=r"(r[3]) : "r"(addr));
}
__device__ __forceinline__ void mma16816(float* c, const uint32_t* a, uint32_t b0, uint32_t b1) {
    asm volatile("mma.sync.aligned.m16n8k16.row.col.f32.bf16.bf16.f32 "
        "{%0,%1,%2,%3}, {%4,%5,%6,%7}, {%8,%9}, {%0,%1,%2,%3};"
        : "+f"(c[0]), "+f"(c[1]), "+f"(c[2]), "+f"(c[3])
        : "r"(a[0]), "r"(a[1]), "r"(a[2]), "r"(a[3]), "r"(b0), "r"(b1));
}
__device__ __forceinline__ uint32_t pack_bf2(float a, float b) {
    return (uint32_t)__bfloat16_as_ushort(__float2bfloat16_rn(a))
         | ((uint32_t)__bfloat16_as_ushort(__float2bfloat16_rn(b)) << 16);
}
__device__ __forceinline__ void st_bf2(__nv_bfloat16* p, float a, float b) {
    *reinterpret_cast<uint32_t*>(p) = pack_bf2(a, b);
}

// ---------------- merged prelude: prep_w + fold_w + fold_b ----------------
__global__ void k_misc(const float* __restrict__ wl, const float* __restrict__ wr,
                       const float* __restrict__ cqw, const float* __restrict__ cqb,
                       const float* __restrict__ d0w, const float* __restrict__ d1w,
                       const float* __restrict__ d2w,
                       const float* __restrict__ d0b, const float* __restrict__ d1b,
                       const float* __restrict__ d2b) {
    int blk = blockIdx.x, tid = threadIdx.x;
    if (blk < 54) {                               // qkv weights -> bf16
        int i = blk*256 + tid;
        int s = i / (C3*CC), r = i - s*(C3*CC);
        reinterpret_cast<__nv_bfloat16*>(g_wq)[i] = __float2bfloat16_rn((s ? wr : wl)[r]);
    } else if (blk < 198) {                       // fold_w: 144 blocks (o, d)
        int idx = blk - 54;
        int o = idx % CC, d = idx / CC;
        const float* dw = (d == 0) ? d0w : (d == 1) ? d1w : d2w;
        __shared__ float qr[C2];
        for (int j = tid; j < C2; j += 256)
            qr[j] = cqw[o*(3*C2) + d*C2 + j];
        __syncthreads();
        for (int ik = tid; ik < C2*9; ik += 256) {
            float acc = 0.f;
            for (int j = 0; j < C2; ++j)
                acc += qr[j] * dw[j*(C2*9) + ik];
            int i = ik / 9, kk = ik - i*9;
            g_wbf[d*9 + kk][o][i] = __float2bfloat16_rn(acc);
        }
    } else {                                      // fold_b
        __shared__ float racc[192];
        if (tid < 192) {
            int o = tid >> 2, q = tid & 3;
            float acc = 0.f;
            for (int j = q*72; j < q*72 + 72; ++j) {
                int dd = j / 96, jj = j - dd*96;
                const float* bp = (dd == 0) ? d0b : (dd == 1) ? d1b : d2b;
                acc += cqw[o*288 + j] * bp[jj];
            }
            racc[tid] = acc;
        }
        __syncthreads();
        if (tid < CC)
            g_beff[tid] = cqb[tid] + racc[tid*4] + racc[tid*4+1] + racc[tid*4+2] + racc[tid*4+3];
    }
}

// ---------------- fused LayerNorm2d + 1x1 qkv GEMM ----------------
#define LQ_XS   0
#define LQ_BS   (48*132*4)
#define LQ_AS   (LQ_BS + 24*BSTR*4)
#define LQ_BIAS (LQ_AS + C3*CC*2)
#define LQ_SM   (LQ_BIAS + C3*4)

__global__ void __launch_bounds__(288) k_lnqkv(const float* __restrict__ xl,
                                               const float* __restrict__ xr,
                                               const float* __restrict__ ln1w, const float* __restrict__ ln1b,
                                               const float* __restrict__ ln2w, const float* __restrict__ ln2b,
                                               const float* __restrict__ bl, const float* __restrict__ br) {
    extern __shared__ __align__(16) char smraw[];
    float*    xs = reinterpret_cast<float*>(smraw + LQ_XS);
    uint32_t* Bs = reinterpret_cast<uint32_t*>(smraw + LQ_BS);
    __nv_bfloat16* As = reinterpret_cast<__nv_bfloat16*>(smraw + LQ_AS);
    float*    bs = reinterpret_cast<float*>(smraw + LQ_BIAS);
    int p0 = blockIdx.x*128, b = blockIdx.y, branch = blockIdx.z;
    int tid = threadIdx.x, lane = tid & 31, wid = tid >> 5;
    const float* x = (branch == 0 ? xl : xr) + b*CC*HWW;
    {
        const uint4* src = reinterpret_cast<const uint4*>(&g_wq[branch][0][0]);
        uint4* dst = reinterpret_cast<uint4*>(As);
        for (int i = tid; i < C3*CC/8; i += 288) dst[i] = src[i];
        const float* bp = branch ? br : bl;
        for (int i = tid; i < C3; i += 288) bs[i] = bp[i];
        for (int i = tid; i < CC*128; i += 288) {
            int c = i >> 7, p = i & 127;
            xs[c*132 + p] = x[c*HWW + p0 + p];
        }
    }
    __syncthreads();
    if (tid < 128) {
        const float* lw = branch == 0 ? ln1w : ln2w;
        const float* lb = branch == 0 ? ln1b : ln2b;
        float mu = 0.f;
        #pragma unroll
        for (int c = 0; c < CC; ++c) mu += xs[c*132 + tid];
        mu *= (1.f/CC);
        float var = 0.f;
        #pragma unroll
        for (int c = 0; c < CC; ++c) { float t = xs[c*132 + tid] - mu; var += t*t; }
        float rstd = rsqrtf(var*(1.f/CC) + 1e-6f);
        #pragma unroll
        for (int kp = 0; kp < 24; ++kp) {
            float v0 = (xs[(2*kp  )*132 + tid] - mu)*rstd*lw[2*kp  ] + lb[2*kp  ];
            float v1 = (xs[(2*kp+1)*132 + tid] - mu)*rstd*lw[2*kp+1] + lb[2*kp+1];
            Bs[kp*BSTR + tid] = pack_bf2(v0, v1);
        }
    }
    __syncthreads();
    uint32_t smbA = smem_u32(As);
    int r0 = lane >> 2, cb = (lane & 3)*2;
    int oc0 = wid*16 + r0, oc1 = oc0 + 8;
    float be0 = bs[oc0], be1 = bs[oc1];
    __nv_bfloat16* o0 = &g_pre_bf[branch][b][oc0][p0];
    __nv_bfloat16* o1 = &g_pre_bf[branch][b][oc1][p0];
    #pragma unroll
    for (int half = 0; half < 2; ++half) {
        float acc[4][2][4];
        #pragma unroll
        for (int np = 0; np < 4; ++np)
            #pragma unroll
            for (int f = 0; f < 2; ++f)
                #pragma unroll
                for (int q = 0; q < 4; ++q) acc[np][f][q] = 0.f;
        #pragma unroll
        for (int kb = 0; kb < 3; ++kb) {
            uint32_t a[4];
            int row = wid*16 + (lane & 15);
            ldsm4(a, smbA + (uint32_t)(row*CC + kb*16 + ((lane >> 4) << 3))*2u);
            const uint32_t* b_lo = Bs + (kb*8 + (lane & 3))*BSTR + (lane >> 2) + half*64;
            const uint32_t* b_hi = b_lo + 4*BSTR;
            #pragma unroll
            for (int np = 0; np < 4; ++np) {
                uint32_t b0 = b_lo[np*16], b1 = b_hi[np*16];
                uint32_t b2 = b_lo[np*16 + 8], b3 = b_hi[np*16 + 8];
                mma16816(acc[np][0], a, b0, b1);
                mma16816(acc[np][1], a, b2, b3);
            }
        }
        #pragma unroll
        for (int np = 0; np < 4; ++np)
            #pragma unroll
            for (int f = 0; f < 2; ++f) {
                int c = half*64 + np*16 + f*8 + cb;
                st_bf2(o0 + c, acc[np][f][0] + be0, acc[np][f][1] + be0);
                st_bf2(o1 + c, acc[np][f][2] + be1, acc[np][f][3] + be1);
            }
    }
}

// ---------------- depthwise 3x3, channel-pair blocks -> packed stores ----------------
__global__ void k_dw(const float* __restrict__ wl, const float* __restrict__ bl,
                     const float* __restrict__ wr, const float* __restrict__ brb) {
    int z = blockIdx.z; int branch = z >> 1, b = z & 1;
    int chp = blockIdx.y;                  // 0..71 (channel pair)
    int c0 = 2*chp;
    int y0 = blockIdx.x * 4;
    __shared__ __align__(16) float rows[2][6][264];
    const float* wbase = (branch == 0 ? wl : wr);
    const float* bbase = (branch == 0 ? bl : brb);
    int tid = threadIdx.x;

    for (int idx = tid; idx < 2*6*64; idx += 256) {
        int cc = idx / 384, rem = idx - cc*384;
        int r = rem >> 6, c4 = rem & 63;
        int gy = y0 - 1 + r;
        float4 f = make_float4(0.f, 0.f, 0.f, 0.f);
        if (gy >= 0 && gy < HH) {
            const __nv_bfloat16* in = &g_pre_bf[branch][b][c0 + cc][0];
            uint2 v = *reinterpret_cast<const uint2*>(&in[gy*WW + c4*4]);
            f.x = __bfloat162float(__ushort_as_bfloat16((unsigned short)(v.x & 0xFFFF)));
            f.y = __bfloat162float(__ushort_as_bfloat16((unsigned short)(v.x >> 16)));
            f.z = __bfloat162float(__ushort_as_bfloat16((unsigned short)(v.y & 0xFFFF)));
            f.w = __bfloat162float(__ushort_as_bfloat16((unsigned short)(v.y >> 16)));
        }
        *reinterpret_cast<float4*>(&rows[cc][r][4 + 4*c4]) = f;
    }
    if (tid < 12) { int cc = tid / 6, r = tid % 6; rows[cc][r][3] = 0.f; rows[cc][r][260] = 0.f; }
    __syncthreads();

    int r  = tid >> 6;
    int x0 = (tid & 63) * 4;
    float out[2][4];
    #pragma unroll
    for (int cc = 0; cc < 2; ++cc) {
        const float* w = wbase + (c0 + cc)*9;
        float bias = bbase[c0 + cc];
        float a0 = bias, a1 = bias, a2 = bias, a3 = bias;
        #pragma unroll
        for (int ky = 0; ky < 3; ++ky) {
            const float* rp = &rows[cc][r + ky][3 + x0];
            float v0 = rp[0];
            float4 vm = *reinterpret_cast<const float4*>(rp + 1);
            float v5 = rp[5];
            float w0 = w[ky*3], w1 = w[ky*3+1], w2 = w[ky*3+2];
            a0 += w0*v0   + w1*vm.x + w2*vm.y;
            a1 += w0*vm.x + w1*vm.y + w2*vm.z;
            a2 += w0*vm.y + w1*vm.z + w2*vm.w;
            a3 += w0*vm.z + w1*vm.w + w2*v5;
        }
        out[cc][0] = a0; out[cc][1] = a1; out[cc][2] = a2; out[cc][3] = a3;
    }
    int px = (y0 + r)*WW + x0;
    if (chp < 24) {
        uint4 u;
        u.x = pack_bf2(out[0][0], out[1][0]); u.y = pack_bf2(out[0][1], out[1][1]);
        u.z = pack_bf2(out[0][2], out[1][2]); u.w = pack_bf2(out[0][3], out[1][3]);
        *reinterpret_cast<uint4*>(&g_xp[b][branch*24 + chp][px]) = u;
    } else if (chp < 48) {
        int kc = c0 - CC;
        *reinterpret_cast<float4*>(&g_kv[branch][b][kc][px]) =
            make_float4(out[0][0], out[0][1], out[0][2], out[0][3]);
        *reinterpret_cast<float4*>(&g_kv[branch][b][kc + 1][px]) =
            make_float4(out[1][0], out[1][1], out[1][2], out[1][3]);
    } else {
        uint4 u;
        u.x = pack_bf2(out[0][0], out[1][0]); u.y = pack_bf2(out[0][1], out[1][1]);
        u.z = pack_bf2(out[0][2], out[1][2]); u.w = pack_bf2(out[0][3], out[1][3]);
        *reinterpret_cast<uint4*>(&g_vp[branch][b][chp - 48][px]) = u;
    }
}

// ---------------- fused dilated convs + convQ: full-row CTA, 27-stage A/B cp.async pipeline ----------------
// Per CTA: (y, b), 256 px, one wave (256 CTAs, 2/SM). 8 warps: warp = 48 oc x 32 px (np=2).
// Stage s: s<9: ky=1, d=s/3 (row y);  9..17: ky=0, d=(s-9)/3 (rows y-2,y-4,y-6);
//          18..26: ky=2, d=(s-18)/3 (rows y+2,y+4,y+6).  kx = s%3 in all cases.
__global__ void __launch_bounds__(256, 2) k_dilated_mma() {
    extern __shared__ __align__(16) uint32_t smx[];
    uint32_t* Bs = smx;                                                  // [2][48*140]
    __nv_bfloat16* As = reinterpret_cast<__nv_bfloat16*>(smx + 2*DBUF);  // [2][48][104]
    uint32_t smbB = smem_u32(Bs), smbA = smem_u32(As);
    int y = blockIdx.x, b = blockIdx.y;
    int tid = threadIdx.x, lane = tid & 31, nq = tid >> 5;
    const uint32_t* xp = &g_xp[b][0][0];

    float acc[3][2][2][4];
    #pragma unroll
    for (int mb = 0; mb < 3; ++mb)
        #pragma unroll
        for (int np = 0; np < 2; ++np)
            #pragma unroll
            for (int f = 0; f < 2; ++f)
                #pragma unroll
                for (int q = 0; q < 4; ++q) acc[mb][np][f][q] = 0.f;

    auto fill_B = [&](int buf, int gy) {
        bool rowok = (gy >= 0 && gy < HH);
        uint32_t dbase = smbB + (uint32_t)buf*DBUF*4u;
        int gys = rowok ? gy : 0;
        for (int i = tid; i < 48*134; i += 256) {
            int kp = i / 134, c2 = i - kp*134;
            int gx = c2*2 - 6;
            bool ok = rowok && gx >= 0 && gx < WW;
            const uint32_t* src = xp + kp*HWW + gys*WW + (ok ? gx : 0);
            uint32_t sz = ok ? 8u : 0u;
            asm volatile("cp.async.ca.shared.global [%0], [%1], 8, %2;"
                         :: "r"(dbase + (uint32_t)(kp*DSTR + c2*2)*4u), "l"(src), "r"(sz)
                         : "memory");
        }
    };
    auto fill_A = [&](int buf, int tap) {
        const __nv_bfloat16* src = &g_wbf[tap][0][0];
        uint32_t dbase = smbA + (uint32_t)buf*ATILE*2u;
        for (int i = tid; i < 576; i += 256) {       // 48 rows x 12 uint4
            int row = i / 12, cu = i - row*12;
            asm volatile("cp.async.ca.shared.global [%0], [%1], 16;"
                         :: "r"(dbase + (uint32_t)(row*ASTR + cu*8)*2u),
                            "l"(src + row*C2 + cu*8) : "memory");
        }
    };
    auto stage_dky = [](int s, int& d, int& ky) {
        if (s < 9)       { d = s/3;      ky = 1; }
        else if (s < 18) { d = (s-9)/3;  ky = 0; }
        else             { d = (s-18)/3; ky = 2; }
    };

    // prologue: stage 0 fills (A tap = d0,ky1,kx0 -> tap 3*0+3*1+0 = 3)
    fill_A(0, 0*9 + 1*3 + 0);
    fill_B(0, y);
    asm volatile("cp.async.commit_group;" ::: "memory");

    #pragma unroll 1
    for (int s = 0; s < 27; ++s) {
        asm volatile("cp.async.wait_group 0;" ::: "memory");
        __syncthreads();
        if (s < 26) {
            int ns = s + 1;
            int nd, nky; stage_dky(ns, nd, nky);
            fill_A(ns & 1, nd*9 + nky*3 + (ns % 3));
            if (ns >= 9 && (ns - 9) % 3 == 0) {      // new B row starts at ns
                int rb = 1 + (ns - 9)/3;              // 1..6
                int gy = y + (nky - 1)*2*(nd + 1);
                fill_B(rb & 1, gy);
            }
            asm volatile("cp.async.commit_group;" ::: "memory");
        }
        int d, ky; stage_dky(s, d, ky);
        int rb = (s < 9) ? 0 : 1 + (s - 9)/3;
        const uint32_t* bcur = Bs + (rb & 1)*DBUF;
        uint32_t ab = smbA + (uint32_t)((s & 1)*ATILE)*2u;
        int dil = 2*(d + 1);
        int coloff = 6 + ((s % 3) - 1)*dil + nq*32 + (lane >> 2);
        #pragma unroll
        for (int kb = 0; kb < 6; ++kb) {
            uint32_t a[3][4];
            #pragma unroll
            for (int mb = 0; mb < 3; ++mb) {
                int row = mb*16 + (lane & 15);
                ldsm4(a[mb], ab + (uint32_t)(row*ASTR + kb*16 + ((lane >> 4) << 3))*2u);
            }
            const uint32_t* b_lo = bcur + (kb*8 + (lane & 3))*DSTR + coloff;
            const uint32_t* b_hi = b_lo + 4*DSTR;
            #pragma unroll
            for (int np = 0; np < 2; ++np) {
                uint32_t b0 = b_lo[np*16], b1 = b_hi[np*16];
                uint32_t b2 = b_lo[np*16 + 8], b3 = b_hi[np*16 + 8];
                #pragma unroll
                for (int mb = 0; mb < 3; ++mb) {
                    mma16816(acc[mb][np][0], a[mb], b0, b1);
                    mma16816(acc[mb][np][1], a[mb], b2, b3);
                }
            }
        }
    }
    #pragma unroll
    for (int mb = 0; mb < 3; ++mb) {
        int oc = mb*16 + (lane >> 2);
        float be0 = g_beff[oc], be1 = g_beff[oc + 8];
        #pragma unroll
        for (int np = 0; np < 2; ++np)
            #pragma unroll
            for (int f = 0; f < 2; ++f) {
                int n = nq*32 + np*16 + f*8 + (lane & 3)*2;
                *reinterpret_cast<float2*>(&g_qfold[b][oc][y*WW + n]) =
                    make_float2(acc[mb][np][f][0] + be0, acc[mb][np][f][1] + be0);
                *reinterpret_cast<float2*>(&g_qfold[b][oc + 8][y*WW + n]) =
                    make_float2(acc[mb][np][f][2] + be1, acc[mb][np][f][3] + be1);
            }
    }
}

// ---------------- per-channel L2 norms over HW ----------------
__global__ void k_norms() {
    int gid = blockIdx.x;
    int t = gid / (BB*CC);
    int r = gid - t*(BB*CC);
    int b = r / CC, c = r - b*CC;
    const float* src;
    if (t == 0)      src = &g_qfold[b][c][0];
    else if (t == 1) src = &g_kv[0][b][c][0];
    else             src = &g_kv[1][b][c][0];
    float ss = 0.f;
    const float4* s4 = reinterpret_cast<const float4*>(src);
    for (int i = threadIdx.x; i < HWW/4; i += blockDim.x) {
        float4 v = s4[i];
        ss += v.x*v.x + v.y*v.y + v.z*v.z + v.w*v.w;
    }
    #pragma unroll
    for (int off = 16; off > 0; off >>= 1)
        ss += __shfl_down_sync(0xffffffffu, ss, off);
    __shared__ float red[8];
    if ((threadIdx.x & 31) == 0) red[threadIdx.x >> 5] = ss;
    __syncthreads();
    if (threadIdx.x == 0) {
        float tot = 0.f;
        for (int i = 0; i < (int)(blockDim.x >> 5); ++i) tot += red[i];
        g_inv[t][b][c] = 1.f / fmaxf(sqrtf(tot), 1e-12f);
    }
}

// ---------------- QK^T dot partials, 2x2 register-blocked ----------------
__global__ void k_dots() {
    int chunk = blockIdx.x;
    int bh    = blockIdx.y;
    int s     = blockIdx.z;
    int b = bh / NH, h = bh - b*NH;
    const float* Q = &g_qfold[b][h*CHD][0];
    const float* K = (s == 0) ? &g_kv[1][b][h*CHD][0] : &g_kv[0][b][h*CHD][0];
    __shared__ float Qs[16][257];
    __shared__ float Ks[16][257];
    __shared__ float red[4][64][4];
    int tid = threadIdx.x;
    int pos = tid & 63, seg = tid >> 6;
    int cq = pos >> 3, ck = pos & 7;
    float a00 = 0.f, a01 = 0.f, a10 = 0.f, a11 = 0.f;
    int p0 = chunk * 2048;
    for (int sub = 0; sub < 8; ++sub) {
        __syncthreads();
        int pb = p0 + sub*256;
        #pragma unroll
        for (int e = 0; e < 16; ++e) {
            Qs[e][tid] = Q[e*HWW + pb + tid];
            Ks[e][tid] = K[e*HWW + pb + tid];
        }
        __syncthreads();
        int i0 = seg*64;
        #pragma unroll 16
        for (int i = 0; i < 64; ++i) {
            float q0 = Qs[cq][i0 + i], q1 = Qs[cq + 8][i0 + i];
            float k0 = Ks[ck][i0 + i], k1 = Ks[ck + 8][i0 + i];
            a00 += q0*k0; a01 += q0*k1; a10 += q1*k0; a11 += q1*k1;
        }
    }
    red[seg][pos][0] = a00; red[seg][pos][1] = a01;
    red[seg][pos][2] = a10; red[seg][pos][3] = a11;
    __syncthreads();
    if (tid < 64) {
        float v[4];
        #pragma unroll
        for (int q = 0; q < 4; ++q)
            v[q] = red[0][tid][q] + red[1][tid][q] + red[2][tid][q] + red[3][tid][q];
        int base = (((s*BB + b)*NH + h)*16 + chunk)*256;
        int cq0 = tid >> 3, ck0 = tid & 7;
        g_dpart[base + (cq0    )*16 + ck0    ] = v[0];
        g_dpart[base + (cq0    )*16 + ck0 + 8] = v[1];
        g_dpart[base + (cq0 + 8)*16 + ck0    ] = v[2];
        g_dpart[base + (cq0 + 8)*16 + ck0 + 8] = v[3];
    }
}

// ---------------- softmax + fold conv1/2 into bf16 M ----------------
__global__ void k_soft_m(const float* __restrict__ temp,
                         const float* __restrict__ w1, const float* __restrict__ w2) {
    __shared__ float As2[192][16];
    int tid = threadIdx.x;
    if (tid < 192) {
        int s = tid / 96, rem = tid - s*96;
        int b = rem / 48, rem2 = rem - b*48;
        int h = rem2 / 16, cq = rem2 - h*16;
        float v[16];
        #pragma unroll
        for (int ck = 0; ck < 16; ++ck) v[ck] = 0.f;
        int base = (((s*BB + b)*NH + h)*16)*256 + cq*16;
        for (int chunk = 0; chunk < 16; ++chunk) {
            #pragma unroll
            for (int ck = 0; ck < 16; ++ck)
                v[ck] += g_dpart[base + chunk*256 + ck];
        }
        float iq = g_inv[0][b][h*16 + cq];
        float tm = temp[h];
        const float* ik = (s == 0) ? &g_inv[2][b][h*16] : &g_inv[1][b][h*16];
        float mx = -1e30f;
        #pragma unroll
        for (int ck = 0; ck < 16; ++ck) { v[ck] *= iq * ik[ck] * tm; mx = fmaxf(mx, v[ck]); }
        float sum = 0.f;
        #pragma unroll
        for (int ck = 0; ck < 16; ++ck) { v[ck] = expf(v[ck] - mx); sum += v[ck]; }
        float inv = 1.f / sum;
        #pragma unroll
        for (int ck = 0; ck < 16; ++ck) As2[tid][ck] = v[ck] * inv;
    }
    __syncthreads();
    for (int idx = tid; idx < 2*BB*CC*CC; idx += blockDim.x) {
        int s = idx / (BB*CC*CC), rem = idx - s*(BB*CC*CC);
        int b = rem / (CC*CC), rem2 = rem - b*(CC*CC);
        int o = rem2 / CC, dg = rem2 - o*CC;
        int h = dg / 16, dd = dg - h*16;
        const float* wv = ((s == 0) ? w1 : w2) + o*CC + h*16;
        int arow = s*96 + b*48 + h*16;
        float acc = 0.f;
        #pragma unroll
        for (int c = 0; c < 16; ++c)
            acc += wv[c] * As2[arow + c][dd];
        g_Mbf[s*BB + b][o*CC + dg] = __float2bfloat16_rn(acc);
    }
}

// ---------------- epilogue: out = x + M @ V + bias via mma.sync ----------------
__global__ void __launch_bounds__(256) k_epilogue(const float* __restrict__ xl,
                                                  const float* __restrict__ xr,
                                                  const float* __restrict__ b1,
                                                  const float* __restrict__ b2,
                                                  float* __restrict__ out) {
    __shared__ __align__(16) __nv_bfloat16 Ms[CC*CC];
    __shared__ uint32_t Vs[24*VSTR];
    __shared__ float bss[CC];
    int p0 = blockIdx.x*256, b = blockIdx.y, s = blockIdx.z;
    int tid = threadIdx.x, lane = tid & 31, nq = tid >> 5;
    {
        const uint4* src = reinterpret_cast<const uint4*>(&g_Mbf[s*BB + b][0]);
        uint4* dst = reinterpret_cast<uint4*>(Ms);
        for (int i = tid; i < CC*CC/8; i += 256) dst[i] = src[i];
        const uint32_t* vsrc = &g_vp[s][b][0][0];
        for (int i = tid; i < 24*256; i += 256) {
            int kp = i >> 8, col = i & 255;
            Vs[kp*VSTR + col] = vsrc[kp*HWW + p0 + col];
        }
        const float* bp = s ? b2 : b1;
        for (int i = tid; i < CC; i += 256) bss[i] = bp[i];
    }
    __syncthreads();
    float acc[3][2][2][4];
    #pragma unroll
    for (int mb = 0; mb < 3; ++mb)
        #pragma unroll
        for (int np = 0; np < 2; ++np)
            #pragma unroll
            for (int f = 0; f < 2; ++f)
                #pragma unroll
                for (int q = 0; q < 4; ++q) acc[mb][np][f][q] = 0.f;
    uint32_t smbA = smem_u32(Ms);
    #pragma unroll
    for (int kb = 0; kb < 3; ++kb) {
        uint32_t a[3][4];
        #pragma unroll
        for (int mb = 0; mb < 3; ++mb) {
            int row = mb*16 + (lane & 15);
            ldsm4(a[mb], smbA + (uint32_t)(row*CC + kb*16 + ((lane >> 4) << 3))*2u);
        }
        const uint32_t* b_lo = Vs + (kb*8 + (lane & 3))*VSTR + nq*32 + (lane >> 2);
        const uint32_t* b_hi = b_lo + 4*VSTR;
        #pragma unroll
        for (int np = 0; np < 2; ++np) {
            uint32_t b0 = b_lo[np*16], b1 = b_hi[np*16];
            uint32_t b2v = b_lo[np*16 + 8], b3 = b_hi[np*16 + 8];
            #pragma unroll
            for (int mb = 0; mb < 3; ++mb) {
                mma16816(acc[mb][np][0], a[mb], b0, b1);
                mma16816(acc[mb][np][1], a[mb], b2v, b3);
            }
        }
    }
    const float* x = (s == 0 ? xl : xr) + b*CC*HWW;
    float* o = out + (s*BB + b)*CC*HWW;
    #pragma unroll
    for (int mb = 0; mb < 3; ++mb) {
        int oc0 = mb*16 + (lane >> 2), oc1 = oc0 + 8;
        float be0 = bss[oc0], be1 = bss[oc1];
        #pragma unroll
        for (int np = 0; np < 2; ++np)
            #pragma unroll
            for (int f = 0; f < 2; ++f) {
                int px = p0 + nq*32 + np*16 + f*8 + (lane & 3)*2;
                float2 x0 = *reinterpret_cast<const float2*>(&x[oc0*HWW + px]);
                float2 x1 = *reinterpret_cast<const float2*>(&x[oc1*HWW + px]);
                *reinterpret_cast<float2*>(&o[oc0*HWW + px]) =
                    make_float2(x0.x + acc[mb][np][f][0] + be0, x0.y + acc[mb][np][f][1] + be0);
                *reinterpret_cast<float2*>(&o[oc1*HWW + px]) =
                    make_float2(x1.x + acc[mb][np][f][2] + be1, x1.y + acc[mb][np][f][3] + be1);
            }
    }
}

// ---------------- launch ----------------
extern "C" void kernel_launch(void* const* d_in, const int* in_sizes, int n_in,
                              void* d_out, int out_size) {
    const float* x_l    = (const float*)d_in[0];
    const float* x_r    = (const float*)d_in[1];
    const float* ln1_w  = (const float*)d_in[2];
    const float* ln1_b  = (const float*)d_in[3];
    const float* ln2_w  = (const float*)d_in[4];
    const float* ln2_b  = (const float*)d_in[5];
    const float* qkvl_w = (const float*)d_in[6];
    const float* qkvl_b = (const float*)d_in[7];
    const float* qkvr_w = (const float*)d_in[8];
    const float* qkvr_b = (const float*)d_in[9];
    const float* dwl_w  = (const float*)d_in[10];
    const float* dwl_b  = (const float*)d_in[11];
    const float* dwr_w  = (const float*)d_in[12];
    const float* dwr_b  = (const float*)d_in[13];
    const float* dil0_w = (const float*)d_in[14];
    const float* dil0_b = (const float*)d_in[15];
    const float* dil1_w = (const float*)d_in[16];
    const float* dil1_b = (const float*)d_in[17];
    const float* dil2_w = (const float*)d_in[18];
    const float* dil2_b = (const float*)d_in[19];
    const float* convQ_w = (const float*)d_in[20];
    const float* convQ_b = (const float*)d_in[21];
    const float* conv1_w = (const float*)d_in[22];
    const float* conv1_b = (const float*)d_in[23];
    const float* conv2_w = (const float*)d_in[24];
    const float* conv2_b = (const float*)d_in[25];
    const float* temperature = (const float*)d_in[26];

    const int SMD = (2*DBUF)*4 + 2*ATILE*2;     // 53760 + 19968 = 73728 -> 2 CTAs/SM
    cudaFuncSetAttribute(k_dilated_mma, cudaFuncAttributeMaxDynamicSharedMemorySize, SMD);
    cudaFuncSetAttribute(k_lnqkv, cudaFuncAttributeMaxDynamicSharedMemorySize, LQ_SM);

    k_misc<<<199, 256>>>(qkvl_w, qkvr_w, convQ_w, convQ_b,
                         dil0_w, dil1_w, dil2_w, dil0_b, dil1_b, dil2_b);
    k_lnqkv<<<dim3(HWW/128, BB, 2), 288, LQ_SM>>>(x_l, x_r, ln1_w, ln1_b, ln2_w, ln2_b,
                                                  qkvl_b, qkvr_b);
    k_dw<<<dim3(HH/4, 72, 2*BB), 256>>>(dwl_w, dwl_b, dwr_w, dwr_b);
    k_dilated_mma<<<dim3(HH, BB), 256, SMD>>>();
    k_norms<<<3*BB*CC, 256>>>();
    k_dots<<<dim3(16, BB*NH, 2), 256>>>();
    k_soft_m<<<1, 256>>>(temperature, conv1_w, conv2_w);
    k_epilogue<<<dim3(HWW/256, BB, 2), 256>>>(x_l, x_r, conv1_b, conv2_b, (float*)d_out);
}

// round 13
// speedup vs baseline: 4.5927x; 1.1366x over previous
#include <cuda_runtime.h>
#include <cuda_bf16.h>
#include <cstdint>
#include <math.h>

#define BB   2
#define CC   48
#define HH   128
#define WW   256
#define HWW  (HH*WW)          // 32768
#define C3   144
#define C2   96
#define NH   3
#define BSTR 140              // qkv B row stride (u32)
#define ASTR 104              // A tile row stride (bf16)
#define DSTR 268              // dilated B row stride (u32): 256 px + 12 halo; 268%32==12
#define DBUF (48*DSTR)        // u32 per dilated B buffer
#define ATILE (48*ASTR)       // bf16 per dilated A buffer
#define VSTR 260              // epilogue V row stride (u32)

// ---------------- scratch (static device globals; no allocation) ----------------
__device__ __nv_bfloat16  g_pre_bf [2][BB][C3][HWW];   // bf16 qkv after LN+1x1
__device__ __nv_bfloat16  g_kb     [2][BB][CC][HWW];   // bf16 K after dw, [c][px]
__device__ uint32_t       g_vp     [2][BB][24][HWW];   // pair-packed bf16 V after dw
__device__ uint32_t       g_xp     [BB][CC][HWW];      // channel-pair-packed bf16 [Q_l;Q_r]
__device__ __nv_bfloat16  g_qb     [BB][CC][HWW];      // bf16 fused dilated+convQ output, [c][px]
__device__ __nv_bfloat16  g_wbf    [27][64][C2];       // folded bf16 weights (rows 48..63 unused)
__device__ __nv_bfloat16  g_wq     [2][C3][CC];        // bf16 qkv weights
__device__ float          g_beff   [CC];
__device__ float          g_dpart  [2*BB*NH*16*256];
__device__ float          g_nsq    [2][BB][NH][16][2][16];  // per-chunk sumsq partials {Q,K}
__device__ __nv_bfloat16  g_Mbf    [2*BB][CC*CC];      // folded conv1/2 @ blockdiag(A), bf16

__device__ __forceinline__ uint32_t smem_u32(const void* p) {
    uint32_t a;
    asm("{ .reg .u64 t; cvta.to.shared.u64 t, %1; cvt.u32.u64 %0, t; }" : "=r"(a) : "l"(p));
    return a;
}
__device__ __forceinline__ void ldsm4(uint32_t* r, uint32_t addr) {
    asm volatile("ldmatrix.sync.aligned.m8n8.x4.shared.b16 {%0,%1,%2,%3}, [%4];"
        : "=r"(r[0]), "=r"(r[1]), "=r"(r[2]), "=r"(r[3]) : "r"(addr));
}
__device__ __forceinline__ void mma16816(float* c, const uint32_t* a, uint32_t b0, uint32_t b1) {
    asm volatile("mma.sync.aligned.m16n8k16.row.col.f32.bf16.bf16.f32 "
        "{%0,%1,%2,%3}, {%4,%5,%6,%7}, {%8,%9}, {%0,%1,%2,%3};"
        : "+f"(c[0]), "+f"(c[1]), "+f"(c[2]), "+f"(c[3])
        : "r"(a[0]), "r"(a[1]), "r"(a[2]), "r"(a[3]), "r"(b0), "r"(b1));
}
__device__ __forceinline__ uint32_t pack_bf2(float a, float b) {
    return (uint32_t)__bfloat16_as_ushort(__float2bfloat16_rn(a))
         | ((uint32_t)__bfloat16_as_ushort(__float2bfloat16_rn(b)) << 16);
}
__device__ __forceinline__ void st_bf2(__nv_bfloat16* p, float a, float b) {
    *reinterpret_cast<uint32_t*>(p) = pack_bf2(a, b);
}
__device__ __forceinline__ float bf_lo(uint32_t u) {
    return __bfloat162float(__ushort_as_bfloat16((unsigned short)(u & 0xFFFF)));
}
__device__ __forceinline__ float bf_hi(uint32_t u) {
    return __bfloat162float(__ushort_as_bfloat16((unsigned short)(u >> 16)));
}

// ---------------- merged prelude: prep_w + fold_w + fold_b ----------------
__global__ void k_misc(const float* __restrict__ wl, const float* __restrict__ wr,
                       const float* __restrict__ cqw, const float* __restrict__ cqb,
                       const float* __restrict__ d0w, const float* __restrict__ d1w,
                       const float* __restrict__ d2w,
                       const float* __restrict__ d0b, const float* __restrict__ d1b,
                       const float* __restrict__ d2b) {
    int blk = blockIdx.x, tid = threadIdx.x;
    if (blk < 54) {                               // qkv weights -> bf16
        int i = blk*256 + tid;
        int s = i / (C3*CC), r = i - s*(C3*CC);
        reinterpret_cast<__nv_bfloat16*>(g_wq)[i] = __float2bfloat16_rn((s ? wr : wl)[r]);
    } else if (blk < 198) {                       // fold_w: 144 blocks (o, d)
        int idx = blk - 54;
        int o = idx % CC, d = idx / CC;
        const float* dw = (d == 0) ? d0w : (d == 1) ? d1w : d2w;
        __shared__ float qr[C2];
        for (int j = tid; j < C2; j += 256)
            qr[j] = cqw[o*(3*C2) + d*C2 + j];
        __syncthreads();
        for (int ik = tid; ik < C2*9; ik += 256) {
            float acc = 0.f;
            for (int j = 0; j < C2; ++j)
                acc += qr[j] * dw[j*(C2*9) + ik];
            int i = ik / 9, kk = ik - i*9;
            g_wbf[d*9 + kk][o][i] = __float2bfloat16_rn(acc);
        }
    } else {                                      // fold_b
        __shared__ float racc[192];
        if (tid < 192) {
            int o = tid >> 2, q = tid & 3;
            float acc = 0.f;
            for (int j = q*72; j < q*72 + 72; ++j) {
                int dd = j / 96, jj = j - dd*96;
                const float* bp = (dd == 0) ? d0b : (dd == 1) ? d1b : d2b;
                acc += cqw[o*288 + j] * bp[jj];
            }
            racc[tid] = acc;
        }
        __syncthreads();
        if (tid < CC)
            g_beff[tid] = cqb[tid] + racc[tid*4] + racc[tid*4+1] + racc[tid*4+2] + racc[tid*4+3];
    }
}

// ---------------- fused LayerNorm2d + 1x1 qkv GEMM ----------------
#define LQ_XS   0
#define LQ_BS   (48*132*4)
#define LQ_AS   (LQ_BS + 24*BSTR*4)
#define LQ_BIAS (LQ_AS + C3*CC*2)
#define LQ_SM   (LQ_BIAS + C3*4)

__global__ void __launch_bounds__(288) k_lnqkv(const float* __restrict__ xl,
                                               const float* __restrict__ xr,
                                               const float* __restrict__ ln1w, const float* __restrict__ ln1b,
                                               const float* __restrict__ ln2w, const float* __restrict__ ln2b,
                                               const float* __restrict__ bl, const float* __restrict__ br) {
    extern __shared__ __align__(16) char smraw[];
    float*    xs = reinterpret_cast<float*>(smraw + LQ_XS);
    uint32_t* Bs = reinterpret_cast<uint32_t*>(smraw + LQ_BS);
    __nv_bfloat16* As = reinterpret_cast<__nv_bfloat16*>(smraw + LQ_AS);
    float*    bs = reinterpret_cast<float*>(smraw + LQ_BIAS);
    int p0 = blockIdx.x*128, b = blockIdx.y, branch = blockIdx.z;
    int tid = threadIdx.x, lane = tid & 31, wid = tid >> 5;
    const float* x = (branch == 0 ? xl : xr) + b*CC*HWW;
    {
        const uint4* src = reinterpret_cast<const uint4*>(&g_wq[branch][0][0]);
        uint4* dst = reinterpret_cast<uint4*>(As);
        for (int i = tid; i < C3*CC/8; i += 288) dst[i] = src[i];
        const float* bp = branch ? br : bl;
        for (int i = tid; i < C3; i += 288) bs[i] = bp[i];
        for (int i = tid; i < CC*128; i += 288) {
            int c = i >> 7, p = i & 127;
            xs[c*132 + p] = x[c*HWW + p0 + p];
        }
    }
    __syncthreads();
    if (tid < 128) {
        const float* lw = branch == 0 ? ln1w : ln2w;
        const float* lb = branch == 0 ? ln1b : ln2b;
        float mu = 0.f;
        #pragma unroll
        for (int c = 0; c < CC; ++c) mu += xs[c*132 + tid];
        mu *= (1.f/CC);
        float var = 0.f;
        #pragma unroll
        for (int c = 0; c < CC; ++c) { float t = xs[c*132 + tid] - mu; var += t*t; }
        float rstd = rsqrtf(var*(1.f/CC) + 1e-6f);
        #pragma unroll
        for (int kp = 0; kp < 24; ++kp) {
            float v0 = (xs[(2*kp  )*132 + tid] - mu)*rstd*lw[2*kp  ] + lb[2*kp  ];
            float v1 = (xs[(2*kp+1)*132 + tid] - mu)*rstd*lw[2*kp+1] + lb[2*kp+1];
            Bs[kp*BSTR + tid] = pack_bf2(v0, v1);
        }
    }
    __syncthreads();
    uint32_t smbA = smem_u32(As);
    int r0 = lane >> 2, cb = (lane & 3)*2;
    int oc0 = wid*16 + r0, oc1 = oc0 + 8;
    float be0 = bs[oc0], be1 = bs[oc1];
    __nv_bfloat16* o0 = &g_pre_bf[branch][b][oc0][p0];
    __nv_bfloat16* o1 = &g_pre_bf[branch][b][oc1][p0];
    #pragma unroll
    for (int half = 0; half < 2; ++half) {
        float acc[4][2][4];
        #pragma unroll
        for (int np = 0; np < 4; ++np)
            #pragma unroll
            for (int f = 0; f < 2; ++f)
                #pragma unroll
                for (int q = 0; q < 4; ++q) acc[np][f][q] = 0.f;
        #pragma unroll
        for (int kb = 0; kb < 3; ++kb) {
            uint32_t a[4];
            int row = wid*16 + (lane & 15);
            ldsm4(a, smbA + (uint32_t)(row*CC + kb*16 + ((lane >> 4) << 3))*2u);
            const uint32_t* b_lo = Bs + (kb*8 + (lane & 3))*BSTR + (lane >> 2) + half*64;
            const uint32_t* b_hi = b_lo + 4*BSTR;
            #pragma unroll
            for (int np = 0; np < 4; ++np) {
                uint32_t b0 = b_lo[np*16], b1 = b_hi[np*16];
                uint32_t b2 = b_lo[np*16 + 8], b3 = b_hi[np*16 + 8];
                mma16816(acc[np][0], a, b0, b1);
                mma16816(acc[np][1], a, b2, b3);
            }
        }
        #pragma unroll
        for (int np = 0; np < 4; ++np)
            #pragma unroll
            for (int f = 0; f < 2; ++f) {
                int c = half*64 + np*16 + f*8 + cb;
                st_bf2(o0 + c, acc[np][f][0] + be0, acc[np][f][1] + be0);
                st_bf2(o1 + c, acc[np][f][2] + be1, acc[np][f][3] + be1);
            }
    }
}

// ---------------- depthwise 3x3, channel-pair blocks ----------------
__global__ void k_dw(const float* __restrict__ wl, const float* __restrict__ bl,
                     const float* __restrict__ wr, const float* __restrict__ brb) {
    int z = blockIdx.z; int branch = z >> 1, b = z & 1;
    int chp = blockIdx.y;                  // 0..71 (channel pair)
    int c0 = 2*chp;
    int y0 = blockIdx.x * 4;
    __shared__ __align__(16) float rows[2][6][264];
    const float* wbase = (branch == 0 ? wl : wr);
    const float* bbase = (branch == 0 ? bl : brb);
    int tid = threadIdx.x;

    for (int idx = tid; idx < 2*6*64; idx += 256) {
        int cc = idx / 384, rem = idx - cc*384;
        int r = rem >> 6, c4 = rem & 63;
        int gy = y0 - 1 + r;
        float4 f = make_float4(0.f, 0.f, 0.f, 0.f);
        if (gy >= 0 && gy < HH) {
            const __nv_bfloat16* in = &g_pre_bf[branch][b][c0 + cc][0];
            uint2 v = *reinterpret_cast<const uint2*>(&in[gy*WW + c4*4]);
            f.x = bf_lo(v.x); f.y = bf_hi(v.x);
            f.z = bf_lo(v.y); f.w = bf_hi(v.y);
        }
        *reinterpret_cast<float4*>(&rows[cc][r][4 + 4*c4]) = f;
    }
    if (tid < 12) { int cc = tid / 6, r = tid % 6; rows[cc][r][3] = 0.f; rows[cc][r][260] = 0.f; }
    __syncthreads();

    int r  = tid >> 6;
    int x0 = (tid & 63) * 4;
    float out[2][4];
    #pragma unroll
    for (int cc = 0; cc < 2; ++cc) {
        const float* w = wbase + (c0 + cc)*9;
        float bias = bbase[c0 + cc];
        float a0 = bias, a1 = bias, a2 = bias, a3 = bias;
        #pragma unroll
        for (int ky = 0; ky < 3; ++ky) {
            const float* rp = &rows[cc][r + ky][3 + x0];
            float v0 = rp[0];
            float4 vm = *reinterpret_cast<const float4*>(rp + 1);
            float v5 = rp[5];
            float w0 = w[ky*3], w1 = w[ky*3+1], w2 = w[ky*3+2];
            a0 += w0*v0   + w1*vm.x + w2*vm.y;
            a1 += w0*vm.x + w1*vm.y + w2*vm.z;
            a2 += w0*vm.y + w1*vm.z + w2*vm.w;
            a3 += w0*vm.z + w1*vm.w + w2*v5;
        }
        out[cc][0] = a0; out[cc][1] = a1; out[cc][2] = a2; out[cc][3] = a3;
    }
    int px = (y0 + r)*WW + x0;
    if (chp < 24) {              // Q pair -> g_xp (channel-pair packed)
        uint4 u;
        u.x = pack_bf2(out[0][0], out[1][0]); u.y = pack_bf2(out[0][1], out[1][1]);
        u.z = pack_bf2(out[0][2], out[1][2]); u.w = pack_bf2(out[0][3], out[1][3]);
        *reinterpret_cast<uint4*>(&g_xp[b][branch*24 + chp][px]) = u;
    } else if (chp < 48) {       // K -> plain bf16 [c][px]
        int kc = c0 - CC;
        uint2 u0, u1;
        u0.x = pack_bf2(out[0][0], out[0][1]); u0.y = pack_bf2(out[0][2], out[0][3]);
        u1.x = pack_bf2(out[1][0], out[1][1]); u1.y = pack_bf2(out[1][2], out[1][3]);
        *reinterpret_cast<uint2*>(&g_kb[branch][b][kc][px])     = u0;
        *reinterpret_cast<uint2*>(&g_kb[branch][b][kc + 1][px]) = u1;
    } else {                     // V pair -> g_vp (channel-pair packed)
        uint4 u;
        u.x = pack_bf2(out[0][0], out[1][0]); u.y = pack_bf2(out[0][1], out[1][1]);
        u.z = pack_bf2(out[0][2], out[1][2]); u.w = pack_bf2(out[0][3], out[1][3]);
        *reinterpret_cast<uint4*>(&g_vp[branch][b][chp - 48][px]) = u;
    }
}

// ---------------- fused dilated convs + convQ: full-row CTA, correct DSTR, A single-buf ----------------
__global__ void __launch_bounds__(256, 2) k_dilated_mma() {
    extern __shared__ __align__(16) uint32_t smx[];
    uint32_t* Bs = smx;                                                  // [2][48*268]
    __nv_bfloat16* As = reinterpret_cast<__nv_bfloat16*>(smx + 2*DBUF);  // [48][104]
    uint32_t smbB = smem_u32(Bs), smbA = smem_u32(As);
    int y = blockIdx.x, b = blockIdx.y;
    int tid = threadIdx.x, lane = tid & 31, nq = tid >> 5;
    const uint32_t* xp = &g_xp[b][0][0];

    float acc[3][2][2][4];
    #pragma unroll
    for (int mb = 0; mb < 3; ++mb)
        #pragma unroll
        for (int np = 0; np < 2; ++np)
            #pragma unroll
            for (int f = 0; f < 2; ++f)
                #pragma unroll
                for (int q = 0; q < 4; ++q) acc[mb][np][f][q] = 0.f;

    auto fill_B = [&](int buf, int gy) {
        bool rowok = (gy >= 0 && gy < HH);
        uint32_t dbase = smbB + (uint32_t)buf*DBUF*4u;
        int gys = rowok ? gy : 0;
        for (int i = tid; i < 48*134; i += 256) {
            int kp = i / 134, c2 = i - kp*134;
            int gx = c2*2 - 6;
            bool ok = rowok && gx >= 0 && gx < WW;
            const uint32_t* src = xp + kp*HWW + gys*WW + (ok ? gx : 0);
            uint32_t sz = ok ? 8u : 0u;
            asm volatile("cp.async.ca.shared.global [%0], [%1], 8, %2;"
                         :: "r"(dbase + (uint32_t)(kp*DSTR + c2*2)*4u), "l"(src), "r"(sz)
                         : "memory");
        }
    };
    auto fill_A = [&](int tap) {
        const __nv_bfloat16* src = &g_wbf[tap][0][0];
        for (int i = tid; i < 576; i += 256) {       // 48 rows x 12 uint4
            int row = i / 12, cu = i - row*12;
            asm volatile("cp.async.ca.shared.global [%0], [%1], 16;"
                         :: "r"(smbA + (uint32_t)(row*ASTR + cu*8)*2u),
                            "l"(src + row*C2 + cu*8) : "memory");
        }
    };
    auto stage_dky = [](int s, int& d, int& ky) {
        if (s < 9)       { d = s/3;      ky = 1; }
        else if (s < 18) { d = (s-9)/3;  ky = 0; }
        else             { d = (s-18)/3; ky = 2; }
    };

    // prologue: A tap for stage 0 = (d0, ky1, kx0) -> 3 ; B row y -> buf 0
    fill_A(3);
    fill_B(0, y);
    asm volatile("cp.async.commit_group;" ::: "memory");

    #pragma unroll 1
    for (int s = 0; s < 27; ++s) {
        asm volatile("cp.async.wait_group 0;" ::: "memory");
        __syncthreads();
        // prefetch next B row (other buffer) — overlaps with this stage's compute
        if (s < 26) {
            int ns = s + 1;
            int nd, nky; stage_dky(ns, nd, nky);
            if (ns >= 9 && (ns - 9) % 3 == 0) {
                int rb = 1 + (ns - 9)/3;
                fill_B(rb & 1, y + (nky - 1)*2*(nd + 1));
                asm volatile("cp.async.commit_group;" ::: "memory");
            }
        }
        int d, ky; stage_dky(s, d, ky);
        int rb = (s < 9) ? 0 : 1 + (s - 9)/3;
        const uint32_t* bcur = Bs + (rb & 1)*DBUF;
        int dil = 2*(d + 1);
        int coloff = 6 + ((s % 3) - 1)*dil + nq*32 + (lane >> 2);
        #pragma unroll
        for (int kb = 0; kb < 6; ++kb) {
            uint32_t a[3][4];
            #pragma unroll
            for (int mb = 0; mb < 3; ++mb) {
                int row = mb*16 + (lane & 15);
                ldsm4(a[mb], smbA + (uint32_t)(row*ASTR + kb*16 + ((lane >> 4) << 3))*2u);
            }
            const uint32_t* b_lo = bcur + (kb*8 + (lane & 3))*DSTR + coloff;
            const uint32_t* b_hi = b_lo + 4*DSTR;
            #pragma unroll
            for (int np = 0; np < 2; ++np) {
                uint32_t b0 = b_lo[np*16], b1 = b_hi[np*16];
                uint32_t b2 = b_lo[np*16 + 8], b3 = b_hi[np*16 + 8];
                #pragma unroll
                for (int mb = 0; mb < 3; ++mb) {
                    mma16816(acc[mb][np][0], a[mb], b0, b1);
                    mma16816(acc[mb][np][1], a[mb], b2, b3);
                }
            }
        }
        __syncthreads();   // all warps done reading A before refill
        if (s < 26) {
            int ns = s + 1;
            int nd, nky; stage_dky(ns, nd, nky);
            fill_A(nd*9 + nky*3 + (ns % 3));
            asm volatile("cp.async.commit_group;" ::: "memory");
        }
    }
    #pragma unroll
    for (int mb = 0; mb < 3; ++mb) {
        int oc = mb*16 + (lane >> 2);
        float be0 = g_beff[oc], be1 = g_beff[oc + 8];
        #pragma unroll
        for (int np = 0; np < 2; ++np)
            #pragma unroll
            for (int f = 0; f < 2; ++f) {
                int n = nq*32 + np*16 + f*8 + (lane & 3)*2;
                *reinterpret_cast<uint32_t*>(&g_qb[b][oc][y*WW + n]) =
                    pack_bf2(acc[mb][np][f][0] + be0, acc[mb][np][f][1] + be0);
                *reinterpret_cast<uint32_t*>(&g_qb[b][oc + 8][y*WW + n]) =
                    pack_bf2(acc[mb][np][f][2] + be1, acc[mb][np][f][3] + be1);
            }
    }
}

// ---------------- QK^T dots via mma.sync + fused sumsq partials ----------------
__global__ void __launch_bounds__(256) k_dots() {
    int chunk = blockIdx.x, bh = blockIdx.y, s = blockIdx.z;
    int b = bh / NH, h = bh - b*NH;
    const uint32_t* Q = reinterpret_cast<const uint32_t*>(&g_qb[b][h*16][0]);
    const uint32_t* K = reinterpret_cast<const uint32_t*>(&g_kb[s == 0 ? 1 : 0][b][h*16][0]);
    __shared__ uint32_t Qs[16][132], Ks[16][132];
    __shared__ float redD[8][256];
    __shared__ float sqs[2][16][16];
    int tid = threadIdx.x, lane = tid & 31, w = tid >> 5;
    int c = tid >> 4, j = tid & 15;
    uint32_t smbQ = smem_u32(Qs);
    float qsq = 0.f, ksq = 0.f;
    float d0[4] = {0.f,0.f,0.f,0.f}, d1[4] = {0.f,0.f,0.f,0.f};
    int p0u = chunk*1024;
    const int rstride = HWW/2;
    for (int sub = 0; sub < 8; ++sub) {
        __syncthreads();
        int pb = p0u + sub*128;
        const uint32_t* qrow = Q + c*rstride + pb + j;
        const uint32_t* krow = K + c*rstride + pb + j;
        #pragma unroll
        for (int q = 0; q < 8; ++q) {
            uint32_t v = qrow[16*q];
            Qs[c][j + 16*q] = v;
            float lo = bf_lo(v), hi = bf_hi(v);
            qsq += lo*lo + hi*hi;
            uint32_t u = krow[16*q];
            Ks[c][j + 16*q] = u;
            lo = bf_lo(u); hi = bf_hi(u);
            ksq += lo*lo + hi*hi;
        }
        __syncthreads();
        #pragma unroll
        for (int ki = 0; ki < 2; ++ki) {
            int k0u = w*16 + ki*8;
            uint32_t a[4];
            ldsm4(a, smbQ + (uint32_t)((lane & 15)*132 + k0u + ((lane >> 4) << 2))*4u);
            uint32_t b0 = Ks[lane >> 2][k0u + (lane & 3)];
            uint32_t b1 = Ks[lane >> 2][k0u + 4 + (lane & 3)];
            uint32_t b2 = Ks[8 + (lane >> 2)][k0u + (lane & 3)];
            uint32_t b3 = Ks[8 + (lane >> 2)][k0u + 4 + (lane & 3)];
            mma16816(d0, a, b0, b1);
            mma16816(d1, a, b2, b3);
        }
    }
    {
        int cq = lane >> 2, ckb = (lane & 3)*2;
        redD[w][cq*16 + ckb]           = d0[0];
        redD[w][cq*16 + ckb + 1]       = d0[1];
        redD[w][(cq+8)*16 + ckb]       = d0[2];
        redD[w][(cq+8)*16 + ckb + 1]   = d0[3];
        redD[w][cq*16 + 8 + ckb]       = d1[0];
        redD[w][cq*16 + 8 + ckb + 1]   = d1[1];
        redD[w][(cq+8)*16 + 8 + ckb]   = d1[2];
        redD[w][(cq+8)*16 + 8 + ckb+1] = d1[3];
    }
    sqs[0][c][j] = qsq;
    sqs[1][c][j] = ksq;
    __syncthreads();
    float tot = 0.f;
    #pragma unroll
    for (int ww = 0; ww < 8; ++ww) tot += redD[ww][tid];
    int base = (((s*BB + b)*NH + h)*16 + chunk)*256;
    g_dpart[base + tid] = tot;
    if (tid < 32) {
        int set = tid >> 4, cc = tid & 15;
        float sm = 0.f;
        #pragma unroll
        for (int jj = 0; jj < 16; ++jj) sm += sqs[set][cc][jj];
        g_nsq[s][b][h][chunk][set][cc] = sm;
    }
}

// ---------------- norms + softmax + fold conv1/2 into bf16 M ----------------
__global__ void k_soft_m(const float* __restrict__ temp,
                         const float* __restrict__ w1, const float* __restrict__ w2) {
    __shared__ float As2[192][16];
    __shared__ float invs[3][2][48];
    int tid = threadIdx.x;
    for (int i = tid; i < 288; i += 256) {
        int set = i / 96, r = i - set*96;
        int b2 = r / 48, c2 = r - b2*48;
        int h2 = c2 >> 4, cc = c2 & 15;
        int ssrc = (set == 1) ? 1 : 0;
        int qk = (set == 0) ? 0 : 1;
        float sum = 0.f;
        #pragma unroll
        for (int ch2 = 0; ch2 < 16; ++ch2)
            sum += g_nsq[ssrc][b2][h2][ch2][qk][cc];
        invs[set][b2][c2] = 1.f / fmaxf(sqrtf(sum), 1e-12f);
    }
    __syncthreads();
    if (tid < 192) {
        int s = tid / 96, rem = tid - s*96;
        int b = rem / 48, rem2 = rem - b*48;
        int h = rem2 / 16, cq = rem2 - h*16;
        float v[16];
        #pragma unroll
        for (int ck = 0; ck < 16; ++ck) v[ck] = 0.f;
        int base = (((s*BB + b)*NH + h)*16)*256 + cq*16;
        for (int chunk = 0; chunk < 16; ++chunk) {
            #pragma unroll
            for (int ck = 0; ck < 16; ++ck)
                v[ck] += g_dpart[base + chunk*256 + ck];
        }
        float iq = invs[0][b][h*16 + cq];
        float tm = temp[h];
        const float* ik = (s == 0) ? &invs[2][b][h*16] : &invs[1][b][h*16];
        float mx = -1e30f;
        #pragma unroll
        for (int ck = 0; ck < 16; ++ck) { v[ck] *= iq * ik[ck] * tm; mx = fmaxf(mx, v[ck]); }
        float sum = 0.f;
        #pragma unroll
        for (int ck = 0; ck < 16; ++ck) { v[ck] = expf(v[ck] - mx); sum += v[ck]; }
        float inv = 1.f / sum;
        #pragma unroll
        for (int ck = 0; ck < 16; ++ck) As2[tid][ck] = v[ck] * inv;
    }
    __syncthreads();
    for (int idx = tid; idx < 2*BB*CC*CC; idx += blockDim.x) {
        int s = idx / (BB*CC*CC), rem = idx - s*(BB*CC*CC);
        int b = rem / (CC*CC), rem2 = rem - b*(CC*CC);
        int o = rem2 / CC, dg = rem2 - o*CC;
        int h = dg / 16, dd = dg - h*16;
        const float* wv = ((s == 0) ? w1 : w2) + o*CC + h*16;
        int arow = s*96 + b*48 + h*16;
        float acc = 0.f;
        #pragma unroll
        for (int c = 0; c < 16; ++c)
            acc += wv[c] * As2[arow + c][dd];
        g_Mbf[s*BB + b][o*CC + dg] = __float2bfloat16_rn(acc);
    }
}

// ---------------- epilogue: out = x + M @ V + bias via mma.sync ----------------
__global__ void __launch_bounds__(256) k_epilogue(const float* __restrict__ xl,
                                                  const float* __restrict__ xr,
                                                  const float* __restrict__ b1,
                                                  const float* __restrict__ b2,
                                                  float* __restrict__ out) {
    __shared__ __align__(16) __nv_bfloat16 Ms[CC*CC];
    __shared__ uint32_t Vs[24*VSTR];
    __shared__ float bss[CC];
    int p0 = blockIdx.x*256, b = blockIdx.y, s = blockIdx.z;
    int tid = threadIdx.x, lane = tid & 31, nq = tid >> 5;
    {
        const uint4* src = reinterpret_cast<const uint4*>(&g_Mbf[s*BB + b][0]);
        uint4* dst = reinterpret_cast<uint4*>(Ms);
        for (int i = tid; i < CC*CC/8; i += 256) dst[i] = src[i];
        const uint32_t* vsrc = &g_vp[s][b][0][0];
        for (int i = tid; i < 24*256; i += 256) {
            int kp = i >> 8, col = i & 255;
            Vs[kp*VSTR + col] = vsrc[kp*HWW + p0 + col];
        }
        const float* bp = s ? b2 : b1;
        for (int i = tid; i < CC; i += 256) bss[i] = bp[i];
    }
    __syncthreads();
    float acc[3][2][2][4];
    #pragma unroll
    for (int mb = 0; mb < 3; ++mb)
        #pragma unroll
        for (int np = 0; np < 2; ++np)
            #pragma unroll
            for (int f = 0; f < 2; ++f)
                #pragma unroll
                for (int q = 0; q < 4; ++q) acc[mb][np][f][q] = 0.f;
    uint32_t smbA = smem_u32(Ms);
    #pragma unroll
    for (int kb = 0; kb < 3; ++kb) {
        uint32_t a[3][4];
        #pragma unroll
        for (int mb = 0; mb < 3; ++mb) {
            int row = mb*16 + (lane & 15);
            ldsm4(a[mb], smbA + (uint32_t)(row*CC + kb*16 + ((lane >> 4) << 3))*2u);
        }
        const uint32_t* b_lo = Vs + (kb*8 + (lane & 3))*VSTR + nq*32 + (lane >> 2);
        const uint32_t* b_hi = b_lo + 4*VSTR;
        #pragma unroll
        for (int np = 0; np < 2; ++np) {
            uint32_t b0 = b_lo[np*16], b1 = b_hi[np*16];
            uint32_t b2v = b_lo[np*16 + 8], b3 = b_hi[np*16 + 8];
            #pragma unroll
            for (int mb = 0; mb < 3; ++mb) {
                mma16816(acc[mb][np][0], a[mb], b0, b1);
                mma16816(acc[mb][np][1], a[mb], b2v, b3);
            }
        }
    }
    const float* x = (s == 0 ? xl : xr) + b*CC*HWW;
    float* o = out + (s*BB + b)*CC*HWW;
    #pragma unroll
    for (int mb = 0; mb < 3; ++mb) {
        int oc0 = mb*16 + (lane >> 2), oc1 = oc0 + 8;
        float be0 = bss[oc0], be1 = bss[oc1];
        #pragma unroll
        for (int np = 0; np < 2; ++np)
            #pragma unroll
            for (int f = 0; f < 2; ++f) {
                int px = p0 + nq*32 + np*16 + f*8 + (lane & 3)*2;
                float2 x0 = *reinterpret_cast<const float2*>(&x[oc0*HWW + px]);
                float2 x1 = *reinterpret_cast<const float2*>(&x[oc1*HWW + px]);
                *reinterpret_cast<float2*>(&o[oc0*HWW + px]) =
                    make_float2(x0.x + acc[mb][np][f][0] + be0, x0.y + acc[mb][np][f][1] + be0);
                *reinterpret_cast<float2*>(&o[oc1*HWW + px]) =
                    make_float2(x1.x + acc[mb][np][f][2] + be1, x1.y + acc[mb][np][f][3] + be1);
            }
    }
}

// ---------------- launch ----------------
extern "C" void kernel_launch(void* const* d_in, const int* in_sizes, int n_in,
                              void* d_out, int out_size) {
    const float* x_l    = (const float*)d_in[0];
    const float* x_r    = (const float*)d_in[1];
    const float* ln1_w  = (const float*)d_in[2];
    const float* ln1_b  = (const float*)d_in[3];
    const float* ln2_w  = (const float*)d_in[4];
    const float* ln2_b  = (const float*)d_in[5];
    const float* qkvl_w = (const float*)d_in[6];
    const float* qkvl_b = (const float*)d_in[7];
    const float* qkvr_w = (const float*)d_in[8];
    const float* qkvr_b = (const float*)d_in[9];
    const float* dwl_w  = (const float*)d_in[10];
    const float* dwl_b  = (const float*)d_in[11];
    const float* dwr_w  = (const float*)d_in[12];
    const float* dwr_b  = (const float*)d_in[13];
    const float* dil0_w = (const float*)d_in[14];
    const float* dil0_b = (const float*)d_in[15];
    const float* dil1_w = (const float*)d_in[16];
    const float* dil1_b = (const float*)d_in[17];
    const float* dil2_w = (const float*)d_in[18];
    const float* dil2_b = (const float*)d_in[19];
    const float* convQ_w = (const float*)d_in[20];
    const float* convQ_b = (const float*)d_in[21];
    const float* conv1_w = (const float*)d_in[22];
    const float* conv1_b = (const float*)d_in[23];
    const float* conv2_w = (const float*)d_in[24];
    const float* conv2_b = (const float*)d_in[25];
    const float* temperature = (const float*)d_in[26];

    const int SMD = (2*DBUF)*4 + ATILE*2;   // 102912 + 9984 = 112896 -> 2 CTAs/SM
    cudaFuncSetAttribute(k_dilated_mma, cudaFuncAttributeMaxDynamicSharedMemorySize, SMD);
    cudaFuncSetAttribute(k_lnqkv, cudaFuncAttributeMaxDynamicSharedMemorySize, LQ_SM);

    k_misc<<<199, 256>>>(qkvl_w, qkvr_w, convQ_w, convQ_b,
                         dil0_w, dil1_w, dil2_w, dil0_b, dil1_b, dil2_b);
    k_lnqkv<<<dim3(HWW/128, BB, 2), 288, LQ_SM>>>(x_l, x_r, ln1_w, ln1_b, ln2_w, ln2_b,
                                                  qkvl_b, qkvr_b);
    k_dw<<<dim3(HH/4, 72, 2*BB), 256>>>(dwl_w, dwl_b, dwr_w, dwr_b);
    k_dilated_mma<<<dim3(HH, BB), 256, SMD>>>();
    k_dots<<<dim3(16, BB*NH, 2), 256>>>();
    k_soft_m<<<1, 256>>>(temperature, conv1_w, conv2_w);
    k_epilogue<<<dim3(HWW/256, BB, 2), 256>>>(x_l, x_r, conv1_b, conv2_b, (float*)d_out);
}